// round 8
// baseline (speedup 1.0000x reference)
#include <cuda_runtime.h>
#include <cuda_bf16.h>
#include <cstdint>

#define BB   16
#define TT   2048
#define NIN  96
#define NOUT 128
#define DD   64
#define BT   (BB*TT)

// ---- global scratch (pre-split bf16 hi/lo, swizzled 128B/256B rows) ----
__device__ uint4 g_QH4[BT*8]; __device__ uint4 g_QL4[BT*8];
__device__ uint4 g_KH4[BT*8]; __device__ uint4 g_KL4[BT*8];
__device__ uint4 g_VH4[BT*8]; __device__ uint4 g_VL4[BT*8];
__device__ uint4 g_AH4[BT*8]; __device__ uint4 g_AL4[BT*8];   // attn out
__device__ uint4 g_HH4[BT*16]; __device__ uint4 g_HL4[BT*16]; // conv1 out (256B rows)
__device__ float g_XDW[BT*NOUT];
__device__ uint4 g_W1H4[3*2*512];   __device__ uint4 g_W1L4[3*2*512];
__device__ uint4 g_W2H4[3*2*2*512]; __device__ uint4 g_W2L4[3*2*2*512];

// ===================== helpers =====================
__device__ __forceinline__ uint32_t smem_u32(const void* p){
    uint32_t a;
    asm("{ .reg .u64 t; cvta.to.shared.u64 t, %1; cvt.u32.u64 %0, t; }" : "=r"(a) : "l"(p));
    return a;
}
#define LDSM4(R, A) \
    asm volatile("ldmatrix.sync.aligned.m8n8.x4.shared.b16 {%0,%1,%2,%3}, [%4];" \
        : "=r"((R)[0]),"=r"((R)[1]),"=r"((R)[2]),"=r"((R)[3]) : "r"(A))
#define LDSM4T(R, A) \
    asm volatile("ldmatrix.sync.aligned.m8n8.x4.trans.shared.b16 {%0,%1,%2,%3}, [%4];" \
        : "=r"((R)[0]),"=r"((R)[1]),"=r"((R)[2]),"=r"((R)[3]) : "r"(A))
#define CPA(dst, src) \
    asm volatile("cp.async.cg.shared.global [%0], [%1], 16;" :: "r"(dst), "l"(src))
#define CPC() asm volatile("cp.async.commit_group;")
#define CPW(n) asm volatile("cp.async.wait_group %0;" :: "n"(n))

__device__ __forceinline__ void mma16816(float* c, const uint32_t* a, uint32_t b0, uint32_t b1){
    asm volatile(
        "mma.sync.aligned.m16n8k16.row.col.f32.bf16.bf16.f32 "
        "{%0,%1,%2,%3},{%4,%5,%6,%7},{%8,%9},{%0,%1,%2,%3};"
        : "+f"(c[0]),"+f"(c[1]),"+f"(c[2]),"+f"(c[3])
        : "r"(a[0]),"r"(a[1]),"r"(a[2]),"r"(a[3]),"r"(b0),"r"(b1));
}
__device__ __forceinline__ uint32_t packbf(float lo, float hi){
    uint16_t l = __bfloat16_as_ushort(__float2bfloat16(lo));
    uint16_t h = __bfloat16_as_ushort(__float2bfloat16(hi));
    return ((uint32_t)h << 16) | (uint32_t)l;
}
__device__ __forceinline__ uint32_t swz(int r, int ch){
    return (uint32_t)(r*128 + ((ch ^ (r & 7)) << 4));
}
// write a hi/lo split pair (cols cl, cl+1, cl even) into 128B-row global arrays
__device__ __forceinline__ void wr_pair64(uint32_t* H, uint32_t* L, int row, int cl,
                                          float a, float bvv){
    int byte = cl*2;
    int u = row*32 + (((byte>>4) ^ (row&7))<<2) + ((byte&15)>>2);
    __nv_bfloat16 ha=__float2bfloat16(a), hb=__float2bfloat16(bvv);
    H[u] = ((uint32_t)__bfloat16_as_ushort(hb)<<16)|__bfloat16_as_ushort(ha);
    L[u] = packbf(a-__bfloat162float(ha), bvv-__bfloat162float(hb));
}

// ===================== weight prep: split + swizzle into tile images ========
__global__ void prep_w_kernel(const float* __restrict__ w, int Cin,
                              uint32_t* __restrict__ wH, uint32_t* __restrict__ wL)
{
    int nh = Cin >> 6;
    int total = 3*Cin*64;   // co-pairs
    for (int idx = blockIdx.x*blockDim.x + threadIdx.x; idx < total;
         idx += gridDim.x*blockDim.x) {
        int k = idx/(Cin*64); int rem = idx - k*Cin*64;
        int ci = rem >> 6, cop = rem & 63;
        float2 v = *(const float2*)(w + (size_t)(k*Cin+ci)*NOUT + cop*2);
        int hci = ci>>6, cil = ci&63, hco = cop>>5, copl = cop&31;
        int tidx = (k*nh + hci)*2 + hco;
        int u = tidx*2048 + cil*32 + (((copl>>2) ^ (cil&7))<<2) + (copl&3);
        __nv_bfloat16 hx=__float2bfloat16(v.x), hy=__float2bfloat16(v.y);
        wH[u] = ((uint32_t)__bfloat16_as_ushort(hy)<<16)|__bfloat16_as_ushort(hx);
        wL[u] = packbf(v.x-__bfloat162float(hx), v.y-__bfloat162float(hy));
    }
}

// ===================== proj: GEMM + split/swizzle epilogue =================
#define PROJ_XS_F   (128*97)
#define PROJ_SMEM   ((PROJ_XS_F + 96*64)*4)
__global__ __launch_bounds__(256) void proj_kernel(
    const float* __restrict__ x, const float* __restrict__ qkv_w,
    const float* __restrict__ qkv_b, const float* __restrict__ scale,
    const float* __restrict__ down_w)
{
    extern __shared__ float sm[];
    float* Xs = sm;
    float* Ws = sm + PROJ_XS_F;
    const int row0 = blockIdx.x * 128;
    const int col0 = blockIdx.y * 64;
    const int tid  = threadIdx.x;

    for (int idx = tid; idx < 128*96; idx += 256) {
        int i = idx / 96, k = idx - i*96;
        Xs[i*97 + k] = x[(row0 + i)*NIN + k];
    }
    for (int idx = tid; idx < 96*64; idx += 256) {
        int k = idx >> 6, j = idx & 63;
        int col = col0 + j;
        Ws[idx] = (col < 192) ? qkv_w[k*192 + col] : down_w[k*128 + (col - 192)];
    }
    __syncthreads();

    const int tr = tid >> 4, tc = tid & 15;
    const int i0 = tr*8, j0 = tc*4;
    float acc[8][4];
    #pragma unroll
    for (int r = 0; r < 8; r++) { acc[r][0]=acc[r][1]=acc[r][2]=acc[r][3]=0.f; }

    #pragma unroll 4
    for (int k = 0; k < 96; k++) {
        float4 bv = *reinterpret_cast<const float4*>(&Ws[k*64 + j0]);
        #pragma unroll
        for (int r = 0; r < 8; r++) {
            float a = Xs[(i0 + r)*97 + k];
            acc[r][0] += a*bv.x; acc[r][1] += a*bv.y;
            acc[r][2] += a*bv.z; acc[r][3] += a*bv.w;
        }
    }

    const float sc    = scale[0];
    const float enres = 1.0f + 1.0f/(float)TT;
    const int yb = blockIdx.y;
    uint32_t *H = nullptr, *L = nullptr;
    if      (yb == 0) { H = (uint32_t*)g_QH4; L = (uint32_t*)g_QL4; }
    else if (yb == 1) { H = (uint32_t*)g_KH4; L = (uint32_t*)g_KL4; }
    else if (yb == 2) { H = (uint32_t*)g_VH4; L = (uint32_t*)g_VL4; }

    #pragma unroll
    for (int r = 0; r < 8; r++) {
        int row = row0 + i0 + r;
        if (yb < 3) {
            float v0 = acc[r][0] + qkv_b[col0 + j0 + 0];
            float v1 = acc[r][1] + qkv_b[col0 + j0 + 1];
            float v2 = acc[r][2] + qkv_b[col0 + j0 + 2];
            float v3 = acc[r][3] + qkv_b[col0 + j0 + 3];
            if (yb == 0) { v0*=sc; v1*=sc; v2*=sc; v3*=sc; }
            wr_pair64(H, L, row, j0,     v0, v1);
            wr_pair64(H, L, row, j0 + 2, v2, v3);
        } else {
            #pragma unroll
            for (int c = 0; c < 4; c++) {
                int col = col0 + j0 + c - 192;
                g_XDW[row*NOUT + col] = acc[r][c] * enres;
            }
        }
    }
}

// ===================== attention: cp.async double-buffered =================
// smem: QH 16K | QL 16K | stage0 {KH,KL,VH,VL} 64K | stage1 64K  = 160KB
#define T_QH 0
#define T_QL 16384
#define T_ST 32768
#define ATTN4_SMEM 163840

__global__ __launch_bounds__(256) void attn4_kernel()
{
    extern __shared__ __align__(16) char smp[];
    const uint32_t sb = smem_u32(smp);
    const int b    = blockIdx.y;
    const int q0   = blockIdx.x * 128;
    const int tid  = threadIdx.x;
    const int w    = tid >> 5;
    const int lane = tid & 31;

    // ---- issue Q copy (group 0) ----
    {
        const uint4* qh = g_QH4 + (size_t)(b*TT + q0)*8;
        const uint4* ql = g_QL4 + (size_t)(b*TT + q0)*8;
        for (int i = tid; i < 2048; i += 256) {
            int sel = i >> 10, j = i & 1023;
            CPA(sb + (sel ? T_QL : T_QH) + j*16, (sel ? ql : qh) + j);
        }
        CPC();
    }
    // ---- issue KV tile (one group each) ----
    auto issue_kv = [&](int t, int s){
        const uint4* s0 = g_KH4 + (size_t)(b*TT + t*128)*8;
        const uint4* s1 = g_KL4 + (size_t)(b*TT + t*128)*8;
        const uint4* s2 = g_VH4 + (size_t)(b*TT + t*128)*8;
        const uint4* s3 = g_VL4 + (size_t)(b*TT + t*128)*8;
        uint32_t base = sb + T_ST + s*65536;
        for (int i = tid; i < 4096; i += 256) {
            int m = i >> 10, j = i & 1023;
            const uint4* src = (m==0) ? s0 : (m==1) ? s1 : (m==2) ? s2 : s3;
            CPA(base + m*16384 + j*16, src + j);
        }
        CPC();
    };
    issue_kv(0, 0);
    CPW(1);              // Q done
    __syncthreads();

    // ---- Q fragments (persistent) ----
    uint32_t qh[4][4], ql[4][4];
    {
        int rr = 16*w + (lane & 7) + ((lane >> 3) & 1)*8;
        #pragma unroll
        for (int k = 0; k < 4; k++) {
            int ch = 2*k + (lane >> 4);
            LDSM4(qh[k], sb + T_QH + swz(rr, ch));
            LDSM4(ql[k], sb + T_QL + swz(rr, ch));
        }
    }

    float o[8][4];
    #pragma unroll
    for (int n = 0; n < 8; n++) { o[n][0]=o[n][1]=o[n][2]=o[n][3]=0.f; }
    float lacc0 = 0.f, lacc1 = 0.f;

    const int rBk = (lane & 7) + (lane >> 4)*8;
    const int chBk = (lane >> 3) & 1;
    const int rBv  = (lane & 7) + ((lane >> 3) & 1)*8;
    const int chBv = (lane >> 4);

    for (int t = 0; t < 16; t++) {
        if (t < 15) { issue_kv(t + 1, (t + 1) & 1); CPW(1); }
        else        { CPW(0); }
        __syncthreads();
        const uint32_t KH = sb + T_ST + (t & 1)*65536;
        const uint32_t KL = KH + 16384, VH = KH + 32768, VL = KH + 49152;

        // ---- S = QK^T, 3-term ----
        uint32_t ph[8][4], pl[8][4];
        #pragma unroll
        for (int n2 = 0; n2 < 8; n2++) {
            float c0[4] = {0,0,0,0}, c1[4] = {0,0,0,0};
            int s0 = n2*16;
            #pragma unroll
            for (int k = 0; k < 4; k++) {
                uint32_t off = swz(s0 + rBk, 2*k + chBk);
                uint32_t bh[4], bl[4];
                LDSM4(bh, KH + off);
                LDSM4(bl, KL + off);
                mma16816(c0, qh[k], bh[0], bh[1]);
                mma16816(c0, ql[k], bh[0], bh[1]);
                mma16816(c0, qh[k], bl[0], bl[1]);
                mma16816(c1, qh[k], bh[2], bh[3]);
                mma16816(c1, ql[k], bh[2], bh[3]);
                mma16816(c1, qh[k], bl[2], bl[3]);
            }
            float e0 = __expf(c0[0]), e1 = __expf(c0[1]);
            float e2 = __expf(c0[2]), e3 = __expf(c0[3]);
            float e4 = __expf(c1[0]), e5 = __expf(c1[1]);
            float e6 = __expf(c1[2]), e7 = __expf(c1[3]);
            lacc0 += e0 + e1 + e4 + e5;
            lacc1 += e2 + e3 + e6 + e7;
            __nv_bfloat16 h0=__float2bfloat16(e0), h1=__float2bfloat16(e1),
                          h2=__float2bfloat16(e2), h3=__float2bfloat16(e3),
                          h4=__float2bfloat16(e4), h5=__float2bfloat16(e5),
                          h6=__float2bfloat16(e6), h7=__float2bfloat16(e7);
            ph[n2][0] = ((uint32_t)__bfloat16_as_ushort(h1)<<16)|__bfloat16_as_ushort(h0);
            ph[n2][1] = ((uint32_t)__bfloat16_as_ushort(h3)<<16)|__bfloat16_as_ushort(h2);
            ph[n2][2] = ((uint32_t)__bfloat16_as_ushort(h5)<<16)|__bfloat16_as_ushort(h4);
            ph[n2][3] = ((uint32_t)__bfloat16_as_ushort(h7)<<16)|__bfloat16_as_ushort(h6);
            pl[n2][0] = packbf(e0-__bfloat162float(h0), e1-__bfloat162float(h1));
            pl[n2][1] = packbf(e2-__bfloat162float(h2), e3-__bfloat162float(h3));
            pl[n2][2] = packbf(e4-__bfloat162float(h4), e5-__bfloat162float(h5));
            pl[n2][3] = packbf(e6-__bfloat162float(h6), e7-__bfloat162float(h7));
        }

        // ---- O += P.V, 3-term ----
        #pragma unroll
        for (int k = 0; k < 8; k++) {
            int s0 = k*16;
            #pragma unroll
            for (int dp = 0; dp < 4; dp++) {
                uint32_t off = swz(s0 + rBv, 2*dp + chBv);
                uint32_t bh[4], bl[4];
                LDSM4T(bh, VH + off);
                LDSM4T(bl, VL + off);
                mma16816(o[2*dp],   ph[k], bh[0], bh[1]);
                mma16816(o[2*dp],   pl[k], bh[0], bh[1]);
                mma16816(o[2*dp],   ph[k], bl[0], bl[1]);
                mma16816(o[2*dp+1], ph[k], bh[2], bh[3]);
                mma16816(o[2*dp+1], pl[k], bh[2], bh[3]);
                mma16816(o[2*dp+1], ph[k], bl[2], bl[3]);
            }
        }
        __syncthreads();
    }

    // ---- finalize: normalize, write pre-split ATT ----
    lacc0 += __shfl_xor_sync(0xffffffffu, lacc0, 1);
    lacc0 += __shfl_xor_sync(0xffffffffu, lacc0, 2);
    lacc1 += __shfl_xor_sync(0xffffffffu, lacc1, 1);
    lacc1 += __shfl_xor_sync(0xffffffffu, lacc1, 2);
    float inv0 = 1.f / lacc0, inv1 = 1.f / lacc1;

    uint32_t* AH = (uint32_t*)g_AH4;
    uint32_t* AL = (uint32_t*)g_AL4;
    int r0 = b*TT + q0 + 16*w + (lane >> 2);
    int cl = (lane & 3)*2;
    #pragma unroll
    for (int n = 0; n < 8; n++) {
        wr_pair64(AH, AL, r0,     n*8 + cl, o[n][0]*inv0, o[n][1]*inv0);
        wr_pair64(AH, AL, r0 + 8, n*8 + cl, o[n][2]*inv1, o[n][3]*inv1);
    }
}

// ===================== conv1d: pre-split operands, X loaded once ===========
// WB = input row bytes (128 or 256); NH = Cin/64; SPLIT: write bf16 out.
// NOTE: smem X row ar holds GLOBAL row t0+ar-1, so its swizzle key is
// (ar-1)&7, not ar&7 (global arrays are swizzled on global row & 7).
template<int WB, int NH, bool SPLIT>
__global__ __launch_bounds__(256) void convt_kernel(
    const uint4* __restrict__ inH4, const uint4* __restrict__ inL4,
    const uint32_t* __restrict__ wH, const uint32_t* __restrict__ wL,
    const float* __restrict__ bias,
    const float* __restrict__ resid, float* __restrict__ outF,
    uint32_t* __restrict__ outH, uint32_t* __restrict__ outL)
{
    extern __shared__ __align__(16) char smp[];
    const uint32_t sb = smem_u32(smp);
    const int b = blockIdx.y, t0 = blockIdx.x*128, z = blockIdx.z;
    const int tid = threadIdx.x, wrp = tid >> 5, lane = tid & 31;

    const int XH = 0, XL = 130*WB;
    const int W0 = 2*130*WB, WL0 = W0 + NH*8192;

    // ---- X halo tile (all ci, both hi/lo), once ----
    const int n4 = 130*(WB/16);
    for (int i = tid; i < 2*n4; i += 256) {
        int sel = (i >= n4); int j = sel ? i - n4 : i;
        int r = j/(WB/16), c = j%(WB/16);
        int t = t0 + r - 1;
        uint4 v = make_uint4(0,0,0,0);
        if (t >= 0 && t < TT) v = (sel ? inL4 : inH4)[(size_t)(b*TT+t)*(WB/16) + c];
        *(uint4*)(smp + (sel ? XL : XH) + r*WB + c*16) = v;
    }

    float o[8][4];
    #pragma unroll
    for (int m = 0; m < 8; m++) { o[m][0]=o[m][1]=o[m][2]=o[m][3]=0.f; }
    const int laneR = (lane & 7) + ((lane >> 3) & 1)*8;
    const int chS   = lane >> 4;

    for (int k = 0; k < 3; k++) {
        __syncthreads();  // X ready (k=0) / prior mma done before W overwrite
        for (int i = tid; i < NH*2*512; i += 256) {
            int sel = (i >= NH*512); int j = sel ? i - NH*512 : i;
            int h = j >> 9, c = j & 511;
            const uint32_t* src = (sel ? wL : wH) + (size_t)((k*NH+h)*2 + z)*2048 + c*4;
            *(uint4*)(smp + (sel ? WL0 : W0) + h*8192 + c*16) = *(const uint4*)src;
        }
        __syncthreads();

        #pragma unroll
        for (int h = 0; h < NH; h++) {
            #pragma unroll
            for (int ks = 0; ks < 4; ks++) {
                int ar = 16*wrp + laneR + k;
                // swizzle key = global row & 7 = (ar-1)&7  (halo shift)
                uint32_t aoff = (uint32_t)(ar*WB + h*128 + (((2*ks+chS) ^ ((ar+7)&7))<<4));
                uint32_t ah[4], al[4];
                LDSM4(ah, sb + XH + aoff);
                LDSM4(al, sb + XL + aoff);
                #pragma unroll
                for (int g = 0; g < 4; g++) {
                    int br = ks*16 + laneR;
                    uint32_t boff = (uint32_t)(h*8192 + br*128 + (((2*g+chS) ^ (br&7))<<4));
                    uint32_t bh[4], bl[4];
                    LDSM4T(bh, sb + W0  + boff);
                    LDSM4T(bl, sb + WL0 + boff);
                    mma16816(o[2*g],   ah, bh[0], bh[1]);
                    mma16816(o[2*g],   al, bh[0], bh[1]);
                    mma16816(o[2*g],   ah, bl[0], bl[1]);
                    mma16816(o[2*g+1], ah, bh[2], bh[3]);
                    mma16816(o[2*g+1], al, bh[2], bh[3]);
                    mma16816(o[2*g+1], ah, bl[2], bl[3]);
                }
            }
        }
    }

    // ---- epilogue ----
    int r0 = t0 + 16*wrp + (lane >> 2);
    #pragma unroll
    for (int m = 0; m < 8; m++) {
        int col = (m >> 1)*16 + (m & 1)*8 + (lane & 3)*2;  // within 64-co block
        int co  = z*64 + col;
        float b0 = bias[co], b1 = bias[co + 1];
        float v0 = fmaxf(o[m][0] + b0, 0.f);
        float v1 = fmaxf(o[m][1] + b1, 0.f);
        float v2 = fmaxf(o[m][2] + b0, 0.f);
        float v3 = fmaxf(o[m][3] + b1, 0.f);
        if (SPLIT) {
            // 256B rows, swizzled pair writes (key = global row & 7)
            #pragma unroll
            for (int rr = 0; rr < 2; rr++) {
                int row = b*TT + r0 + rr*8;
                float a = rr ? v2 : v0, bb = rr ? v3 : v1;
                int ch = co >> 3;
                int chp = (ch & 8) | ((ch ^ (row & 7)) & 7);
                int u = row*64 + (chp << 2) + ((co & 7) >> 1);
                __nv_bfloat16 ha=__float2bfloat16(a), hb=__float2bfloat16(bb);
                outH[u] = ((uint32_t)__bfloat16_as_ushort(hb)<<16)|__bfloat16_as_ushort(ha);
                outL[u] = packbf(a-__bfloat162float(ha), bb-__bfloat162float(hb));
            }
        } else {
            size_t base0 = (size_t)(b*TT + r0)*NOUT + co;
            size_t base1 = (size_t)(b*TT + r0 + 8)*NOUT + co;
            float2 ra = *(const float2*)(resid + base0);
            float2 rb = *(const float2*)(resid + base1);
            float2 s0; s0.x = fmaxf(v0 + ra.x, 0.f); s0.y = fmaxf(v1 + ra.y, 0.f);
            float2 s1; s1.x = fmaxf(v2 + rb.x, 0.f); s1.y = fmaxf(v3 + rb.y, 0.f);
            *(float2*)(outF + base0) = s0;
            *(float2*)(outF + base1) = s1;
        }
    }
}

// ---------------------------------------------------------------------------
extern "C" void kernel_launch(void* const* d_in, const int* in_sizes, int n_in,
                              void* d_out, int out_size)
{
    const float* x       = (const float*)d_in[0];
    const float* qkv_w   = (const float*)d_in[1];
    const float* qkv_b   = (const float*)d_in[2];
    const float* scale   = (const float*)d_in[3];
    const float* conv_w1 = (const float*)d_in[4];
    const float* conv_b1 = (const float*)d_in[5];
    const float* conv_w2 = (const float*)d_in[6];
    const float* conv_b2 = (const float*)d_in[7];
    const float* down_w  = (const float*)d_in[8];
    float* out = (float*)d_out;

    const int SM1 = 2*130*128 + 2*8192;          // 49664
    const int SM2 = 2*130*256 + 2*2*8192;        // 99328

    cudaFuncSetAttribute(proj_kernel,  cudaFuncAttributeMaxDynamicSharedMemorySize, PROJ_SMEM);
    cudaFuncSetAttribute(attn4_kernel, cudaFuncAttributeMaxDynamicSharedMemorySize, ATTN4_SMEM);
    cudaFuncSetAttribute((const void*)convt_kernel<128,1,true>,
                         cudaFuncAttributeMaxDynamicSharedMemorySize, SM1);
    cudaFuncSetAttribute((const void*)convt_kernel<256,2,false>,
                         cudaFuncAttributeMaxDynamicSharedMemorySize, SM2);

    uint4 *aH, *aL, *hH, *hL, *w1H, *w1L, *w2H, *w2L;
    float *xdw;
    cudaGetSymbolAddress((void**)&aH,  g_AH4);
    cudaGetSymbolAddress((void**)&aL,  g_AL4);
    cudaGetSymbolAddress((void**)&hH,  g_HH4);
    cudaGetSymbolAddress((void**)&hL,  g_HL4);
    cudaGetSymbolAddress((void**)&w1H, g_W1H4);
    cudaGetSymbolAddress((void**)&w1L, g_W1L4);
    cudaGetSymbolAddress((void**)&w2H, g_W2H4);
    cudaGetSymbolAddress((void**)&w2L, g_W2L4);
    cudaGetSymbolAddress((void**)&xdw, g_XDW);

    prep_w_kernel<<<48, 256>>>(conv_w1, 64,  (uint32_t*)w1H, (uint32_t*)w1L);
    prep_w_kernel<<<96, 256>>>(conv_w2, 128, (uint32_t*)w2H, (uint32_t*)w2L);
    proj_kernel <<<dim3(BT/128, 5), 256, PROJ_SMEM>>>(x, qkv_w, qkv_b, scale, down_w);
    attn4_kernel<<<dim3(TT/128, BB), 256, ATTN4_SMEM>>>();
    convt_kernel<128,1,true ><<<dim3(TT/128, BB, 2), 256, SM1>>>(
        aH, aL, (uint32_t*)w1H, (uint32_t*)w1L, conv_b1, nullptr, nullptr,
        (uint32_t*)hH, (uint32_t*)hL);
    convt_kernel<256,2,false><<<dim3(TT/128, BB, 2), 256, SM2>>>(
        hH, hL, (uint32_t*)w2H, (uint32_t*)w2L, conv_b2, xdw, out,
        nullptr, nullptr);
}

// round 9
// speedup vs baseline: 1.0879x; 1.0879x over previous
#include <cuda_runtime.h>
#include <cuda_bf16.h>
#include <cstdint>

#define BB   16
#define TT   2048
#define NIN  96
#define NOUT 128
#define DD   64
#define BT   (BB*TT)

// ---- global scratch (pre-split bf16 hi/lo, swizzled 128B/256B rows) ----
__device__ uint4 g_QH4[BT*8]; __device__ uint4 g_QL4[BT*8];
__device__ uint4 g_KH4[BT*8]; __device__ uint4 g_KL4[BT*8];
__device__ uint4 g_VH4[BT*8]; __device__ uint4 g_VL4[BT*8];
__device__ uint4 g_AH4[BT*8]; __device__ uint4 g_AL4[BT*8];   // attn out
__device__ uint4 g_HH4[BT*16]; __device__ uint4 g_HL4[BT*16]; // conv1 out (256B rows)
__device__ float g_XDW[BT*NOUT];
__device__ uint4 g_W1H4[3*2*512];   __device__ uint4 g_W1L4[3*2*512];
__device__ uint4 g_W2H4[3*2*2*512]; __device__ uint4 g_W2L4[3*2*2*512];

// ===================== helpers =====================
__device__ __forceinline__ uint32_t smem_u32(const void* p){
    uint32_t a;
    asm("{ .reg .u64 t; cvta.to.shared.u64 t, %1; cvt.u32.u64 %0, t; }" : "=r"(a) : "l"(p));
    return a;
}
#define LDSM4(R, A) \
    asm volatile("ldmatrix.sync.aligned.m8n8.x4.shared.b16 {%0,%1,%2,%3}, [%4];" \
        : "=r"((R)[0]),"=r"((R)[1]),"=r"((R)[2]),"=r"((R)[3]) : "r"(A))
#define LDSM4T(R, A) \
    asm volatile("ldmatrix.sync.aligned.m8n8.x4.trans.shared.b16 {%0,%1,%2,%3}, [%4];" \
        : "=r"((R)[0]),"=r"((R)[1]),"=r"((R)[2]),"=r"((R)[3]) : "r"(A))
#define CPA(dst, src) \
    asm volatile("cp.async.cg.shared.global [%0], [%1], 16;" :: "r"(dst), "l"(src))
#define CPC() asm volatile("cp.async.commit_group;")
#define CPW(n) asm volatile("cp.async.wait_group %0;" :: "n"(n))

__device__ __forceinline__ void mma16816(float* c, const uint32_t* a, uint32_t b0, uint32_t b1){
    asm volatile(
        "mma.sync.aligned.m16n8k16.row.col.f32.bf16.bf16.f32 "
        "{%0,%1,%2,%3},{%4,%5,%6,%7},{%8,%9},{%0,%1,%2,%3};"
        : "+f"(c[0]),"+f"(c[1]),"+f"(c[2]),"+f"(c[3])
        : "r"(a[0]),"r"(a[1]),"r"(a[2]),"r"(a[3]),"r"(b0),"r"(b1));
}
__device__ __forceinline__ uint32_t packbf(float lo, float hi){
    uint16_t l = __bfloat16_as_ushort(__float2bfloat16(lo));
    uint16_t h = __bfloat16_as_ushort(__float2bfloat16(hi));
    return ((uint32_t)h << 16) | (uint32_t)l;
}
__device__ __forceinline__ uint32_t swz(int r, int ch){
    return (uint32_t)(r*128 + ((ch ^ (r & 7)) << 4));
}
// write a hi/lo split pair (cols cl, cl+1, cl even) into 128B-row global arrays
__device__ __forceinline__ void wr_pair64(uint32_t* H, uint32_t* L, int row, int cl,
                                          float a, float bvv){
    int byte = cl*2;
    int u = row*32 + (((byte>>4) ^ (row&7))<<2) + ((byte&15)>>2);
    __nv_bfloat16 ha=__float2bfloat16(a), hb=__float2bfloat16(bvv);
    H[u] = ((uint32_t)__bfloat16_as_ushort(hb)<<16)|__bfloat16_as_ushort(ha);
    L[u] = packbf(a-__bfloat162float(ha), bvv-__bfloat162float(hb));
}

// ===================== weight prep: split + swizzle into tile images ========
__global__ void prep_w_kernel(const float* __restrict__ w, int Cin,
                              uint32_t* __restrict__ wH, uint32_t* __restrict__ wL)
{
    int nh = Cin >> 6;
    int total = 3*Cin*64;   // co-pairs
    for (int idx = blockIdx.x*blockDim.x + threadIdx.x; idx < total;
         idx += gridDim.x*blockDim.x) {
        int k = idx/(Cin*64); int rem = idx - k*Cin*64;
        int ci = rem >> 6, cop = rem & 63;
        float2 v = *(const float2*)(w + (size_t)(k*Cin+ci)*NOUT + cop*2);
        int hci = ci>>6, cil = ci&63, hco = cop>>5, copl = cop&31;
        int tidx = (k*nh + hci)*2 + hco;
        int u = tidx*2048 + cil*32 + (((copl>>2) ^ (cil&7))<<2) + (copl&3);
        __nv_bfloat16 hx=__float2bfloat16(v.x), hy=__float2bfloat16(v.y);
        wH[u] = ((uint32_t)__bfloat16_as_ushort(hy)<<16)|__bfloat16_as_ushort(hx);
        wL[u] = packbf(v.x-__bfloat162float(hx), v.y-__bfloat162float(hy));
    }
}

// ===================== proj: GEMM + split/swizzle epilogue =================
#define PROJ_XS_F   (128*97)
#define PROJ_SMEM   ((PROJ_XS_F + 96*64)*4)
__global__ __launch_bounds__(256) void proj_kernel(
    const float* __restrict__ x, const float* __restrict__ qkv_w,
    const float* __restrict__ qkv_b, const float* __restrict__ scale,
    const float* __restrict__ down_w)
{
    extern __shared__ float sm[];
    float* Xs = sm;
    float* Ws = sm + PROJ_XS_F;
    const int row0 = blockIdx.x * 128;
    const int col0 = blockIdx.y * 64;
    const int tid  = threadIdx.x;

    for (int idx = tid; idx < 128*96; idx += 256) {
        int i = idx / 96, k = idx - i*96;
        Xs[i*97 + k] = x[(row0 + i)*NIN + k];
    }
    for (int idx = tid; idx < 96*64; idx += 256) {
        int k = idx >> 6, j = idx & 63;
        int col = col0 + j;
        Ws[idx] = (col < 192) ? qkv_w[k*192 + col] : down_w[k*128 + (col - 192)];
    }
    __syncthreads();

    const int tr = tid >> 4, tc = tid & 15;
    const int i0 = tr*8, j0 = tc*4;
    float acc[8][4];
    #pragma unroll
    for (int r = 0; r < 8; r++) { acc[r][0]=acc[r][1]=acc[r][2]=acc[r][3]=0.f; }

    #pragma unroll 4
    for (int k = 0; k < 96; k++) {
        float4 bv = *reinterpret_cast<const float4*>(&Ws[k*64 + j0]);
        #pragma unroll
        for (int r = 0; r < 8; r++) {
            float a = Xs[(i0 + r)*97 + k];
            acc[r][0] += a*bv.x; acc[r][1] += a*bv.y;
            acc[r][2] += a*bv.z; acc[r][3] += a*bv.w;
        }
    }

    const float sc    = scale[0];
    const float enres = 1.0f + 1.0f/(float)TT;
    const int yb = blockIdx.y;
    uint32_t *H = nullptr, *L = nullptr;
    if      (yb == 0) { H = (uint32_t*)g_QH4; L = (uint32_t*)g_QL4; }
    else if (yb == 1) { H = (uint32_t*)g_KH4; L = (uint32_t*)g_KL4; }
    else if (yb == 2) { H = (uint32_t*)g_VH4; L = (uint32_t*)g_VL4; }

    #pragma unroll
    for (int r = 0; r < 8; r++) {
        int row = row0 + i0 + r;
        if (yb < 3) {
            float v0 = acc[r][0] + qkv_b[col0 + j0 + 0];
            float v1 = acc[r][1] + qkv_b[col0 + j0 + 1];
            float v2 = acc[r][2] + qkv_b[col0 + j0 + 2];
            float v3 = acc[r][3] + qkv_b[col0 + j0 + 3];
            if (yb == 0) { v0*=sc; v1*=sc; v2*=sc; v3*=sc; }
            wr_pair64(H, L, row, j0,     v0, v1);
            wr_pair64(H, L, row, j0 + 2, v2, v3);
        } else {
            #pragma unroll
            for (int c = 0; c < 4; c++) {
                int col = col0 + j0 + c - 192;
                g_XDW[row*NOUT + col] = acc[r][c] * enres;
            }
        }
    }
}

// ===================== attention: 2 CTAs/SM, S/PV interleaved ==============
// smem: QH 16K | QL 16K | one KV stage {KH,KL,VH,VL} 64K = 96KB -> 2 CTAs/SM.
// Registers capped at 128 by launch_bounds(256,2): per-s-block P fragments are
// consumed immediately (no [8][4] array). Cross-CTA overlap hides loads.
#define T_QH 0
#define T_QL 16384
#define T_KV 32768
#define ATTN5_SMEM 98304

__global__ __launch_bounds__(256, 2) void attn5_kernel()
{
    extern __shared__ __align__(16) char smp[];
    const uint32_t sb = smem_u32(smp);
    const int b    = blockIdx.y;
    const int q0   = blockIdx.x * 128;
    const int tid  = threadIdx.x;
    const int w    = tid >> 5;
    const int lane = tid & 31;

    auto issue_kv = [&](int t){
        const uint4* s0 = g_KH4 + (size_t)(b*TT + t*128)*8;
        const uint4* s1 = g_KL4 + (size_t)(b*TT + t*128)*8;
        const uint4* s2 = g_VH4 + (size_t)(b*TT + t*128)*8;
        const uint4* s3 = g_VL4 + (size_t)(b*TT + t*128)*8;
        uint32_t base = sb + T_KV;
        for (int i = tid; i < 4096; i += 256) {
            int m = i >> 10, j = i & 1023;
            const uint4* src = (m==0) ? s0 : (m==1) ? s1 : (m==2) ? s2 : s3;
            CPA(base + m*16384 + j*16, src + j);
        }
        CPC();
    };

    // ---- Q + first KV tile ----
    {
        const uint4* qh4 = g_QH4 + (size_t)(b*TT + q0)*8;
        const uint4* ql4 = g_QL4 + (size_t)(b*TT + q0)*8;
        for (int i = tid; i < 2048; i += 256) {
            int sel = i >> 10, j = i & 1023;
            CPA(sb + (sel ? T_QL : T_QH) + j*16, (sel ? ql4 : qh4) + j);
        }
        CPC();
        issue_kv(0);
        CPW(0);
        __syncthreads();
    }

    // ---- Q fragments (persistent) ----
    uint32_t qh[4][4], ql[4][4];
    {
        int rr = 16*w + (lane & 7) + ((lane >> 3) & 1)*8;
        #pragma unroll
        for (int k = 0; k < 4; k++) {
            int ch = 2*k + (lane >> 4);
            LDSM4(qh[k], sb + T_QH + swz(rr, ch));
            LDSM4(ql[k], sb + T_QL + swz(rr, ch));
        }
    }

    float o[8][4];
    #pragma unroll
    for (int n = 0; n < 8; n++) { o[n][0]=o[n][1]=o[n][2]=o[n][3]=0.f; }
    float lacc0 = 0.f, lacc1 = 0.f;

    const int rBk  = (lane & 7) + (lane >> 4)*8;
    const int chBk = (lane >> 3) & 1;
    const int rBv  = (lane & 7) + ((lane >> 3) & 1)*8;
    const int chBv = (lane >> 4);
    const uint32_t KH = sb + T_KV, KL = KH + 16384, VH = KH + 32768, VL = KH + 49152;

    for (int t = 0; t < 16; t++) {
        if (t > 0) {
            __syncthreads();        // prior compute done before overwrite
            issue_kv(t);
            CPW(0);
            __syncthreads();
        }

        #pragma unroll
        for (int n2 = 0; n2 < 8; n2++) {
            // ---- S block (16 s-cols), 3-term ----
            float c0[4] = {0,0,0,0}, c1[4] = {0,0,0,0};
            int s0 = n2*16;
            #pragma unroll
            for (int k = 0; k < 4; k++) {
                uint32_t off = swz(s0 + rBk, 2*k + chBk);
                uint32_t bh[4], bl[4];
                LDSM4(bh, KH + off);
                LDSM4(bl, KL + off);
                mma16816(c0, qh[k], bh[0], bh[1]);
                mma16816(c0, ql[k], bh[0], bh[1]);
                mma16816(c0, qh[k], bl[0], bl[1]);
                mma16816(c1, qh[k], bh[2], bh[3]);
                mma16816(c1, ql[k], bh[2], bh[3]);
                mma16816(c1, qh[k], bl[2], bl[3]);
            }
            // ---- exp + pack (consumed immediately) ----
            float e0 = __expf(c0[0]), e1 = __expf(c0[1]);
            float e2 = __expf(c0[2]), e3 = __expf(c0[3]);
            float e4 = __expf(c1[0]), e5 = __expf(c1[1]);
            float e6 = __expf(c1[2]), e7 = __expf(c1[3]);
            lacc0 += e0 + e1 + e4 + e5;
            lacc1 += e2 + e3 + e6 + e7;
            __nv_bfloat16 h0=__float2bfloat16(e0), h1=__float2bfloat16(e1),
                          h2=__float2bfloat16(e2), h3=__float2bfloat16(e3),
                          h4=__float2bfloat16(e4), h5=__float2bfloat16(e5),
                          h6=__float2bfloat16(e6), h7=__float2bfloat16(e7);
            uint32_t ph[4], pl[4];
            ph[0] = ((uint32_t)__bfloat16_as_ushort(h1)<<16)|__bfloat16_as_ushort(h0);
            ph[1] = ((uint32_t)__bfloat16_as_ushort(h3)<<16)|__bfloat16_as_ushort(h2);
            ph[2] = ((uint32_t)__bfloat16_as_ushort(h5)<<16)|__bfloat16_as_ushort(h4);
            ph[3] = ((uint32_t)__bfloat16_as_ushort(h7)<<16)|__bfloat16_as_ushort(h6);
            pl[0] = packbf(e0-__bfloat162float(h0), e1-__bfloat162float(h1));
            pl[1] = packbf(e2-__bfloat162float(h2), e3-__bfloat162float(h3));
            pl[2] = packbf(e4-__bfloat162float(h4), e5-__bfloat162float(h5));
            pl[3] = packbf(e6-__bfloat162float(h6), e7-__bfloat162float(h7));

            // ---- PV for this s-block, 3-term ----
            #pragma unroll
            for (int dp = 0; dp < 4; dp++) {
                uint32_t off = swz(s0 + rBv, 2*dp + chBv);
                uint32_t bh[4], bl[4];
                LDSM4T(bh, VH + off);
                LDSM4T(bl, VL + off);
                mma16816(o[2*dp],   ph, bh[0], bh[1]);
                mma16816(o[2*dp],   pl, bh[0], bh[1]);
                mma16816(o[2*dp],   ph, bl[0], bl[1]);
                mma16816(o[2*dp+1], ph, bh[2], bh[3]);
                mma16816(o[2*dp+1], pl, bh[2], bh[3]);
                mma16816(o[2*dp+1], ph, bl[2], bl[3]);
            }
        }
    }

    // ---- finalize: normalize, write pre-split ATT ----
    lacc0 += __shfl_xor_sync(0xffffffffu, lacc0, 1);
    lacc0 += __shfl_xor_sync(0xffffffffu, lacc0, 2);
    lacc1 += __shfl_xor_sync(0xffffffffu, lacc1, 1);
    lacc1 += __shfl_xor_sync(0xffffffffu, lacc1, 2);
    float inv0 = 1.f / lacc0, inv1 = 1.f / lacc1;

    uint32_t* AH = (uint32_t*)g_AH4;
    uint32_t* AL = (uint32_t*)g_AL4;
    int r0 = b*TT + q0 + 16*w + (lane >> 2);
    int cl = (lane & 3)*2;
    #pragma unroll
    for (int n = 0; n < 8; n++) {
        wr_pair64(AH, AL, r0,     n*8 + cl, o[n][0]*inv0, o[n][1]*inv0);
        wr_pair64(AH, AL, r0 + 8, n*8 + cl, o[n][2]*inv1, o[n][3]*inv1);
    }
}

// ===================== conv1d: pre-split operands, X loaded once ===========
// WB = input row bytes (128 or 256); NH = Cin/64; SPLIT: write bf16 out.
// NOTE: smem X row ar holds GLOBAL row t0+ar-1, so swizzle key is (ar-1)&7.
template<int WB, int NH, bool SPLIT>
__global__ __launch_bounds__(256) void convt_kernel(
    const uint4* __restrict__ inH4, const uint4* __restrict__ inL4,
    const uint32_t* __restrict__ wH, const uint32_t* __restrict__ wL,
    const float* __restrict__ bias,
    const float* __restrict__ resid, float* __restrict__ outF,
    uint32_t* __restrict__ outH, uint32_t* __restrict__ outL)
{
    extern __shared__ __align__(16) char smp[];
    const uint32_t sb = smem_u32(smp);
    const int b = blockIdx.y, t0 = blockIdx.x*128, z = blockIdx.z;
    const int tid = threadIdx.x, wrp = tid >> 5, lane = tid & 31;

    const int XH = 0, XL = 130*WB;
    const int W0 = 2*130*WB, WL0 = W0 + NH*8192;

    // ---- X halo tile (all ci, both hi/lo), once ----
    const int n4 = 130*(WB/16);
    for (int i = tid; i < 2*n4; i += 256) {
        int sel = (i >= n4); int j = sel ? i - n4 : i;
        int r = j/(WB/16), c = j%(WB/16);
        int t = t0 + r - 1;
        uint4 v = make_uint4(0,0,0,0);
        if (t >= 0 && t < TT) v = (sel ? inL4 : inH4)[(size_t)(b*TT+t)*(WB/16) + c];
        *(uint4*)(smp + (sel ? XL : XH) + r*WB + c*16) = v;
    }

    float o[8][4];
    #pragma unroll
    for (int m = 0; m < 8; m++) { o[m][0]=o[m][1]=o[m][2]=o[m][3]=0.f; }
    const int laneR = (lane & 7) + ((lane >> 3) & 1)*8;
    const int chS   = lane >> 4;

    for (int k = 0; k < 3; k++) {
        __syncthreads();  // X ready (k=0) / prior mma done before W overwrite
        for (int i = tid; i < NH*2*512; i += 256) {
            int sel = (i >= NH*512); int j = sel ? i - NH*512 : i;
            int h = j >> 9, c = j & 511;
            const uint32_t* src = (sel ? wL : wH) + (size_t)((k*NH+h)*2 + z)*2048 + c*4;
            *(uint4*)(smp + (sel ? WL0 : W0) + h*8192 + c*16) = *(const uint4*)src;
        }
        __syncthreads();

        #pragma unroll
        for (int h = 0; h < NH; h++) {
            #pragma unroll
            for (int ks = 0; ks < 4; ks++) {
                int ar = 16*wrp + laneR + k;
                // swizzle key = global row & 7 = (ar-1)&7  (halo shift)
                uint32_t aoff = (uint32_t)(ar*WB + h*128 + (((2*ks+chS) ^ ((ar+7)&7))<<4));
                uint32_t ah[4], al[4];
                LDSM4(ah, sb + XH + aoff);
                LDSM4(al, sb + XL + aoff);
                #pragma unroll
                for (int g = 0; g < 4; g++) {
                    int br = ks*16 + laneR;
                    uint32_t boff = (uint32_t)(h*8192 + br*128 + (((2*g+chS) ^ (br&7))<<4));
                    uint32_t bh[4], bl[4];
                    LDSM4T(bh, sb + W0  + boff);
                    LDSM4T(bl, sb + WL0 + boff);
                    mma16816(o[2*g],   ah, bh[0], bh[1]);
                    mma16816(o[2*g],   al, bh[0], bh[1]);
                    mma16816(o[2*g],   ah, bl[0], bl[1]);
                    mma16816(o[2*g+1], ah, bh[2], bh[3]);
                    mma16816(o[2*g+1], al, bh[2], bh[3]);
                    mma16816(o[2*g+1], ah, bl[2], bl[3]);
                }
            }
        }
    }

    // ---- epilogue ----
    int r0 = t0 + 16*wrp + (lane >> 2);
    #pragma unroll
    for (int m = 0; m < 8; m++) {
        int col = (m >> 1)*16 + (m & 1)*8 + (lane & 3)*2;  // within 64-co block
        int co  = z*64 + col;
        float b0 = bias[co], b1 = bias[co + 1];
        float v0 = fmaxf(o[m][0] + b0, 0.f);
        float v1 = fmaxf(o[m][1] + b1, 0.f);
        float v2 = fmaxf(o[m][2] + b0, 0.f);
        float v3 = fmaxf(o[m][3] + b1, 0.f);
        if (SPLIT) {
            #pragma unroll
            for (int rr = 0; rr < 2; rr++) {
                int row = b*TT + r0 + rr*8;
                float a = rr ? v2 : v0, bb = rr ? v3 : v1;
                int ch = co >> 3;
                int chp = (ch & 8) | ((ch ^ (row & 7)) & 7);
                int u = row*64 + (chp << 2) + ((co & 7) >> 1);
                __nv_bfloat16 ha=__float2bfloat16(a), hb=__float2bfloat16(bb);
                outH[u] = ((uint32_t)__bfloat16_as_ushort(hb)<<16)|__bfloat16_as_ushort(ha);
                outL[u] = packbf(a-__bfloat162float(ha), bb-__bfloat162float(hb));
            }
        } else {
            size_t base0 = (size_t)(b*TT + r0)*NOUT + co;
            size_t base1 = (size_t)(b*TT + r0 + 8)*NOUT + co;
            float2 ra = *(const float2*)(resid + base0);
            float2 rb = *(const float2*)(resid + base1);
            float2 s0; s0.x = fmaxf(v0 + ra.x, 0.f); s0.y = fmaxf(v1 + ra.y, 0.f);
            float2 s1; s1.x = fmaxf(v2 + rb.x, 0.f); s1.y = fmaxf(v3 + rb.y, 0.f);
            *(float2*)(outF + base0) = s0;
            *(float2*)(outF + base1) = s1;
        }
    }
}

// ---------------------------------------------------------------------------
extern "C" void kernel_launch(void* const* d_in, const int* in_sizes, int n_in,
                              void* d_out, int out_size)
{
    const float* x       = (const float*)d_in[0];
    const float* qkv_w   = (const float*)d_in[1];
    const float* qkv_b   = (const float*)d_in[2];
    const float* scale   = (const float*)d_in[3];
    const float* conv_w1 = (const float*)d_in[4];
    const float* conv_b1 = (const float*)d_in[5];
    const float* conv_w2 = (const float*)d_in[6];
    const float* conv_b2 = (const float*)d_in[7];
    const float* down_w  = (const float*)d_in[8];
    float* out = (float*)d_out;

    const int SM1 = 2*130*128 + 2*8192;          // 49664
    const int SM2 = 2*130*256 + 2*2*8192;        // 99328

    cudaFuncSetAttribute(proj_kernel,  cudaFuncAttributeMaxDynamicSharedMemorySize, PROJ_SMEM);
    cudaFuncSetAttribute(attn5_kernel, cudaFuncAttributeMaxDynamicSharedMemorySize, ATTN5_SMEM);
    cudaFuncSetAttribute((const void*)convt_kernel<128,1,true>,
                         cudaFuncAttributeMaxDynamicSharedMemorySize, SM1);
    cudaFuncSetAttribute((const void*)convt_kernel<256,2,false>,
                         cudaFuncAttributeMaxDynamicSharedMemorySize, SM2);

    uint4 *aH, *aL, *hH, *hL, *w1H, *w1L, *w2H, *w2L;
    float *xdw;
    cudaGetSymbolAddress((void**)&aH,  g_AH4);
    cudaGetSymbolAddress((void**)&aL,  g_AL4);
    cudaGetSymbolAddress((void**)&hH,  g_HH4);
    cudaGetSymbolAddress((void**)&hL,  g_HL4);
    cudaGetSymbolAddress((void**)&w1H, g_W1H4);
    cudaGetSymbolAddress((void**)&w1L, g_W1L4);
    cudaGetSymbolAddress((void**)&w2H, g_W2H4);
    cudaGetSymbolAddress((void**)&w2L, g_W2L4);
    cudaGetSymbolAddress((void**)&xdw, g_XDW);

    prep_w_kernel<<<48, 256>>>(conv_w1, 64,  (uint32_t*)w1H, (uint32_t*)w1L);
    prep_w_kernel<<<96, 256>>>(conv_w2, 128, (uint32_t*)w2H, (uint32_t*)w2L);
    proj_kernel <<<dim3(BT/128, 5), 256, PROJ_SMEM>>>(x, qkv_w, qkv_b, scale, down_w);
    attn5_kernel<<<dim3(TT/128, BB), 256, ATTN5_SMEM>>>();
    convt_kernel<128,1,true ><<<dim3(TT/128, BB, 2), 256, SM1>>>(
        aH, aL, (uint32_t*)w1H, (uint32_t*)w1L, conv_b1, nullptr, nullptr,
        (uint32_t*)hH, (uint32_t*)hL);
    convt_kernel<256,2,false><<<dim3(TT/128, BB, 2), 256, SM2>>>(
        hH, hL, (uint32_t*)w2H, (uint32_t*)w2L, conv_b2, xdw, out,
        nullptr, nullptr);
}

// round 10
// speedup vs baseline: 1.1293x; 1.0380x over previous
#include <cuda_runtime.h>
#include <cuda_bf16.h>
#include <cstdint>

#define BB   16
#define TT   2048
#define NIN  96
#define NOUT 128
#define DD   64
#define BT   (BB*TT)

// ---- global scratch (pre-split bf16 hi/lo, swizzled 128B/256B rows) ----
__device__ uint4 g_QH4[BT*8]; __device__ uint4 g_QL4[BT*8];
__device__ uint4 g_KH4[BT*8]; __device__ uint4 g_KL4[BT*8];
__device__ uint4 g_VH4[BT*8]; __device__ uint4 g_VL4[BT*8];
__device__ uint4 g_AH4[BT*8]; __device__ uint4 g_AL4[BT*8];   // attn out
__device__ uint4 g_HH4[BT*16]; __device__ uint4 g_HL4[BT*16]; // conv1 out (256B rows)
__device__ float g_XDW[BT*NOUT];
__device__ uint4 g_W1H4[3*2*512];   __device__ uint4 g_W1L4[3*2*512];
__device__ uint4 g_W2H4[3*2*2*512]; __device__ uint4 g_W2L4[3*2*2*512];

// ===================== helpers =====================
__device__ __forceinline__ uint32_t smem_u32(const void* p){
    uint32_t a;
    asm("{ .reg .u64 t; cvta.to.shared.u64 t, %1; cvt.u32.u64 %0, t; }" : "=r"(a) : "l"(p));
    return a;
}
#define LDSM4(R, A) \
    asm volatile("ldmatrix.sync.aligned.m8n8.x4.shared.b16 {%0,%1,%2,%3}, [%4];" \
        : "=r"((R)[0]),"=r"((R)[1]),"=r"((R)[2]),"=r"((R)[3]) : "r"(A))
#define LDSM4T(R, A) \
    asm volatile("ldmatrix.sync.aligned.m8n8.x4.trans.shared.b16 {%0,%1,%2,%3}, [%4];" \
        : "=r"((R)[0]),"=r"((R)[1]),"=r"((R)[2]),"=r"((R)[3]) : "r"(A))
#define CPA(dst, src) \
    asm volatile("cp.async.cg.shared.global [%0], [%1], 16;" :: "r"(dst), "l"(src))
#define CPC() asm volatile("cp.async.commit_group;")
#define CPW(n) asm volatile("cp.async.wait_group %0;" :: "n"(n))

__device__ __forceinline__ void mma16816(float* c, const uint32_t* a, uint32_t b0, uint32_t b1){
    asm volatile(
        "mma.sync.aligned.m16n8k16.row.col.f32.bf16.bf16.f32 "
        "{%0,%1,%2,%3},{%4,%5,%6,%7},{%8,%9},{%0,%1,%2,%3};"
        : "+f"(c[0]),"+f"(c[1]),"+f"(c[2]),"+f"(c[3])
        : "r"(a[0]),"r"(a[1]),"r"(a[2]),"r"(a[3]),"r"(b0),"r"(b1));
}
__device__ __forceinline__ uint32_t packbf(float lo, float hi){
    uint16_t l = __bfloat16_as_ushort(__float2bfloat16(lo));
    uint16_t h = __bfloat16_as_ushort(__float2bfloat16(hi));
    return ((uint32_t)h << 16) | (uint32_t)l;
}
__device__ __forceinline__ uint32_t swz(int r, int ch){
    return (uint32_t)(r*128 + ((ch ^ (r & 7)) << 4));
}
// write a hi/lo split pair (cols cl, cl+1, cl even) into 128B-row global arrays
__device__ __forceinline__ void wr_pair64(uint32_t* H, uint32_t* L, int row, int cl,
                                          float a, float bvv){
    int byte = cl*2;
    int u = row*32 + (((byte>>4) ^ (row&7))<<2) + ((byte&15)>>2);
    __nv_bfloat16 ha=__float2bfloat16(a), hb=__float2bfloat16(bvv);
    H[u] = ((uint32_t)__bfloat16_as_ushort(hb)<<16)|__bfloat16_as_ushort(ha);
    L[u] = packbf(a-__bfloat162float(ha), bvv-__bfloat162float(hb));
}

// ===================== weight prep: split + swizzle into tile images ========
__global__ void prep_w_kernel(const float* __restrict__ w, int Cin,
                              uint32_t* __restrict__ wH, uint32_t* __restrict__ wL)
{
    int nh = Cin >> 6;
    int total = 3*Cin*64;   // co-pairs
    for (int idx = blockIdx.x*blockDim.x + threadIdx.x; idx < total;
         idx += gridDim.x*blockDim.x) {
        int k = idx/(Cin*64); int rem = idx - k*Cin*64;
        int ci = rem >> 6, cop = rem & 63;
        float2 v = *(const float2*)(w + (size_t)(k*Cin+ci)*NOUT + cop*2);
        int hci = ci>>6, cil = ci&63, hco = cop>>5, copl = cop&31;
        int tidx = (k*nh + hci)*2 + hco;
        int u = tidx*2048 + cil*32 + (((copl>>2) ^ (cil&7))<<2) + (copl&3);
        __nv_bfloat16 hx=__float2bfloat16(v.x), hy=__float2bfloat16(v.y);
        wH[u] = ((uint32_t)__bfloat16_as_ushort(hy)<<16)|__bfloat16_as_ushort(hx);
        wL[u] = packbf(v.x-__bfloat162float(hx), v.y-__bfloat162float(hy));
    }
}

// ===================== proj: GEMM + split/swizzle epilogue =================
#define PROJ_XS_F   (128*97)
#define PROJ_SMEM   ((PROJ_XS_F + 96*64)*4)
__global__ __launch_bounds__(256) void proj_kernel(
    const float* __restrict__ x, const float* __restrict__ qkv_w,
    const float* __restrict__ qkv_b, const float* __restrict__ scale,
    const float* __restrict__ down_w)
{
    extern __shared__ float sm[];
    float* Xs = sm;
    float* Ws = sm + PROJ_XS_F;
    const int row0 = blockIdx.x * 128;
    const int col0 = blockIdx.y * 64;
    const int tid  = threadIdx.x;

    for (int idx = tid; idx < 128*96; idx += 256) {
        int i = idx / 96, k = idx - i*96;
        Xs[i*97 + k] = x[(row0 + i)*NIN + k];
    }
    for (int idx = tid; idx < 96*64; idx += 256) {
        int k = idx >> 6, j = idx & 63;
        int col = col0 + j;
        Ws[idx] = (col < 192) ? qkv_w[k*192 + col] : down_w[k*128 + (col - 192)];
    }
    __syncthreads();

    const int tr = tid >> 4, tc = tid & 15;
    const int i0 = tr*8, j0 = tc*4;
    float acc[8][4];
    #pragma unroll
    for (int r = 0; r < 8; r++) { acc[r][0]=acc[r][1]=acc[r][2]=acc[r][3]=0.f; }

    #pragma unroll 4
    for (int k = 0; k < 96; k++) {
        float4 bv = *reinterpret_cast<const float4*>(&Ws[k*64 + j0]);
        #pragma unroll
        for (int r = 0; r < 8; r++) {
            float a = Xs[(i0 + r)*97 + k];
            acc[r][0] += a*bv.x; acc[r][1] += a*bv.y;
            acc[r][2] += a*bv.z; acc[r][3] += a*bv.w;
        }
    }

    const float sc    = scale[0];
    const float enres = 1.0f + 1.0f/(float)TT;
    const int yb = blockIdx.y;
    uint32_t *H = nullptr, *L = nullptr;
    if      (yb == 0) { H = (uint32_t*)g_QH4; L = (uint32_t*)g_QL4; }
    else if (yb == 1) { H = (uint32_t*)g_KH4; L = (uint32_t*)g_KL4; }
    else if (yb == 2) { H = (uint32_t*)g_VH4; L = (uint32_t*)g_VL4; }

    #pragma unroll
    for (int r = 0; r < 8; r++) {
        int row = row0 + i0 + r;
        if (yb < 3) {
            float v0 = acc[r][0] + qkv_b[col0 + j0 + 0];
            float v1 = acc[r][1] + qkv_b[col0 + j0 + 1];
            float v2 = acc[r][2] + qkv_b[col0 + j0 + 2];
            float v3 = acc[r][3] + qkv_b[col0 + j0 + 3];
            if (yb == 0) { v0*=sc; v1*=sc; v2*=sc; v3*=sc; }
            wr_pair64(H, L, row, j0,     v0, v1);
            wr_pair64(H, L, row, j0 + 2, v2, v3);
        } else {
            #pragma unroll
            for (int c = 0; c < 4; c++) {
                int col = col0 + j0 + c - 192;
                g_XDW[row*NOUT + col] = acc[r][c] * enres;
            }
        }
    }
}

// ===================== attention: 64-row KV tiles, double-buffered =========
// smem: QH 16K | QL 16K | 2 stages x {KH,KL,VH,VL} 32K each = 96KB, 2 CTAs/SM.
// Prefetch tile t+1 while computing t. Tile visit order rotated per CTA
// (non-causal pure-sum => any order valid) to decorrelate resident CTAs.
#define T_QH 0
#define T_QL 16384
#define T_KV 32768
#define ATTN6_SMEM 98304

__global__ __launch_bounds__(256, 2) void attn6_kernel()
{
    extern __shared__ __align__(16) char smp[];
    const uint32_t sb = smem_u32(smp);
    const int b    = blockIdx.y;
    const int q0   = blockIdx.x * 128;
    const int tid  = threadIdx.x;
    const int w    = tid >> 5;
    const int lane = tid & 31;
    const int toff = ((blockIdx.x + blockIdx.y) & 3) << 3;   // stagger start

    auto issue_kv = [&](int t, int s){
        const uint4* s0 = g_KH4 + (size_t)(b*TT + t*64)*8;
        const uint4* s1 = g_KL4 + (size_t)(b*TT + t*64)*8;
        const uint4* s2 = g_VH4 + (size_t)(b*TT + t*64)*8;
        const uint4* s3 = g_VL4 + (size_t)(b*TT + t*64)*8;
        uint32_t base = sb + T_KV + s*32768;
        #pragma unroll
        for (int i = tid; i < 2048; i += 256) {
            int m = i >> 9, j = i & 511;
            const uint4* src = (m==0) ? s0 : (m==1) ? s1 : (m==2) ? s2 : s3;
            CPA(base + m*8192 + j*16, src + j);
        }
        CPC();
    };

    // ---- Q (group) then KV tile 0 (group) ----
    {
        const uint4* qh4 = g_QH4 + (size_t)(b*TT + q0)*8;
        const uint4* ql4 = g_QL4 + (size_t)(b*TT + q0)*8;
        for (int i = tid; i < 2048; i += 256) {
            int sel = i >> 10, j = i & 1023;
            CPA(sb + (sel ? T_QL : T_QH) + j*16, (sel ? ql4 : qh4) + j);
        }
        CPC();
    }
    issue_kv(toff & 31, 0);
    CPW(1);                 // Q ready
    __syncthreads();

    // ---- Q fragments (persistent) ----
    uint32_t qh[4][4], ql[4][4];
    {
        int rr = 16*w + (lane & 7) + ((lane >> 3) & 1)*8;
        #pragma unroll
        for (int k = 0; k < 4; k++) {
            int ch = 2*k + (lane >> 4);
            LDSM4(qh[k], sb + T_QH + swz(rr, ch));
            LDSM4(ql[k], sb + T_QL + swz(rr, ch));
        }
    }

    float o[8][4];
    #pragma unroll
    for (int n = 0; n < 8; n++) { o[n][0]=o[n][1]=o[n][2]=o[n][3]=0.f; }
    float lacc0 = 0.f, lacc1 = 0.f;

    const int rBk  = (lane & 7) + (lane >> 4)*8;
    const int chBk = (lane >> 3) & 1;
    const int rBv  = (lane & 7) + ((lane >> 3) & 1)*8;
    const int chBv = (lane >> 4);

    for (int t = 0; t < 32; t++) {
        const int s = t & 1;
        if (t < 31) { issue_kv((t + 1 + toff) & 31, s ^ 1); CPW(1); }
        else        { CPW(0); }
        __syncthreads();
        const uint32_t KH = sb + T_KV + s*32768;
        const uint32_t KL = KH + 8192, VH = KH + 16384, VL = KH + 24576;

        #pragma unroll
        for (int n2 = 0; n2 < 4; n2++) {
            // ---- S block (16 s-cols), 3-term ----
            float c0[4] = {0,0,0,0}, c1[4] = {0,0,0,0};
            int s0 = n2*16;
            #pragma unroll
            for (int k = 0; k < 4; k++) {
                uint32_t off = swz(s0 + rBk, 2*k + chBk);
                uint32_t bh[4], bl[4];
                LDSM4(bh, KH + off);
                LDSM4(bl, KL + off);
                mma16816(c0, qh[k], bh[0], bh[1]);
                mma16816(c0, ql[k], bh[0], bh[1]);
                mma16816(c0, qh[k], bl[0], bl[1]);
                mma16816(c1, qh[k], bh[2], bh[3]);
                mma16816(c1, ql[k], bh[2], bh[3]);
                mma16816(c1, qh[k], bl[2], bl[3]);
            }
            // ---- exp + pack (consumed immediately) ----
            float e0 = __expf(c0[0]), e1 = __expf(c0[1]);
            float e2 = __expf(c0[2]), e3 = __expf(c0[3]);
            float e4 = __expf(c1[0]), e5 = __expf(c1[1]);
            float e6 = __expf(c1[2]), e7 = __expf(c1[3]);
            lacc0 += e0 + e1 + e4 + e5;
            lacc1 += e2 + e3 + e6 + e7;
            __nv_bfloat16 h0=__float2bfloat16(e0), h1=__float2bfloat16(e1),
                          h2=__float2bfloat16(e2), h3=__float2bfloat16(e3),
                          h4=__float2bfloat16(e4), h5=__float2bfloat16(e5),
                          h6=__float2bfloat16(e6), h7=__float2bfloat16(e7);
            uint32_t ph[4], pl[4];
            ph[0] = ((uint32_t)__bfloat16_as_ushort(h1)<<16)|__bfloat16_as_ushort(h0);
            ph[1] = ((uint32_t)__bfloat16_as_ushort(h3)<<16)|__bfloat16_as_ushort(h2);
            ph[2] = ((uint32_t)__bfloat16_as_ushort(h5)<<16)|__bfloat16_as_ushort(h4);
            ph[3] = ((uint32_t)__bfloat16_as_ushort(h7)<<16)|__bfloat16_as_ushort(h6);
            pl[0] = packbf(e0-__bfloat162float(h0), e1-__bfloat162float(h1));
            pl[1] = packbf(e2-__bfloat162float(h2), e3-__bfloat162float(h3));
            pl[2] = packbf(e4-__bfloat162float(h4), e5-__bfloat162float(h5));
            pl[3] = packbf(e6-__bfloat162float(h6), e7-__bfloat162float(h7));

            // ---- PV for this s-block, 3-term ----
            #pragma unroll
            for (int dp = 0; dp < 4; dp++) {
                uint32_t off = swz(s0 + rBv, 2*dp + chBv);
                uint32_t bh[4], bl[4];
                LDSM4T(bh, VH + off);
                LDSM4T(bl, VL + off);
                mma16816(o[2*dp],   ph, bh[0], bh[1]);
                mma16816(o[2*dp],   pl, bh[0], bh[1]);
                mma16816(o[2*dp],   ph, bl[0], bl[1]);
                mma16816(o[2*dp+1], ph, bh[2], bh[3]);
                mma16816(o[2*dp+1], pl, bh[2], bh[3]);
                mma16816(o[2*dp+1], ph, bl[2], bl[3]);
            }
        }
        __syncthreads();
    }

    // ---- finalize: normalize, write pre-split ATT ----
    lacc0 += __shfl_xor_sync(0xffffffffu, lacc0, 1);
    lacc0 += __shfl_xor_sync(0xffffffffu, lacc0, 2);
    lacc1 += __shfl_xor_sync(0xffffffffu, lacc1, 1);
    lacc1 += __shfl_xor_sync(0xffffffffu, lacc1, 2);
    float inv0 = 1.f / lacc0, inv1 = 1.f / lacc1;

    uint32_t* AH = (uint32_t*)g_AH4;
    uint32_t* AL = (uint32_t*)g_AL4;
    int r0 = b*TT + q0 + 16*w + (lane >> 2);
    int cl = (lane & 3)*2;
    #pragma unroll
    for (int n = 0; n < 8; n++) {
        wr_pair64(AH, AL, r0,     n*8 + cl, o[n][0]*inv0, o[n][1]*inv0);
        wr_pair64(AH, AL, r0 + 8, n*8 + cl, o[n][2]*inv1, o[n][3]*inv1);
    }
}

// ===================== conv1d: pre-split operands, X loaded once ===========
template<int WB, int NH, bool SPLIT>
__global__ __launch_bounds__(256) void convt_kernel(
    const uint4* __restrict__ inH4, const uint4* __restrict__ inL4,
    const uint32_t* __restrict__ wH, const uint32_t* __restrict__ wL,
    const float* __restrict__ bias,
    const float* __restrict__ resid, float* __restrict__ outF,
    uint32_t* __restrict__ outH, uint32_t* __restrict__ outL)
{
    extern __shared__ __align__(16) char smp[];
    const uint32_t sb = smem_u32(smp);
    const int b = blockIdx.y, t0 = blockIdx.x*128, z = blockIdx.z;
    const int tid = threadIdx.x, wrp = tid >> 5, lane = tid & 31;

    const int XH = 0, XL = 130*WB;
    const int W0 = 2*130*WB, WL0 = W0 + NH*8192;

    const int n4 = 130*(WB/16);
    for (int i = tid; i < 2*n4; i += 256) {
        int sel = (i >= n4); int j = sel ? i - n4 : i;
        int r = j/(WB/16), c = j%(WB/16);
        int t = t0 + r - 1;
        uint4 v = make_uint4(0,0,0,0);
        if (t >= 0 && t < TT) v = (sel ? inL4 : inH4)[(size_t)(b*TT+t)*(WB/16) + c];
        *(uint4*)(smp + (sel ? XL : XH) + r*WB + c*16) = v;
    }

    float o[8][4];
    #pragma unroll
    for (int m = 0; m < 8; m++) { o[m][0]=o[m][1]=o[m][2]=o[m][3]=0.f; }
    const int laneR = (lane & 7) + ((lane >> 3) & 1)*8;
    const int chS   = lane >> 4;

    for (int k = 0; k < 3; k++) {
        __syncthreads();
        for (int i = tid; i < NH*2*512; i += 256) {
            int sel = (i >= NH*512); int j = sel ? i - NH*512 : i;
            int h = j >> 9, c = j & 511;
            const uint32_t* src = (sel ? wL : wH) + (size_t)((k*NH+h)*2 + z)*2048 + c*4;
            *(uint4*)(smp + (sel ? WL0 : W0) + h*8192 + c*16) = *(const uint4*)src;
        }
        __syncthreads();

        #pragma unroll
        for (int h = 0; h < NH; h++) {
            #pragma unroll
            for (int ks = 0; ks < 4; ks++) {
                int ar = 16*wrp + laneR + k;
                uint32_t aoff = (uint32_t)(ar*WB + h*128 + (((2*ks+chS) ^ ((ar+7)&7))<<4));
                uint32_t ah[4], al[4];
                LDSM4(ah, sb + XH + aoff);
                LDSM4(al, sb + XL + aoff);
                #pragma unroll
                for (int g = 0; g < 4; g++) {
                    int br = ks*16 + laneR;
                    uint32_t boff = (uint32_t)(h*8192 + br*128 + (((2*g+chS) ^ (br&7))<<4));
                    uint32_t bh[4], bl[4];
                    LDSM4T(bh, sb + W0  + boff);
                    LDSM4T(bl, sb + WL0 + boff);
                    mma16816(o[2*g],   ah, bh[0], bh[1]);
                    mma16816(o[2*g],   al, bh[0], bh[1]);
                    mma16816(o[2*g],   ah, bl[0], bl[1]);
                    mma16816(o[2*g+1], ah, bh[2], bh[3]);
                    mma16816(o[2*g+1], al, bh[2], bh[3]);
                    mma16816(o[2*g+1], ah, bl[2], bl[3]);
                }
            }
        }
    }

    int r0 = t0 + 16*wrp + (lane >> 2);
    #pragma unroll
    for (int m = 0; m < 8; m++) {
        int col = (m >> 1)*16 + (m & 1)*8 + (lane & 3)*2;
        int co  = z*64 + col;
        float b0 = bias[co], b1 = bias[co + 1];
        float v0 = fmaxf(o[m][0] + b0, 0.f);
        float v1 = fmaxf(o[m][1] + b1, 0.f);
        float v2 = fmaxf(o[m][2] + b0, 0.f);
        float v3 = fmaxf(o[m][3] + b1, 0.f);
        if (SPLIT) {
            #pragma unroll
            for (int rr = 0; rr < 2; rr++) {
                int row = b*TT + r0 + rr*8;
                float a = rr ? v2 : v0, bb = rr ? v3 : v1;
                int ch = co >> 3;
                int chp = (ch & 8) | ((ch ^ (row & 7)) & 7);
                int u = row*64 + (chp << 2) + ((co & 7) >> 1);
                __nv_bfloat16 ha=__float2bfloat16(a), hb=__float2bfloat16(bb);
                outH[u] = ((uint32_t)__bfloat16_as_ushort(hb)<<16)|__bfloat16_as_ushort(ha);
                outL[u] = packbf(a-__bfloat162float(ha), bb-__bfloat162float(hb));
            }
        } else {
            size_t base0 = (size_t)(b*TT + r0)*NOUT + co;
            size_t base1 = (size_t)(b*TT + r0 + 8)*NOUT + co;
            float2 ra = *(const float2*)(resid + base0);
            float2 rb = *(const float2*)(resid + base1);
            float2 s0; s0.x = fmaxf(v0 + ra.x, 0.f); s0.y = fmaxf(v1 + ra.y, 0.f);
            float2 s1; s1.x = fmaxf(v2 + rb.x, 0.f); s1.y = fmaxf(v3 + rb.y, 0.f);
            *(float2*)(outF + base0) = s0;
            *(float2*)(outF + base1) = s1;
        }
    }
}

// ---------------------------------------------------------------------------
extern "C" void kernel_launch(void* const* d_in, const int* in_sizes, int n_in,
                              void* d_out, int out_size)
{
    const float* x       = (const float*)d_in[0];
    const float* qkv_w   = (const float*)d_in[1];
    const float* qkv_b   = (const float*)d_in[2];
    const float* scale   = (const float*)d_in[3];
    const float* conv_w1 = (const float*)d_in[4];
    const float* conv_b1 = (const float*)d_in[5];
    const float* conv_w2 = (const float*)d_in[6];
    const float* conv_b2 = (const float*)d_in[7];
    const float* down_w  = (const float*)d_in[8];
    float* out = (float*)d_out;

    const int SM1 = 2*130*128 + 2*8192;          // 49664
    const int SM2 = 2*130*256 + 2*2*8192;        // 99328

    cudaFuncSetAttribute(proj_kernel,  cudaFuncAttributeMaxDynamicSharedMemorySize, PROJ_SMEM);
    cudaFuncSetAttribute(attn6_kernel, cudaFuncAttributeMaxDynamicSharedMemorySize, ATTN6_SMEM);
    cudaFuncSetAttribute((const void*)convt_kernel<128,1,true>,
                         cudaFuncAttributeMaxDynamicSharedMemorySize, SM1);
    cudaFuncSetAttribute((const void*)convt_kernel<256,2,false>,
                         cudaFuncAttributeMaxDynamicSharedMemorySize, SM2);

    uint4 *aH, *aL, *hH, *hL, *w1H, *w1L, *w2H, *w2L;
    float *xdw;
    cudaGetSymbolAddress((void**)&aH,  g_AH4);
    cudaGetSymbolAddress((void**)&aL,  g_AL4);
    cudaGetSymbolAddress((void**)&hH,  g_HH4);
    cudaGetSymbolAddress((void**)&hL,  g_HL4);
    cudaGetSymbolAddress((void**)&w1H, g_W1H4);
    cudaGetSymbolAddress((void**)&w1L, g_W1L4);
    cudaGetSymbolAddress((void**)&w2H, g_W2H4);
    cudaGetSymbolAddress((void**)&w2L, g_W2L4);
    cudaGetSymbolAddress((void**)&xdw, g_XDW);

    prep_w_kernel<<<48, 256>>>(conv_w1, 64,  (uint32_t*)w1H, (uint32_t*)w1L);
    prep_w_kernel<<<96, 256>>>(conv_w2, 128, (uint32_t*)w2H, (uint32_t*)w2L);
    proj_kernel <<<dim3(BT/128, 5), 256, PROJ_SMEM>>>(x, qkv_w, qkv_b, scale, down_w);
    attn6_kernel<<<dim3(TT/128, BB), 256, ATTN6_SMEM>>>();
    convt_kernel<128,1,true ><<<dim3(TT/128, BB, 2), 256, SM1>>>(
        aH, aL, (uint32_t*)w1H, (uint32_t*)w1L, conv_b1, nullptr, nullptr,
        (uint32_t*)hH, (uint32_t*)hL);
    convt_kernel<256,2,false><<<dim3(TT/128, BB, 2), 256, SM2>>>(
        hH, hL, (uint32_t*)w2H, (uint32_t*)w2L, conv_b2, xdw, out,
        nullptr, nullptr);
}

// round 11
// speedup vs baseline: 1.1573x; 1.0248x over previous
#include <cuda_runtime.h>
#include <cuda_bf16.h>
#include <cstdint>

#define BB   16
#define TT   2048
#define NIN  96
#define NOUT 128
#define DD   64
#define BT   (BB*TT)

// ---- global scratch (pre-split bf16 hi/lo, swizzled 128B/256B rows) ----
__device__ uint4 g_QH4[BT*8]; __device__ uint4 g_QL4[BT*8];
__device__ uint4 g_KH4[BT*8]; __device__ uint4 g_KL4[BT*8];
__device__ uint4 g_VH4[BT*8]; __device__ uint4 g_VL4[BT*8];
__device__ uint4 g_AH4[BT*8]; __device__ uint4 g_AL4[BT*8];   // attn out
__device__ uint4 g_HH4[BT*16]; __device__ uint4 g_HL4[BT*16]; // conv1 out (256B rows)
__device__ float g_XDW[BT*NOUT];
__device__ uint4 g_W1H4[3*2*512];   __device__ uint4 g_W1L4[3*2*512];
__device__ uint4 g_W2H4[3*2*2*512]; __device__ uint4 g_W2L4[3*2*2*512];

// ===================== helpers =====================
__device__ __forceinline__ uint32_t smem_u32(const void* p){
    uint32_t a;
    asm("{ .reg .u64 t; cvta.to.shared.u64 t, %1; cvt.u32.u64 %0, t; }" : "=r"(a) : "l"(p));
    return a;
}
#define LDSM4(R, A) \
    asm volatile("ldmatrix.sync.aligned.m8n8.x4.shared.b16 {%0,%1,%2,%3}, [%4];" \
        : "=r"((R)[0]),"=r"((R)[1]),"=r"((R)[2]),"=r"((R)[3]) : "r"(A))
#define LDSM4T(R, A) \
    asm volatile("ldmatrix.sync.aligned.m8n8.x4.trans.shared.b16 {%0,%1,%2,%3}, [%4];" \
        : "=r"((R)[0]),"=r"((R)[1]),"=r"((R)[2]),"=r"((R)[3]) : "r"(A))
#define CPA(dst, src) \
    asm volatile("cp.async.cg.shared.global [%0], [%1], 16;" :: "r"(dst), "l"(src))
#define CPC() asm volatile("cp.async.commit_group;")
#define CPW(n) asm volatile("cp.async.wait_group %0;" :: "n"(n))

__device__ __forceinline__ void mma16816(float* c, const uint32_t* a, uint32_t b0, uint32_t b1){
    asm volatile(
        "mma.sync.aligned.m16n8k16.row.col.f32.bf16.bf16.f32 "
        "{%0,%1,%2,%3},{%4,%5,%6,%7},{%8,%9},{%0,%1,%2,%3};"
        : "+f"(c[0]),"+f"(c[1]),"+f"(c[2]),"+f"(c[3])
        : "r"(a[0]),"r"(a[1]),"r"(a[2]),"r"(a[3]),"r"(b0),"r"(b1));
}
__device__ __forceinline__ uint32_t packbf(float lo, float hi){
    uint16_t l = __bfloat16_as_ushort(__float2bfloat16(lo));
    uint16_t h = __bfloat16_as_ushort(__float2bfloat16(hi));
    return ((uint32_t)h << 16) | (uint32_t)l;
}
// pack pair with one cvt: result.hi = bf16(hi), result.lo = bf16(lo), RN
__device__ __forceinline__ uint32_t cvt2(float hi, float lo){
    uint32_t r;
    asm("cvt.rn.bf16x2.f32 %0, %1, %2;" : "=r"(r) : "f"(hi), "f"(lo));
    return r;
}
__device__ __forceinline__ uint32_t swz(int r, int ch){
    return (uint32_t)(r*128 + ((ch ^ (r & 7)) << 4));
}
// write a hi/lo split pair (cols cl, cl+1, cl even) into 128B-row global arrays
__device__ __forceinline__ void wr_pair64(uint32_t* H, uint32_t* L, int row, int cl,
                                          float a, float bvv){
    int byte = cl*2;
    int u = row*32 + (((byte>>4) ^ (row&7))<<2) + ((byte&15)>>2);
    __nv_bfloat16 ha=__float2bfloat16(a), hb=__float2bfloat16(bvv);
    H[u] = ((uint32_t)__bfloat16_as_ushort(hb)<<16)|__bfloat16_as_ushort(ha);
    L[u] = packbf(a-__bfloat162float(ha), bvv-__bfloat162float(hb));
}

// ===================== weight prep: split + swizzle into tile images ========
__global__ void prep_w_kernel(const float* __restrict__ w, int Cin,
                              uint32_t* __restrict__ wH, uint32_t* __restrict__ wL)
{
    int nh = Cin >> 6;
    int total = 3*Cin*64;   // co-pairs
    for (int idx = blockIdx.x*blockDim.x + threadIdx.x; idx < total;
         idx += gridDim.x*blockDim.x) {
        int k = idx/(Cin*64); int rem = idx - k*Cin*64;
        int ci = rem >> 6, cop = rem & 63;
        float2 v = *(const float2*)(w + (size_t)(k*Cin+ci)*NOUT + cop*2);
        int hci = ci>>6, cil = ci&63, hco = cop>>5, copl = cop&31;
        int tidx = (k*nh + hci)*2 + hco;
        int u = tidx*2048 + cil*32 + (((copl>>2) ^ (cil&7))<<2) + (copl&3);
        __nv_bfloat16 hx=__float2bfloat16(v.x), hy=__float2bfloat16(v.y);
        wH[u] = ((uint32_t)__bfloat16_as_ushort(hy)<<16)|__bfloat16_as_ushort(hx);
        wL[u] = packbf(v.x-__bfloat162float(hx), v.y-__bfloat162float(hy));
    }
}

// ===================== proj: GEMM + split/swizzle epilogue =================
#define PROJ_XS_F   (128*97)
#define PROJ_SMEM   ((PROJ_XS_F + 96*64)*4)
__global__ __launch_bounds__(256) void proj_kernel(
    const float* __restrict__ x, const float* __restrict__ qkv_w,
    const float* __restrict__ qkv_b, const float* __restrict__ scale,
    const float* __restrict__ down_w)
{
    extern __shared__ float sm[];
    float* Xs = sm;
    float* Ws = sm + PROJ_XS_F;
    const int row0 = blockIdx.x * 128;
    const int col0 = blockIdx.y * 64;
    const int tid  = threadIdx.x;

    for (int idx = tid; idx < 128*96; idx += 256) {
        int i = idx / 96, k = idx - i*96;
        Xs[i*97 + k] = x[(row0 + i)*NIN + k];
    }
    for (int idx = tid; idx < 96*64; idx += 256) {
        int k = idx >> 6, j = idx & 63;
        int col = col0 + j;
        Ws[idx] = (col < 192) ? qkv_w[k*192 + col] : down_w[k*128 + (col - 192)];
    }
    __syncthreads();

    const int tr = tid >> 4, tc = tid & 15;
    const int i0 = tr*8, j0 = tc*4;
    float acc[8][4];
    #pragma unroll
    for (int r = 0; r < 8; r++) { acc[r][0]=acc[r][1]=acc[r][2]=acc[r][3]=0.f; }

    #pragma unroll 4
    for (int k = 0; k < 96; k++) {
        float4 bv = *reinterpret_cast<const float4*>(&Ws[k*64 + j0]);
        #pragma unroll
        for (int r = 0; r < 8; r++) {
            float a = Xs[(i0 + r)*97 + k];
            acc[r][0] += a*bv.x; acc[r][1] += a*bv.y;
            acc[r][2] += a*bv.z; acc[r][3] += a*bv.w;
        }
    }

    const float sc    = scale[0];
    const float enres = 1.0f + 1.0f/(float)TT;
    const int yb = blockIdx.y;
    uint32_t *H = nullptr, *L = nullptr;
    if      (yb == 0) { H = (uint32_t*)g_QH4; L = (uint32_t*)g_QL4; }
    else if (yb == 1) { H = (uint32_t*)g_KH4; L = (uint32_t*)g_KL4; }
    else if (yb == 2) { H = (uint32_t*)g_VH4; L = (uint32_t*)g_VL4; }

    #pragma unroll
    for (int r = 0; r < 8; r++) {
        int row = row0 + i0 + r;
        if (yb < 3) {
            float v0 = acc[r][0] + qkv_b[col0 + j0 + 0];
            float v1 = acc[r][1] + qkv_b[col0 + j0 + 1];
            float v2 = acc[r][2] + qkv_b[col0 + j0 + 2];
            float v3 = acc[r][3] + qkv_b[col0 + j0 + 3];
            if (yb == 0) { v0*=sc; v1*=sc; v2*=sc; v3*=sc; }
            wr_pair64(H, L, row, j0,     v0, v1);
            wr_pair64(H, L, row, j0 + 2, v2, v3);
        } else {
            #pragma unroll
            for (int c = 0; c < 4; c++) {
                int col = col0 + j0 + c - 192;
                g_XDW[row*NOUT + col] = acc[r][c] * enres;
            }
        }
    }
}

// ===================== attention: 32-row KV tiles, 3-stage pipeline ========
// smem: QH 16K | QL 16K | 3 stages x {KH,KL,VH,VL} 16K each = 80KB, 2 CTAs/SM.
// Loop: CPW(1) [tile t issued 2 iters ago -> free]; sync; issue t+2; compute.
// One barrier per tile. Tile order rotated per CTA (pure-sum, order-free).
#define T_QH 0
#define T_QL 16384
#define T_KV 32768
#define ATTN7_SMEM 81920

__global__ __launch_bounds__(256, 2) void attn7_kernel()
{
    extern __shared__ __align__(16) char smp[];
    const uint32_t sb = smem_u32(smp);
    const int b    = blockIdx.y;
    const int q0   = blockIdx.x * 128;
    const int tid  = threadIdx.x;
    const int w    = tid >> 5;
    const int lane = tid & 31;
    const int toff = ((blockIdx.x + blockIdx.y) & 7) << 3;   // stagger start (tiles of 32)

    auto issue_kv = [&](int t, int s){
        const uint4* s0 = g_KH4 + (size_t)(b*TT + t*32)*8;
        const uint4* s1 = g_KL4 + (size_t)(b*TT + t*32)*8;
        const uint4* s2 = g_VH4 + (size_t)(b*TT + t*32)*8;
        const uint4* s3 = g_VL4 + (size_t)(b*TT + t*32)*8;
        uint32_t base = sb + T_KV + s*16384;
        #pragma unroll
        for (int i = tid; i < 1024; i += 256) {
            int m = i >> 8, j = i & 255;
            const uint4* src = (m==0) ? s0 : (m==1) ? s1 : (m==2) ? s2 : s3;
            CPA(base + m*4096 + j*16, src + j);
        }
        CPC();
    };

    // ---- prologue: Q (group) + KV tiles 0,1 ----
    {
        const uint4* qh4 = g_QH4 + (size_t)(b*TT + q0)*8;
        const uint4* ql4 = g_QL4 + (size_t)(b*TT + q0)*8;
        for (int i = tid; i < 2048; i += 256) {
            int sel = i >> 10, j = i & 1023;
            CPA(sb + (sel ? T_QL : T_QH) + j*16, (sel ? ql4 : qh4) + j);
        }
        CPC();
    }
    issue_kv(toff, 0);
    issue_kv((toff + 1) & 63, 1);
    CPW(2);                 // Q ready; kv0/kv1 in flight
    __syncthreads();

    // ---- Q fragments (persistent) ----
    uint32_t qh[4][4], ql[4][4];
    {
        int rr = 16*w + (lane & 7) + ((lane >> 3) & 1)*8;
        #pragma unroll
        for (int k = 0; k < 4; k++) {
            int ch = 2*k + (lane >> 4);
            LDSM4(qh[k], sb + T_QH + swz(rr, ch));
            LDSM4(ql[k], sb + T_QL + swz(rr, ch));
        }
    }

    float o[8][4];
    #pragma unroll
    for (int n = 0; n < 8; n++) { o[n][0]=o[n][1]=o[n][2]=o[n][3]=0.f; }
    float lacc0 = 0.f, lacc1 = 0.f;

    const int rBk  = (lane & 7) + (lane >> 4)*8;
    const int chBk = (lane >> 3) & 1;
    const int rBv  = (lane & 7) + ((lane >> 3) & 1)*8;
    const int chBv = (lane >> 4);

    int stage = 0;
    for (int t = 0; t < 64; t++) {
        if (t < 63) CPW(1); else CPW(0);   // tile t arrived (issued 2 iters ago)
        __syncthreads();                   // visibility + all warps past t-1
        if (t + 2 < 64) {
            int s2 = stage + 2; if (s2 >= 3) s2 -= 3;
            issue_kv((t + 2 + toff) & 63, s2);   // stage consumed at t-1: safe
        }
        const uint32_t KH = sb + T_KV + stage*16384;
        const uint32_t KL = KH + 4096, VH = KH + 8192, VL = KH + 12288;

        #pragma unroll
        for (int n2 = 0; n2 < 2; n2++) {
            // ---- S block (16 s-cols), 3-term ----
            float c0[4] = {0,0,0,0}, c1[4] = {0,0,0,0};
            int s0 = n2*16;
            #pragma unroll
            for (int k = 0; k < 4; k++) {
                uint32_t off = swz(s0 + rBk, 2*k + chBk);
                uint32_t bh[4], bl[4];
                LDSM4(bh, KH + off);
                LDSM4(bl, KL + off);
                mma16816(c0, qh[k], bh[0], bh[1]);
                mma16816(c0, ql[k], bh[0], bh[1]);
                mma16816(c0, qh[k], bl[0], bl[1]);
                mma16816(c1, qh[k], bh[2], bh[3]);
                mma16816(c1, ql[k], bh[2], bh[3]);
                mma16816(c1, qh[k], bl[2], bl[3]);
            }
            // ---- exp + pack (bf16x2 cvt; consumed immediately) ----
            float e0 = __expf(c0[0]), e1 = __expf(c0[1]);
            float e2 = __expf(c0[2]), e3 = __expf(c0[3]);
            float e4 = __expf(c1[0]), e5 = __expf(c1[1]);
            float e6 = __expf(c1[2]), e7 = __expf(c1[3]);
            lacc0 += e0 + e1 + e4 + e5;
            lacc1 += e2 + e3 + e6 + e7;
            uint32_t ph[4], pl[4];
            ph[0] = cvt2(e1, e0);
            ph[1] = cvt2(e3, e2);
            ph[2] = cvt2(e5, e4);
            ph[3] = cvt2(e7, e6);
            pl[0] = cvt2(e1 - __uint_as_float(ph[0] & 0xFFFF0000u),
                         e0 - __uint_as_float(ph[0] << 16));
            pl[1] = cvt2(e3 - __uint_as_float(ph[1] & 0xFFFF0000u),
                         e2 - __uint_as_float(ph[1] << 16));
            pl[2] = cvt2(e5 - __uint_as_float(ph[2] & 0xFFFF0000u),
                         e4 - __uint_as_float(ph[2] << 16));
            pl[3] = cvt2(e7 - __uint_as_float(ph[3] & 0xFFFF0000u),
                         e6 - __uint_as_float(ph[3] << 16));

            // ---- PV for this s-block, 3-term ----
            #pragma unroll
            for (int dp = 0; dp < 4; dp++) {
                uint32_t off = swz(s0 + rBv, 2*dp + chBv);
                uint32_t bh[4], bl[4];
                LDSM4T(bh, VH + off);
                LDSM4T(bl, VL + off);
                mma16816(o[2*dp],   ph, bh[0], bh[1]);
                mma16816(o[2*dp],   pl, bh[0], bh[1]);
                mma16816(o[2*dp],   ph, bl[0], bl[1]);
                mma16816(o[2*dp+1], ph, bh[2], bh[3]);
                mma16816(o[2*dp+1], pl, bh[2], bh[3]);
                mma16816(o[2*dp+1], ph, bl[2], bl[3]);
            }
        }
        if (++stage == 3) stage = 0;
    }

    // ---- finalize: normalize, write pre-split ATT ----
    lacc0 += __shfl_xor_sync(0xffffffffu, lacc0, 1);
    lacc0 += __shfl_xor_sync(0xffffffffu, lacc0, 2);
    lacc1 += __shfl_xor_sync(0xffffffffu, lacc1, 1);
    lacc1 += __shfl_xor_sync(0xffffffffu, lacc1, 2);
    float inv0 = 1.f / lacc0, inv1 = 1.f / lacc1;

    uint32_t* AH = (uint32_t*)g_AH4;
    uint32_t* AL = (uint32_t*)g_AL4;
    int r0 = b*TT + q0 + 16*w + (lane >> 2);
    int cl = (lane & 3)*2;
    #pragma unroll
    for (int n = 0; n < 8; n++) {
        wr_pair64(AH, AL, r0,     n*8 + cl, o[n][0]*inv0, o[n][1]*inv0);
        wr_pair64(AH, AL, r0 + 8, n*8 + cl, o[n][2]*inv1, o[n][3]*inv1);
    }
}

// ===================== conv1d: pre-split operands, X loaded once ===========
template<int WB, int NH, bool SPLIT>
__global__ __launch_bounds__(256) void convt_kernel(
    const uint4* __restrict__ inH4, const uint4* __restrict__ inL4,
    const uint32_t* __restrict__ wH, const uint32_t* __restrict__ wL,
    const float* __restrict__ bias,
    const float* __restrict__ resid, float* __restrict__ outF,
    uint32_t* __restrict__ outH, uint32_t* __restrict__ outL)
{
    extern __shared__ __align__(16) char smp[];
    const uint32_t sb = smem_u32(smp);
    const int b = blockIdx.y, t0 = blockIdx.x*128, z = blockIdx.z;
    const int tid = threadIdx.x, wrp = tid >> 5, lane = tid & 31;

    const int XH = 0, XL = 130*WB;
    const int W0 = 2*130*WB, WL0 = W0 + NH*8192;

    const int n4 = 130*(WB/16);
    for (int i = tid; i < 2*n4; i += 256) {
        int sel = (i >= n4); int j = sel ? i - n4 : i;
        int r = j/(WB/16), c = j%(WB/16);
        int t = t0 + r - 1;
        uint4 v = make_uint4(0,0,0,0);
        if (t >= 0 && t < TT) v = (sel ? inL4 : inH4)[(size_t)(b*TT+t)*(WB/16) + c];
        *(uint4*)(smp + (sel ? XL : XH) + r*WB + c*16) = v;
    }

    float o[8][4];
    #pragma unroll
    for (int m = 0; m < 8; m++) { o[m][0]=o[m][1]=o[m][2]=o[m][3]=0.f; }
    const int laneR = (lane & 7) + ((lane >> 3) & 1)*8;
    const int chS   = lane >> 4;

    for (int k = 0; k < 3; k++) {
        __syncthreads();
        for (int i = tid; i < NH*2*512; i += 256) {
            int sel = (i >= NH*512); int j = sel ? i - NH*512 : i;
            int h = j >> 9, c = j & 511;
            const uint32_t* src = (sel ? wL : wH) + (size_t)((k*NH+h)*2 + z)*2048 + c*4;
            *(uint4*)(smp + (sel ? WL0 : W0) + h*8192 + c*16) = *(const uint4*)src;
        }
        __syncthreads();

        #pragma unroll
        for (int h = 0; h < NH; h++) {
            #pragma unroll
            for (int ks = 0; ks < 4; ks++) {
                int ar = 16*wrp + laneR + k;
                uint32_t aoff = (uint32_t)(ar*WB + h*128 + (((2*ks+chS) ^ ((ar+7)&7))<<4));
                uint32_t ah[4], al[4];
                LDSM4(ah, sb + XH + aoff);
                LDSM4(al, sb + XL + aoff);
                #pragma unroll
                for (int g = 0; g < 4; g++) {
                    int br = ks*16 + laneR;
                    uint32_t boff = (uint32_t)(h*8192 + br*128 + (((2*g+chS) ^ (br&7))<<4));
                    uint32_t bh[4], bl[4];
                    LDSM4T(bh, sb + W0  + boff);
                    LDSM4T(bl, sb + WL0 + boff);
                    mma16816(o[2*g],   ah, bh[0], bh[1]);
                    mma16816(o[2*g],   al, bh[0], bh[1]);
                    mma16816(o[2*g],   ah, bl[0], bl[1]);
                    mma16816(o[2*g+1], ah, bh[2], bh[3]);
                    mma16816(o[2*g+1], al, bh[2], bh[3]);
                    mma16816(o[2*g+1], ah, bl[2], bl[3]);
                }
            }
        }
    }

    int r0 = t0 + 16*wrp + (lane >> 2);
    #pragma unroll
    for (int m = 0; m < 8; m++) {
        int col = (m >> 1)*16 + (m & 1)*8 + (lane & 3)*2;
        int co  = z*64 + col;
        float b0 = bias[co], b1 = bias[co + 1];
        float v0 = fmaxf(o[m][0] + b0, 0.f);
        float v1 = fmaxf(o[m][1] + b1, 0.f);
        float v2 = fmaxf(o[m][2] + b0, 0.f);
        float v3 = fmaxf(o[m][3] + b1, 0.f);
        if (SPLIT) {
            #pragma unroll
            for (int rr = 0; rr < 2; rr++) {
                int row = b*TT + r0 + rr*8;
                float a = rr ? v2 : v0, bb = rr ? v3 : v1;
                int ch = co >> 3;
                int chp = (ch & 8) | ((ch ^ (row & 7)) & 7);
                int u = row*64 + (chp << 2) + ((co & 7) >> 1);
                __nv_bfloat16 ha=__float2bfloat16(a), hb=__float2bfloat16(bb);
                outH[u] = ((uint32_t)__bfloat16_as_ushort(hb)<<16)|__bfloat16_as_ushort(ha);
                outL[u] = packbf(a-__bfloat162float(ha), bb-__bfloat162float(hb));
            }
        } else {
            size_t base0 = (size_t)(b*TT + r0)*NOUT + co;
            size_t base1 = (size_t)(b*TT + r0 + 8)*NOUT + co;
            float2 ra = *(const float2*)(resid + base0);
            float2 rb = *(const float2*)(resid + base1);
            float2 s0; s0.x = fmaxf(v0 + ra.x, 0.f); s0.y = fmaxf(v1 + ra.y, 0.f);
            float2 s1; s1.x = fmaxf(v2 + rb.x, 0.f); s1.y = fmaxf(v3 + rb.y, 0.f);
            *(float2*)(outF + base0) = s0;
            *(float2*)(outF + base1) = s1;
        }
    }
}

// ---------------------------------------------------------------------------
extern "C" void kernel_launch(void* const* d_in, const int* in_sizes, int n_in,
                              void* d_out, int out_size)
{
    const float* x       = (const float*)d_in[0];
    const float* qkv_w   = (const float*)d_in[1];
    const float* qkv_b   = (const float*)d_in[2];
    const float* scale   = (const float*)d_in[3];
    const float* conv_w1 = (const float*)d_in[4];
    const float* conv_b1 = (const float*)d_in[5];
    const float* conv_w2 = (const float*)d_in[6];
    const float* conv_b2 = (const float*)d_in[7];
    const float* down_w  = (const float*)d_in[8];
    float* out = (float*)d_out;

    const int SM1 = 2*130*128 + 2*8192;          // 49664
    const int SM2 = 2*130*256 + 2*2*8192;        // 99328

    cudaFuncSetAttribute(proj_kernel,  cudaFuncAttributeMaxDynamicSharedMemorySize, PROJ_SMEM);
    cudaFuncSetAttribute(attn7_kernel, cudaFuncAttributeMaxDynamicSharedMemorySize, ATTN7_SMEM);
    cudaFuncSetAttribute((const void*)convt_kernel<128,1,true>,
                         cudaFuncAttributeMaxDynamicSharedMemorySize, SM1);
    cudaFuncSetAttribute((const void*)convt_kernel<256,2,false>,
                         cudaFuncAttributeMaxDynamicSharedMemorySize, SM2);

    uint4 *aH, *aL, *hH, *hL, *w1H, *w1L, *w2H, *w2L;
    float *xdw;
    cudaGetSymbolAddress((void**)&aH,  g_AH4);
    cudaGetSymbolAddress((void**)&aL,  g_AL4);
    cudaGetSymbolAddress((void**)&hH,  g_HH4);
    cudaGetSymbolAddress((void**)&hL,  g_HL4);
    cudaGetSymbolAddress((void**)&w1H, g_W1H4);
    cudaGetSymbolAddress((void**)&w1L, g_W1L4);
    cudaGetSymbolAddress((void**)&w2H, g_W2H4);
    cudaGetSymbolAddress((void**)&w2L, g_W2L4);
    cudaGetSymbolAddress((void**)&xdw, g_XDW);

    prep_w_kernel<<<48, 256>>>(conv_w1, 64,  (uint32_t*)w1H, (uint32_t*)w1L);
    prep_w_kernel<<<96, 256>>>(conv_w2, 128, (uint32_t*)w2H, (uint32_t*)w2L);
    proj_kernel <<<dim3(BT/128, 5), 256, PROJ_SMEM>>>(x, qkv_w, qkv_b, scale, down_w);
    attn7_kernel<<<dim3(TT/128, BB), 256, ATTN7_SMEM>>>();
    convt_kernel<128,1,true ><<<dim3(TT/128, BB, 2), 256, SM1>>>(
        aH, aL, (uint32_t*)w1H, (uint32_t*)w1L, conv_b1, nullptr, nullptr,
        (uint32_t*)hH, (uint32_t*)hL);
    convt_kernel<256,2,false><<<dim3(TT/128, BB, 2), 256, SM2>>>(
        hH, hL, (uint32_t*)w2H, (uint32_t*)w2L, conv_b2, xdw, out,
        nullptr, nullptr);
}

// round 12
// speedup vs baseline: 1.2527x; 1.0825x over previous
#include <cuda_runtime.h>
#include <cuda_bf16.h>
#include <cstdint>

#define BB   16
#define TT   2048
#define NIN  96
#define NOUT 128
#define DD   64
#define BT   (BB*TT)

// ---- global scratch (pre-split bf16 hi/lo, swizzled 128B/256B rows) ----
__device__ uint4 g_QH4[BT*8]; __device__ uint4 g_QL4[BT*8];
__device__ uint4 g_KH4[BT*8]; __device__ uint4 g_KL4[BT*8];
__device__ uint4 g_VH4[BT*8]; __device__ uint4 g_VL4[BT*8];
__device__ uint4 g_AH4[BT*8]; __device__ uint4 g_AL4[BT*8];   // attn out
__device__ uint4 g_HH4[BT*16]; __device__ uint4 g_HL4[BT*16]; // conv1 out (256B rows)
__device__ float g_XDW[BT*NOUT];
__device__ uint4 g_W1H4[3*2*512];   __device__ uint4 g_W1L4[3*2*512];
__device__ uint4 g_W2H4[3*2*2*512]; __device__ uint4 g_W2L4[3*2*2*512];
__device__ uint4 g_PWH4[5*768];     __device__ uint4 g_PWL4[5*768];   // proj weights

// ===================== helpers =====================
__device__ __forceinline__ uint32_t smem_u32(const void* p){
    uint32_t a;
    asm("{ .reg .u64 t; cvta.to.shared.u64 t, %1; cvt.u32.u64 %0, t; }" : "=r"(a) : "l"(p));
    return a;
}
#define LDSM4(R, A) \
    asm volatile("ldmatrix.sync.aligned.m8n8.x4.shared.b16 {%0,%1,%2,%3}, [%4];" \
        : "=r"((R)[0]),"=r"((R)[1]),"=r"((R)[2]),"=r"((R)[3]) : "r"(A))
#define LDSM4T(R, A) \
    asm volatile("ldmatrix.sync.aligned.m8n8.x4.trans.shared.b16 {%0,%1,%2,%3}, [%4];" \
        : "=r"((R)[0]),"=r"((R)[1]),"=r"((R)[2]),"=r"((R)[3]) : "r"(A))
#define CPA(dst, src) \
    asm volatile("cp.async.cg.shared.global [%0], [%1], 16;" :: "r"(dst), "l"(src))
#define CPC() asm volatile("cp.async.commit_group;")
#define CPW(n) asm volatile("cp.async.wait_group %0;" :: "n"(n))

__device__ __forceinline__ void mma16816(float* c, const uint32_t* a, uint32_t b0, uint32_t b1){
    asm volatile(
        "mma.sync.aligned.m16n8k16.row.col.f32.bf16.bf16.f32 "
        "{%0,%1,%2,%3},{%4,%5,%6,%7},{%8,%9},{%0,%1,%2,%3};"
        : "+f"(c[0]),"+f"(c[1]),"+f"(c[2]),"+f"(c[3])
        : "r"(a[0]),"r"(a[1]),"r"(a[2]),"r"(a[3]),"r"(b0),"r"(b1));
}
__device__ __forceinline__ uint32_t packbf(float lo, float hi){
    uint16_t l = __bfloat16_as_ushort(__float2bfloat16(lo));
    uint16_t h = __bfloat16_as_ushort(__float2bfloat16(hi));
    return ((uint32_t)h << 16) | (uint32_t)l;
}
__device__ __forceinline__ uint32_t cvt2(float hi, float lo){
    uint32_t r;
    asm("cvt.rn.bf16x2.f32 %0, %1, %2;" : "=r"(r) : "f"(hi), "f"(lo));
    return r;
}
__device__ __forceinline__ uint32_t swz(int r, int ch){
    return (uint32_t)(r*128 + ((ch ^ (r & 7)) << 4));
}
// write a hi/lo split pair (cols cl, cl+1, cl even) into 128B-row global arrays
__device__ __forceinline__ void wr_pair64(uint32_t* H, uint32_t* L, int row, int cl,
                                          float a, float bvv){
    int byte = cl*2;
    int u = row*32 + (((byte>>4) ^ (row&7))<<2) + ((byte&15)>>2);
    __nv_bfloat16 ha=__float2bfloat16(a), hb=__float2bfloat16(bvv);
    H[u] = ((uint32_t)__bfloat16_as_ushort(hb)<<16)|__bfloat16_as_ushort(ha);
    L[u] = packbf(a-__bfloat162float(ha), bvv-__bfloat162float(hb));
}

// ===================== conv weight prep =====================
__global__ void prep_w_kernel(const float* __restrict__ w, int Cin,
                              uint32_t* __restrict__ wH, uint32_t* __restrict__ wL)
{
    int nh = Cin >> 6;
    int total = 3*Cin*64;   // co-pairs
    for (int idx = blockIdx.x*blockDim.x + threadIdx.x; idx < total;
         idx += gridDim.x*blockDim.x) {
        int k = idx/(Cin*64); int rem = idx - k*Cin*64;
        int ci = rem >> 6, cop = rem & 63;
        float2 v = *(const float2*)(w + (size_t)(k*Cin+ci)*NOUT + cop*2);
        int hci = ci>>6, cil = ci&63, hco = cop>>5, copl = cop&31;
        int tidx = (k*nh + hci)*2 + hco;
        int u = tidx*2048 + cil*32 + (((copl>>2) ^ (cil&7))<<2) + (copl&3);
        __nv_bfloat16 hx=__float2bfloat16(v.x), hy=__float2bfloat16(v.y);
        wH[u] = ((uint32_t)__bfloat16_as_ushort(hy)<<16)|__bfloat16_as_ushort(hx);
        wL[u] = packbf(v.x-__bfloat162float(hx), v.y-__bfloat162float(hy));
    }
}

// ===================== proj weight prep: [96, 192|128] -> 5 z-tiles ========
// tile z: [96 ci][64 co] bf16 hi/lo, 128B rows, swizzled. 3072 u32 per z.
__global__ void prep_pw_kernel(const float* __restrict__ qkv_w,
                               const float* __restrict__ down_w,
                               uint32_t* __restrict__ pH, uint32_t* __restrict__ pL)
{
    int total = 96*160;   // (ci, co-pair)
    for (int idx = blockIdx.x*blockDim.x + threadIdx.x; idx < total;
         idx += gridDim.x*blockDim.x) {
        int ci = idx/160, cop = idx - ci*160;
        int z = cop >> 5, copl = cop & 31;
        int col = cop*2;
        float2 v = (z < 3) ? *(const float2*)(qkv_w + ci*192 + col)
                           : *(const float2*)(down_w + ci*128 + (col - 192));
        int u = z*3072 + ci*32 + (((copl>>2) ^ (ci&7))<<2) + (copl&3);
        __nv_bfloat16 hx=__float2bfloat16(v.x), hy=__float2bfloat16(v.y);
        pH[u] = ((uint32_t)__bfloat16_as_ushort(hy)<<16)|__bfloat16_as_ushort(hx);
        pL[u] = packbf(v.x-__bfloat162float(hx), v.y-__bfloat162float(hy));
    }
}

// ===================== proj as 3-term bf16 mma GEMM ========================
// CTA = 128 rows x 64 cols (z-block). K=96. X split in-kernel into 256B-row
// swizzled smem (half-swizzle convention, chunks 0..11 used).
#define PM_XH 0
#define PM_XL 32768
#define PM_WH 65536
#define PM_WL 77824
#define PROJM_SMEM 90112
__global__ __launch_bounds__(256) void projm_kernel(
    const float* __restrict__ x, const float* __restrict__ qkv_b,
    const float* __restrict__ scale)
{
    extern __shared__ __align__(16) char smp[];
    const uint32_t sb = smem_u32(smp);
    const int row0 = blockIdx.x * 128;
    const int z    = blockIdx.y;
    const int tid  = threadIdx.x, wrp = tid >> 5, lane = tid & 31;

    // ---- X tile [128][96] -> hi/lo bf16, 256B rows, half-swizzled ----
    for (int i = tid; i < 128*48; i += 256) {
        int r = i/48, p = i - r*48;           // p = col-pair 0..47
        float2 v = *(const float2*)(x + (size_t)(row0 + r)*NIN + p*2);
        int c = p >> 2;                       // 16B chunk 0..11
        int pos = (c & 8) | ((c ^ (r & 7)) & 7);
        uint32_t off = (uint32_t)(r*256 + pos*16 + (p & 3)*4);
        uint32_t h = cvt2(v.y, v.x);
        *(uint32_t*)(smp + PM_XH + off) = h;
        *(uint32_t*)(smp + PM_XL + off) = cvt2(v.y - __uint_as_float(h & 0xFFFF0000u),
                                               v.x - __uint_as_float(h << 16));
    }
    // ---- W tile for this z: 768 uint4 per split ----
    {
        const uint4* srcH = g_PWH4 + z*192;   // 3072 u32 = 192 uint4... (see below)
        const uint4* srcL = g_PWL4 + z*192;
        // 3072 u32 per z = 768 uint4; pointer math in uint4 units:
        srcH = (const uint4*)((const uint32_t*)g_PWH4 + z*3072);
        srcL = (const uint4*)((const uint32_t*)g_PWL4 + z*3072);
        for (int i = tid; i < 2*768; i += 256) {
            int sel = (i >= 768); int j = sel ? i - 768 : i;
            *(uint4*)(smp + (sel ? PM_WL : PM_WH) + j*16) = (sel ? srcL : srcH)[j];
        }
    }
    __syncthreads();

    float o[8][4];
    #pragma unroll
    for (int m = 0; m < 8; m++) { o[m][0]=o[m][1]=o[m][2]=o[m][3]=0.f; }
    const int laneR = (lane & 7) + ((lane >> 3) & 1)*8;
    const int chS   = lane >> 4;

    #pragma unroll
    for (int ks = 0; ks < 6; ks++) {
        int ar = 16*wrp + laneR;
        int c  = 2*ks + chS;                            // chunk 0..11
        uint32_t aoff = (uint32_t)(ar*256 + (((c & 8) | ((c ^ (ar & 7)) & 7)) << 4));
        uint32_t ah[4], al[4];
        LDSM4(ah, sb + PM_XH + aoff);
        LDSM4(al, sb + PM_XL + aoff);
        #pragma unroll
        for (int g = 0; g < 4; g++) {
            int br = ks*16 + laneR;
            uint32_t boff = (uint32_t)(br*128 + (((2*g + chS) ^ (br & 7)) << 4));
            uint32_t bh[4], bl[4];
            LDSM4T(bh, sb + PM_WH + boff);
            LDSM4T(bl, sb + PM_WL + boff);
            mma16816(o[2*g],   ah, bh[0], bh[1]);
            mma16816(o[2*g],   al, bh[0], bh[1]);
            mma16816(o[2*g],   ah, bl[0], bl[1]);
            mma16816(o[2*g+1], ah, bh[2], bh[3]);
            mma16816(o[2*g+1], al, bh[2], bh[3]);
            mma16816(o[2*g+1], ah, bl[2], bl[3]);
        }
    }

    // ---- epilogue ----
    const float sc    = scale[0];
    const float enres = 1.0f + 1.0f/(float)TT;
    uint32_t *H = nullptr, *L = nullptr;
    if      (z == 0) { H = (uint32_t*)g_QH4; L = (uint32_t*)g_QL4; }
    else if (z == 1) { H = (uint32_t*)g_KH4; L = (uint32_t*)g_KL4; }
    else if (z == 2) { H = (uint32_t*)g_VH4; L = (uint32_t*)g_VL4; }

    int r0 = row0 + 16*wrp + (lane >> 2);
    #pragma unroll
    for (int m = 0; m < 8; m++) {
        int col = (m >> 1)*16 + (m & 1)*8 + (lane & 3)*2;   // 0..62 even
        if (z < 3) {
            float b0 = qkv_b[z*64 + col], b1 = qkv_b[z*64 + col + 1];
            float v0 = o[m][0] + b0, v1 = o[m][1] + b1;
            float v2 = o[m][2] + b0, v3 = o[m][3] + b1;
            if (z == 0) { v0*=sc; v1*=sc; v2*=sc; v3*=sc; }
            wr_pair64(H, L, r0,     col, v0, v1);
            wr_pair64(H, L, r0 + 8, col, v2, v3);
        } else {
            int oc = (z - 3)*64 + col;
            float2 s0; s0.x = o[m][0]*enres; s0.y = o[m][1]*enres;
            float2 s1; s1.x = o[m][2]*enres; s1.y = o[m][3]*enres;
            *(float2*)(g_XDW + (size_t)r0*NOUT + oc)       = s0;
            *(float2*)(g_XDW + (size_t)(r0 + 8)*NOUT + oc) = s1;
        }
    }
}

// ===================== attention: 32-row KV tiles, 3-stage pipeline ========
#define T_QH 0
#define T_QL 16384
#define T_KV 32768
#define ATTN7_SMEM 81920

__global__ __launch_bounds__(256, 2) void attn7_kernel()
{
    extern __shared__ __align__(16) char smp[];
    const uint32_t sb = smem_u32(smp);
    const int b    = blockIdx.y;
    const int q0   = blockIdx.x * 128;
    const int tid  = threadIdx.x;
    const int w    = tid >> 5;
    const int lane = tid & 31;
    const int toff = ((blockIdx.x + blockIdx.y) & 7) << 3;

    auto issue_kv = [&](int t, int s){
        const uint4* s0 = g_KH4 + (size_t)(b*TT + t*32)*8;
        const uint4* s1 = g_KL4 + (size_t)(b*TT + t*32)*8;
        const uint4* s2 = g_VH4 + (size_t)(b*TT + t*32)*8;
        const uint4* s3 = g_VL4 + (size_t)(b*TT + t*32)*8;
        uint32_t base = sb + T_KV + s*16384;
        #pragma unroll
        for (int i = tid; i < 1024; i += 256) {
            int m = i >> 8, j = i & 255;
            const uint4* src = (m==0) ? s0 : (m==1) ? s1 : (m==2) ? s2 : s3;
            CPA(base + m*4096 + j*16, src + j);
        }
        CPC();
    };

    {
        const uint4* qh4 = g_QH4 + (size_t)(b*TT + q0)*8;
        const uint4* ql4 = g_QL4 + (size_t)(b*TT + q0)*8;
        for (int i = tid; i < 2048; i += 256) {
            int sel = i >> 10, j = i & 1023;
            CPA(sb + (sel ? T_QL : T_QH) + j*16, (sel ? ql4 : qh4) + j);
        }
        CPC();
    }
    issue_kv(toff, 0);
    issue_kv((toff + 1) & 63, 1);
    CPW(2);
    __syncthreads();

    uint32_t qh[4][4], ql[4][4];
    {
        int rr = 16*w + (lane & 7) + ((lane >> 3) & 1)*8;
        #pragma unroll
        for (int k = 0; k < 4; k++) {
            int ch = 2*k + (lane >> 4);
            LDSM4(qh[k], sb + T_QH + swz(rr, ch));
            LDSM4(ql[k], sb + T_QL + swz(rr, ch));
        }
    }

    float o[8][4];
    #pragma unroll
    for (int n = 0; n < 8; n++) { o[n][0]=o[n][1]=o[n][2]=o[n][3]=0.f; }
    float lacc0 = 0.f, lacc1 = 0.f;

    const int rBk  = (lane & 7) + (lane >> 4)*8;
    const int chBk = (lane >> 3) & 1;
    const int rBv  = (lane & 7) + ((lane >> 3) & 1)*8;
    const int chBv = (lane >> 4);

    int stage = 0;
    for (int t = 0; t < 64; t++) {
        if (t < 63) CPW(1); else CPW(0);
        __syncthreads();
        if (t + 2 < 64) {
            int s2 = stage + 2; if (s2 >= 3) s2 -= 3;
            issue_kv((t + 2 + toff) & 63, s2);
        }
        const uint32_t KH = sb + T_KV + stage*16384;
        const uint32_t KL = KH + 4096, VH = KH + 8192, VL = KH + 12288;

        #pragma unroll
        for (int n2 = 0; n2 < 2; n2++) {
            float c0[4] = {0,0,0,0}, c1[4] = {0,0,0,0};
            int s0 = n2*16;
            #pragma unroll
            for (int k = 0; k < 4; k++) {
                uint32_t off = swz(s0 + rBk, 2*k + chBk);
                uint32_t bh[4], bl[4];
                LDSM4(bh, KH + off);
                LDSM4(bl, KL + off);
                mma16816(c0, qh[k], bh[0], bh[1]);
                mma16816(c0, ql[k], bh[0], bh[1]);
                mma16816(c0, qh[k], bl[0], bl[1]);
                mma16816(c1, qh[k], bh[2], bh[3]);
                mma16816(c1, ql[k], bh[2], bh[3]);
                mma16816(c1, qh[k], bl[2], bl[3]);
            }
            float e0 = __expf(c0[0]), e1 = __expf(c0[1]);
            float e2 = __expf(c0[2]), e3 = __expf(c0[3]);
            float e4 = __expf(c1[0]), e5 = __expf(c1[1]);
            float e6 = __expf(c1[2]), e7 = __expf(c1[3]);
            lacc0 += e0 + e1 + e4 + e5;
            lacc1 += e2 + e3 + e6 + e7;
            uint32_t ph[4], pl[4];
            ph[0] = cvt2(e1, e0);
            ph[1] = cvt2(e3, e2);
            ph[2] = cvt2(e5, e4);
            ph[3] = cvt2(e7, e6);
            pl[0] = cvt2(e1 - __uint_as_float(ph[0] & 0xFFFF0000u),
                         e0 - __uint_as_float(ph[0] << 16));
            pl[1] = cvt2(e3 - __uint_as_float(ph[1] & 0xFFFF0000u),
                         e2 - __uint_as_float(ph[1] << 16));
            pl[2] = cvt2(e5 - __uint_as_float(ph[2] & 0xFFFF0000u),
                         e4 - __uint_as_float(ph[2] << 16));
            pl[3] = cvt2(e7 - __uint_as_float(ph[3] & 0xFFFF0000u),
                         e6 - __uint_as_float(ph[3] << 16));

            #pragma unroll
            for (int dp = 0; dp < 4; dp++) {
                uint32_t off = swz(s0 + rBv, 2*dp + chBv);
                uint32_t bh[4], bl[4];
                LDSM4T(bh, VH + off);
                LDSM4T(bl, VL + off);
                mma16816(o[2*dp],   ph, bh[0], bh[1]);
                mma16816(o[2*dp],   pl, bh[0], bh[1]);
                mma16816(o[2*dp],   ph, bl[0], bl[1]);
                mma16816(o[2*dp+1], ph, bh[2], bh[3]);
                mma16816(o[2*dp+1], pl, bh[2], bh[3]);
                mma16816(o[2*dp+1], ph, bl[2], bl[3]);
            }
        }
        if (++stage == 3) stage = 0;
    }

    lacc0 += __shfl_xor_sync(0xffffffffu, lacc0, 1);
    lacc0 += __shfl_xor_sync(0xffffffffu, lacc0, 2);
    lacc1 += __shfl_xor_sync(0xffffffffu, lacc1, 1);
    lacc1 += __shfl_xor_sync(0xffffffffu, lacc1, 2);
    float inv0 = 1.f / lacc0, inv1 = 1.f / lacc1;

    uint32_t* AH = (uint32_t*)g_AH4;
    uint32_t* AL = (uint32_t*)g_AL4;
    int r0 = b*TT + q0 + 16*w + (lane >> 2);
    int cl = (lane & 3)*2;
    #pragma unroll
    for (int n = 0; n < 8; n++) {
        wr_pair64(AH, AL, r0,     n*8 + cl, o[n][0]*inv0, o[n][1]*inv0);
        wr_pair64(AH, AL, r0 + 8, n*8 + cl, o[n][2]*inv1, o[n][3]*inv1);
    }
}

// ===================== conv1d: pre-split operands, X loaded once ===========
template<int WB, int NH, bool SPLIT>
__global__ __launch_bounds__(256) void convt_kernel(
    const uint4* __restrict__ inH4, const uint4* __restrict__ inL4,
    const uint32_t* __restrict__ wH, const uint32_t* __restrict__ wL,
    const float* __restrict__ bias,
    const float* __restrict__ resid, float* __restrict__ outF,
    uint32_t* __restrict__ outH, uint32_t* __restrict__ outL)
{
    extern __shared__ __align__(16) char smp[];
    const uint32_t sb = smem_u32(smp);
    const int b = blockIdx.y, t0 = blockIdx.x*128, z = blockIdx.z;
    const int tid = threadIdx.x, wrp = tid >> 5, lane = tid & 31;

    const int XH = 0, XL = 130*WB;
    const int W0 = 2*130*WB, WL0 = W0 + NH*8192;

    const int n4 = 130*(WB/16);
    for (int i = tid; i < 2*n4; i += 256) {
        int sel = (i >= n4); int j = sel ? i - n4 : i;
        int r = j/(WB/16), c = j%(WB/16);
        int t = t0 + r - 1;
        uint4 v = make_uint4(0,0,0,0);
        if (t >= 0 && t < TT) v = (sel ? inL4 : inH4)[(size_t)(b*TT+t)*(WB/16) + c];
        *(uint4*)(smp + (sel ? XL : XH) + r*WB + c*16) = v;
    }

    float o[8][4];
    #pragma unroll
    for (int m = 0; m < 8; m++) { o[m][0]=o[m][1]=o[m][2]=o[m][3]=0.f; }
    const int laneR = (lane & 7) + ((lane >> 3) & 1)*8;
    const int chS   = lane >> 4;

    for (int k = 0; k < 3; k++) {
        __syncthreads();
        for (int i = tid; i < NH*2*512; i += 256) {
            int sel = (i >= NH*512); int j = sel ? i - NH*512 : i;
            int h = j >> 9, c = j & 511;
            const uint32_t* src = (sel ? wL : wH) + (size_t)((k*NH+h)*2 + z)*2048 + c*4;
            *(uint4*)(smp + (sel ? WL0 : W0) + h*8192 + c*16) = *(const uint4*)src;
        }
        __syncthreads();

        #pragma unroll
        for (int h = 0; h < NH; h++) {
            #pragma unroll
            for (int ks = 0; ks < 4; ks++) {
                int ar = 16*wrp + laneR + k;
                uint32_t aoff = (uint32_t)(ar*WB + h*128 + (((2*ks+chS) ^ ((ar+7)&7))<<4));
                uint32_t ah[4], al[4];
                LDSM4(ah, sb + XH + aoff);
                LDSM4(al, sb + XL + aoff);
                #pragma unroll
                for (int g = 0; g < 4; g++) {
                    int br = ks*16 + laneR;
                    uint32_t boff = (uint32_t)(h*8192 + br*128 + (((2*g+chS) ^ (br&7))<<4));
                    uint32_t bh[4], bl[4];
                    LDSM4T(bh, sb + W0  + boff);
                    LDSM4T(bl, sb + WL0 + boff);
                    mma16816(o[2*g],   ah, bh[0], bh[1]);
                    mma16816(o[2*g],   al, bh[0], bh[1]);
                    mma16816(o[2*g],   ah, bl[0], bl[1]);
                    mma16816(o[2*g+1], ah, bh[2], bh[3]);
                    mma16816(o[2*g+1], al, bh[2], bh[3]);
                    mma16816(o[2*g+1], ah, bl[2], bl[3]);
                }
            }
        }
    }

    int r0 = t0 + 16*wrp + (lane >> 2);
    #pragma unroll
    for (int m = 0; m < 8; m++) {
        int col = (m >> 1)*16 + (m & 1)*8 + (lane & 3)*2;
        int co  = z*64 + col;
        float b0 = bias[co], b1 = bias[co + 1];
        float v0 = fmaxf(o[m][0] + b0, 0.f);
        float v1 = fmaxf(o[m][1] + b1, 0.f);
        float v2 = fmaxf(o[m][2] + b0, 0.f);
        float v3 = fmaxf(o[m][3] + b1, 0.f);
        if (SPLIT) {
            #pragma unroll
            for (int rr = 0; rr < 2; rr++) {
                int row = b*TT + r0 + rr*8;
                float a = rr ? v2 : v0, bb = rr ? v3 : v1;
                int ch = co >> 3;
                int chp = (ch & 8) | ((ch ^ (row & 7)) & 7);
                int u = row*64 + (chp << 2) + ((co & 7) >> 1);
                __nv_bfloat16 ha=__float2bfloat16(a), hb=__float2bfloat16(bb);
                outH[u] = ((uint32_t)__bfloat16_as_ushort(hb)<<16)|__bfloat16_as_ushort(ha);
                outL[u] = packbf(a-__bfloat162float(ha), bb-__bfloat162float(hb));
            }
        } else {
            size_t base0 = (size_t)(b*TT + r0)*NOUT + co;
            size_t base1 = (size_t)(b*TT + r0 + 8)*NOUT + co;
            float2 ra = *(const float2*)(resid + base0);
            float2 rb = *(const float2*)(resid + base1);
            float2 s0; s0.x = fmaxf(v0 + ra.x, 0.f); s0.y = fmaxf(v1 + ra.y, 0.f);
            float2 s1; s1.x = fmaxf(v2 + rb.x, 0.f); s1.y = fmaxf(v3 + rb.y, 0.f);
            *(float2*)(outF + base0) = s0;
            *(float2*)(outF + base1) = s1;
        }
    }
}

// ---------------------------------------------------------------------------
extern "C" void kernel_launch(void* const* d_in, const int* in_sizes, int n_in,
                              void* d_out, int out_size)
{
    const float* x       = (const float*)d_in[0];
    const float* qkv_w   = (const float*)d_in[1];
    const float* qkv_b   = (const float*)d_in[2];
    const float* scale   = (const float*)d_in[3];
    const float* conv_w1 = (const float*)d_in[4];
    const float* conv_b1 = (const float*)d_in[5];
    const float* conv_w2 = (const float*)d_in[6];
    const float* conv_b2 = (const float*)d_in[7];
    const float* down_w  = (const float*)d_in[8];
    float* out = (float*)d_out;

    const int SM1 = 2*130*128 + 2*8192;          // 49664
    const int SM2 = 2*130*256 + 2*2*8192;        // 99328

    cudaFuncSetAttribute(projm_kernel, cudaFuncAttributeMaxDynamicSharedMemorySize, PROJM_SMEM);
    cudaFuncSetAttribute(attn7_kernel, cudaFuncAttributeMaxDynamicSharedMemorySize, ATTN7_SMEM);
    cudaFuncSetAttribute((const void*)convt_kernel<128,1,true>,
                         cudaFuncAttributeMaxDynamicSharedMemorySize, SM1);
    cudaFuncSetAttribute((const void*)convt_kernel<256,2,false>,
                         cudaFuncAttributeMaxDynamicSharedMemorySize, SM2);

    uint4 *aH, *aL, *hH, *hL, *w1H, *w1L, *w2H, *w2L, *pwH, *pwL;
    float *xdw;
    cudaGetSymbolAddress((void**)&aH,  g_AH4);
    cudaGetSymbolAddress((void**)&aL,  g_AL4);
    cudaGetSymbolAddress((void**)&hH,  g_HH4);
    cudaGetSymbolAddress((void**)&hL,  g_HL4);
    cudaGetSymbolAddress((void**)&w1H, g_W1H4);
    cudaGetSymbolAddress((void**)&w1L, g_W1L4);
    cudaGetSymbolAddress((void**)&w2H, g_W2H4);
    cudaGetSymbolAddress((void**)&w2L, g_W2L4);
    cudaGetSymbolAddress((void**)&pwH, g_PWH4);
    cudaGetSymbolAddress((void**)&pwL, g_PWL4);
    cudaGetSymbolAddress((void**)&xdw, g_XDW);

    prep_w_kernel <<<48, 256>>>(conv_w1, 64,  (uint32_t*)w1H, (uint32_t*)w1L);
    prep_w_kernel <<<96, 256>>>(conv_w2, 128, (uint32_t*)w2H, (uint32_t*)w2L);
    prep_pw_kernel<<<60, 256>>>(qkv_w, down_w, (uint32_t*)pwH, (uint32_t*)pwL);
    projm_kernel<<<dim3(BT/128, 5), 256, PROJM_SMEM>>>(x, qkv_b, scale);
    attn7_kernel<<<dim3(TT/128, BB), 256, ATTN7_SMEM>>>();
    convt_kernel<128,1,true ><<<dim3(TT/128, BB, 2), 256, SM1>>>(
        aH, aL, (uint32_t*)w1H, (uint32_t*)w1L, conv_b1, nullptr, nullptr,
        (uint32_t*)hH, (uint32_t*)hL);
    convt_kernel<256,2,false><<<dim3(TT/128, BB, 2), 256, SM2>>>(
        hH, hL, (uint32_t*)w2H, (uint32_t*)w2L, conv_b2, xdw, out,
        nullptr, nullptr);
}

// round 13
// speedup vs baseline: 1.3305x; 1.0621x over previous
#include <cuda_runtime.h>
#include <cuda_bf16.h>
#include <cstdint>

#define BB   16
#define TT   2048
#define NIN  96
#define NOUT 128
#define DD   64
#define BT   (BB*TT)

// ---- global scratch (pre-split bf16 hi/lo, swizzled 128B/256B rows) ----
__device__ uint4 g_QH4[BT*8]; __device__ uint4 g_QL4[BT*8];
__device__ uint4 g_KH4[BT*8]; __device__ uint4 g_KL4[BT*8];
__device__ uint4 g_VH4[BT*8]; __device__ uint4 g_VL4[BT*8];
__device__ uint4 g_AH4[BT*8]; __device__ uint4 g_AL4[BT*8];   // attn out
__device__ uint4 g_HH4[BT*16]; __device__ uint4 g_HL4[BT*16]; // conv1 out (256B rows)
__device__ float g_XDW[BT*NOUT];
__device__ uint4 g_W1H4[3*2*512];   __device__ uint4 g_W1L4[3*2*512];
__device__ uint4 g_W2H4[3*2*2*512]; __device__ uint4 g_W2L4[3*2*2*512];
__device__ uint4 g_PWH4[5*768];     __device__ uint4 g_PWL4[5*768];   // proj weights

// ===================== helpers =====================
__device__ __forceinline__ uint32_t smem_u32(const void* p){
    uint32_t a;
    asm("{ .reg .u64 t; cvta.to.shared.u64 t, %1; cvt.u32.u64 %0, t; }" : "=r"(a) : "l"(p));
    return a;
}
#define LDSM4(R, A) \
    asm volatile("ldmatrix.sync.aligned.m8n8.x4.shared.b16 {%0,%1,%2,%3}, [%4];" \
        : "=r"((R)[0]),"=r"((R)[1]),"=r"((R)[2]),"=r"((R)[3]) : "r"(A))
#define LDSM4T(R, A) \
    asm volatile("ldmatrix.sync.aligned.m8n8.x4.trans.shared.b16 {%0,%1,%2,%3}, [%4];" \
        : "=r"((R)[0]),"=r"((R)[1]),"=r"((R)[2]),"=r"((R)[3]) : "r"(A))
#define CPA(dst, src) \
    asm volatile("cp.async.cg.shared.global [%0], [%1], 16;" :: "r"(dst), "l"(src))
#define CPC() asm volatile("cp.async.commit_group;")
#define CPW(n) asm volatile("cp.async.wait_group %0;" :: "n"(n))

__device__ __forceinline__ void mma16816(float* c, const uint32_t* a, uint32_t b0, uint32_t b1){
    asm volatile(
        "mma.sync.aligned.m16n8k16.row.col.f32.bf16.bf16.f32 "
        "{%0,%1,%2,%3},{%4,%5,%6,%7},{%8,%9},{%0,%1,%2,%3};"
        : "+f"(c[0]),"+f"(c[1]),"+f"(c[2]),"+f"(c[3])
        : "r"(a[0]),"r"(a[1]),"r"(a[2]),"r"(a[3]),"r"(b0),"r"(b1));
}
__device__ __forceinline__ uint32_t packbf(float lo, float hi){
    uint16_t l = __bfloat16_as_ushort(__float2bfloat16(lo));
    uint16_t h = __bfloat16_as_ushort(__float2bfloat16(hi));
    return ((uint32_t)h << 16) | (uint32_t)l;
}
__device__ __forceinline__ uint32_t cvt2(float hi, float lo){
    uint32_t r;
    asm("cvt.rn.bf16x2.f32 %0, %1, %2;" : "=r"(r) : "f"(hi), "f"(lo));
    return r;
}
__device__ __forceinline__ uint32_t swz(int r, int ch){
    return (uint32_t)(r*128 + ((ch ^ (r & 7)) << 4));
}
// write a hi/lo split pair (cols cl, cl+1, cl even) into 128B-row global arrays
__device__ __forceinline__ void wr_pair64(uint32_t* H, uint32_t* L, int row, int cl,
                                          float a, float bvv){
    int byte = cl*2;
    int u = row*32 + (((byte>>4) ^ (row&7))<<2) + ((byte&15)>>2);
    __nv_bfloat16 ha=__float2bfloat16(a), hb=__float2bfloat16(bvv);
    H[u] = ((uint32_t)__bfloat16_as_ushort(hb)<<16)|__bfloat16_as_ushort(ha);
    L[u] = packbf(a-__bfloat162float(ha), bvv-__bfloat162float(hb));
}

// ===================== conv weight prep =====================
__global__ void prep_w_kernel(const float* __restrict__ w, int Cin,
                              uint32_t* __restrict__ wH, uint32_t* __restrict__ wL)
{
    int nh = Cin >> 6;
    int total = 3*Cin*64;   // co-pairs
    for (int idx = blockIdx.x*blockDim.x + threadIdx.x; idx < total;
         idx += gridDim.x*blockDim.x) {
        int k = idx/(Cin*64); int rem = idx - k*Cin*64;
        int ci = rem >> 6, cop = rem & 63;
        float2 v = *(const float2*)(w + (size_t)(k*Cin+ci)*NOUT + cop*2);
        int hci = ci>>6, cil = ci&63, hco = cop>>5, copl = cop&31;
        int tidx = (k*nh + hci)*2 + hco;
        int u = tidx*2048 + cil*32 + (((copl>>2) ^ (cil&7))<<2) + (copl&3);
        __nv_bfloat16 hx=__float2bfloat16(v.x), hy=__float2bfloat16(v.y);
        wH[u] = ((uint32_t)__bfloat16_as_ushort(hy)<<16)|__bfloat16_as_ushort(hx);
        wL[u] = packbf(v.x-__bfloat162float(hx), v.y-__bfloat162float(hy));
    }
}

// ===================== proj weight prep: [96, 192|128] -> 5 z-tiles ========
__global__ void prep_pw_kernel(const float* __restrict__ qkv_w,
                               const float* __restrict__ down_w,
                               uint32_t* __restrict__ pH, uint32_t* __restrict__ pL)
{
    int total = 96*160;   // (ci, co-pair)
    for (int idx = blockIdx.x*blockDim.x + threadIdx.x; idx < total;
         idx += gridDim.x*blockDim.x) {
        int ci = idx/160, cop = idx - ci*160;
        int z = cop >> 5, copl = cop & 31;
        int col = cop*2;
        float2 v = (z < 3) ? *(const float2*)(qkv_w + ci*192 + col)
                           : *(const float2*)(down_w + ci*128 + (col - 192));
        int u = z*3072 + ci*32 + (((copl>>2) ^ (ci&7))<<2) + (copl&3);
        __nv_bfloat16 hx=__float2bfloat16(v.x), hy=__float2bfloat16(v.y);
        pH[u] = ((uint32_t)__bfloat16_as_ushort(hy)<<16)|__bfloat16_as_ushort(hx);
        pL[u] = packbf(v.x-__bfloat162float(hx), v.y-__bfloat162float(hy));
    }
}

// ===================== proj as 3-term bf16 mma GEMM (M=64 tiles) ===========
// CTA = 64 rows x 64 cols (z-block). 4 m-warps x 2 n-halves. 56KB -> 4 CTA/SM.
// W tiles prefetched by cp.async, overlapped with X load/convert.
#define PM_XH 0
#define PM_XL 16384
#define PM_WH 32768
#define PM_WL 45056
#define PROJM_SMEM 57344
__global__ __launch_bounds__(256) void projm_kernel(
    const float* __restrict__ x, const float* __restrict__ qkv_b,
    const float* __restrict__ scale)
{
    extern __shared__ __align__(16) char smp[];
    const uint32_t sb = smem_u32(smp);
    const int row0 = blockIdx.x * 64;
    const int z    = blockIdx.y;
    const int tid  = threadIdx.x, wrp = tid >> 5, lane = tid & 31;
    const int mw   = wrp & 3, nh = wrp >> 2;

    // ---- issue W tile cp.async first (overlaps X convert) ----
    {
        const uint4* srcH = (const uint4*)((const uint32_t*)g_PWH4 + z*3072);
        const uint4* srcL = (const uint4*)((const uint32_t*)g_PWL4 + z*3072);
        #pragma unroll
        for (int i = tid; i < 1536; i += 256) {
            int sel = (i >= 768); int j = sel ? i - 768 : i;
            CPA(sb + (sel ? PM_WL : PM_WH) + j*16, (sel ? srcL : srcH) + j);
        }
        CPC();
    }

    // ---- X tile [64][96] -> hi/lo bf16, 256B rows, half-swizzled ----
    {
        float2 vals[12];
        #pragma unroll
        for (int j = 0; j < 12; j++) {
            int i = tid + j*256;
            int r = i/48, p = i - r*48;
            vals[j] = *(const float2*)(x + (size_t)(row0 + r)*NIN + p*2);
        }
        #pragma unroll
        for (int j = 0; j < 12; j++) {
            int i = tid + j*256;
            int r = i/48, p = i - r*48;
            int c = p >> 2;
            int pos = (c & 8) | ((c ^ (r & 7)) & 7);
            uint32_t off = (uint32_t)(r*256 + pos*16 + (p & 3)*4);
            uint32_t h = cvt2(vals[j].y, vals[j].x);
            *(uint32_t*)(smp + PM_XH + off) = h;
            *(uint32_t*)(smp + PM_XL + off) = cvt2(vals[j].y - __uint_as_float(h & 0xFFFF0000u),
                                                   vals[j].x - __uint_as_float(h << 16));
        }
    }
    CPW(0);
    __syncthreads();

    float o[4][4];
    #pragma unroll
    for (int m = 0; m < 4; m++) { o[m][0]=o[m][1]=o[m][2]=o[m][3]=0.f; }
    const int laneR = (lane & 7) + ((lane >> 3) & 1)*8;
    const int chS   = lane >> 4;

    #pragma unroll
    for (int ks = 0; ks < 6; ks++) {
        int ar = 16*mw + laneR;
        int c  = 2*ks + chS;                            // chunk 0..11
        uint32_t aoff = (uint32_t)(ar*256 + (((c & 8) | ((c ^ (ar & 7)) & 7)) << 4));
        uint32_t ah[4], al[4];
        LDSM4(ah, sb + PM_XH + aoff);
        LDSM4(al, sb + PM_XL + aoff);
        #pragma unroll
        for (int g = 0; g < 2; g++) {
            int br = ks*16 + laneR;
            int cch = nh*4 + 2*g + chS;
            uint32_t boff = (uint32_t)(br*128 + ((cch ^ (br & 7)) << 4));
            uint32_t bh[4], bl[4];
            LDSM4T(bh, sb + PM_WH + boff);
            LDSM4T(bl, sb + PM_WL + boff);
            mma16816(o[2*g],   ah, bh[0], bh[1]);
            mma16816(o[2*g],   al, bh[0], bh[1]);
            mma16816(o[2*g],   ah, bl[0], bl[1]);
            mma16816(o[2*g+1], ah, bh[2], bh[3]);
            mma16816(o[2*g+1], al, bh[2], bh[3]);
            mma16816(o[2*g+1], ah, bl[2], bl[3]);
        }
    }

    // ---- epilogue ----
    const float sc    = scale[0];
    const float enres = 1.0f + 1.0f/(float)TT;
    uint32_t *H = nullptr, *L = nullptr;
    if      (z == 0) { H = (uint32_t*)g_QH4; L = (uint32_t*)g_QL4; }
    else if (z == 1) { H = (uint32_t*)g_KH4; L = (uint32_t*)g_KL4; }
    else if (z == 2) { H = (uint32_t*)g_VH4; L = (uint32_t*)g_VL4; }

    int r0 = row0 + 16*mw + (lane >> 2);
    #pragma unroll
    for (int m = 0; m < 4; m++) {
        int col = nh*32 + (m >> 1)*16 + (m & 1)*8 + (lane & 3)*2;
        if (z < 3) {
            float b0 = qkv_b[z*64 + col], b1 = qkv_b[z*64 + col + 1];
            float v0 = o[m][0] + b0, v1 = o[m][1] + b1;
            float v2 = o[m][2] + b0, v3 = o[m][3] + b1;
            if (z == 0) { v0*=sc; v1*=sc; v2*=sc; v3*=sc; }
            wr_pair64(H, L, r0,     col, v0, v1);
            wr_pair64(H, L, r0 + 8, col, v2, v3);
        } else {
            int oc = (z - 3)*64 + col;
            float2 s0; s0.x = o[m][0]*enres; s0.y = o[m][1]*enres;
            float2 s1; s1.x = o[m][2]*enres; s1.y = o[m][3]*enres;
            *(float2*)(g_XDW + (size_t)r0*NOUT + oc)       = s0;
            *(float2*)(g_XDW + (size_t)(r0 + 8)*NOUT + oc) = s1;
        }
    }
}

// ===================== attention: 32-row KV tiles, 3-stage pipeline ========
#define T_QH 0
#define T_QL 16384
#define T_KV 32768
#define ATTN7_SMEM 81920

__global__ __launch_bounds__(256, 2) void attn7_kernel()
{
    extern __shared__ __align__(16) char smp[];
    const uint32_t sb = smem_u32(smp);
    const int b    = blockIdx.y;
    const int q0   = blockIdx.x * 128;
    const int tid  = threadIdx.x;
    const int w    = tid >> 5;
    const int lane = tid & 31;
    const int toff = ((blockIdx.x + blockIdx.y) & 7) << 3;

    auto issue_kv = [&](int t, int s){
        const uint4* s0 = g_KH4 + (size_t)(b*TT + t*32)*8;
        const uint4* s1 = g_KL4 + (size_t)(b*TT + t*32)*8;
        const uint4* s2 = g_VH4 + (size_t)(b*TT + t*32)*8;
        const uint4* s3 = g_VL4 + (size_t)(b*TT + t*32)*8;
        uint32_t base = sb + T_KV + s*16384;
        #pragma unroll
        for (int i = tid; i < 1024; i += 256) {
            int m = i >> 8, j = i & 255;
            const uint4* src = (m==0) ? s0 : (m==1) ? s1 : (m==2) ? s2 : s3;
            CPA(base + m*4096 + j*16, src + j);
        }
        CPC();
    };

    {
        const uint4* qh4 = g_QH4 + (size_t)(b*TT + q0)*8;
        const uint4* ql4 = g_QL4 + (size_t)(b*TT + q0)*8;
        for (int i = tid; i < 2048; i += 256) {
            int sel = i >> 10, j = i & 1023;
            CPA(sb + (sel ? T_QL : T_QH) + j*16, (sel ? ql4 : qh4) + j);
        }
        CPC();
    }
    issue_kv(toff, 0);
    issue_kv((toff + 1) & 63, 1);
    CPW(2);
    __syncthreads();

    uint32_t qh[4][4], ql[4][4];
    {
        int rr = 16*w + (lane & 7) + ((lane >> 3) & 1)*8;
        #pragma unroll
        for (int k = 0; k < 4; k++) {
            int ch = 2*k + (lane >> 4);
            LDSM4(qh[k], sb + T_QH + swz(rr, ch));
            LDSM4(ql[k], sb + T_QL + swz(rr, ch));
        }
    }

    float o[8][4];
    #pragma unroll
    for (int n = 0; n < 8; n++) { o[n][0]=o[n][1]=o[n][2]=o[n][3]=0.f; }
    float lacc0 = 0.f, lacc1 = 0.f;

    const int rBk  = (lane & 7) + (lane >> 4)*8;
    const int chBk = (lane >> 3) & 1;
    const int rBv  = (lane & 7) + ((lane >> 3) & 1)*8;
    const int chBv = (lane >> 4);

    int stage = 0;
    for (int t = 0; t < 64; t++) {
        if (t < 63) CPW(1); else CPW(0);
        __syncthreads();
        if (t + 2 < 64) {
            int s2 = stage + 2; if (s2 >= 3) s2 -= 3;
            issue_kv((t + 2 + toff) & 63, s2);
        }
        const uint32_t KH = sb + T_KV + stage*16384;
        const uint32_t KL = KH + 4096, VH = KH + 8192, VL = KH + 12288;

        #pragma unroll
        for (int n2 = 0; n2 < 2; n2++) {
            float c0[4] = {0,0,0,0}, c1[4] = {0,0,0,0};
            int s0 = n2*16;
            #pragma unroll
            for (int k = 0; k < 4; k++) {
                uint32_t off = swz(s0 + rBk, 2*k + chBk);
                uint32_t bh[4], bl[4];
                LDSM4(bh, KH + off);
                LDSM4(bl, KL + off);
                mma16816(c0, qh[k], bh[0], bh[1]);
                mma16816(c0, ql[k], bh[0], bh[1]);
                mma16816(c0, qh[k], bl[0], bl[1]);
                mma16816(c1, qh[k], bh[2], bh[3]);
                mma16816(c1, ql[k], bh[2], bh[3]);
                mma16816(c1, qh[k], bl[2], bl[3]);
            }
            float e0 = __expf(c0[0]), e1 = __expf(c0[1]);
            float e2 = __expf(c0[2]), e3 = __expf(c0[3]);
            float e4 = __expf(c1[0]), e5 = __expf(c1[1]);
            float e6 = __expf(c1[2]), e7 = __expf(c1[3]);
            lacc0 += e0 + e1 + e4 + e5;
            lacc1 += e2 + e3 + e6 + e7;
            uint32_t ph[4], pl[4];
            ph[0] = cvt2(e1, e0);
            ph[1] = cvt2(e3, e2);
            ph[2] = cvt2(e5, e4);
            ph[3] = cvt2(e7, e6);
            pl[0] = cvt2(e1 - __uint_as_float(ph[0] & 0xFFFF0000u),
                         e0 - __uint_as_float(ph[0] << 16));
            pl[1] = cvt2(e3 - __uint_as_float(ph[1] & 0xFFFF0000u),
                         e2 - __uint_as_float(ph[1] << 16));
            pl[2] = cvt2(e5 - __uint_as_float(ph[2] & 0xFFFF0000u),
                         e4 - __uint_as_float(ph[2] << 16));
            pl[3] = cvt2(e7 - __uint_as_float(ph[3] & 0xFFFF0000u),
                         e6 - __uint_as_float(ph[3] << 16));

            #pragma unroll
            for (int dp = 0; dp < 4; dp++) {
                uint32_t off = swz(s0 + rBv, 2*dp + chBv);
                uint32_t bh[4], bl[4];
                LDSM4T(bh, VH + off);
                LDSM4T(bl, VL + off);
                mma16816(o[2*dp],   ph, bh[0], bh[1]);
                mma16816(o[2*dp],   pl, bh[0], bh[1]);
                mma16816(o[2*dp],   ph, bl[0], bl[1]);
                mma16816(o[2*dp+1], ph, bh[2], bh[3]);
                mma16816(o[2*dp+1], pl, bh[2], bh[3]);
                mma16816(o[2*dp+1], ph, bl[2], bl[3]);
            }
        }
        if (++stage == 3) stage = 0;
    }

    lacc0 += __shfl_xor_sync(0xffffffffu, lacc0, 1);
    lacc0 += __shfl_xor_sync(0xffffffffu, lacc0, 2);
    lacc1 += __shfl_xor_sync(0xffffffffu, lacc1, 1);
    lacc1 += __shfl_xor_sync(0xffffffffu, lacc1, 2);
    float inv0 = 1.f / lacc0, inv1 = 1.f / lacc1;

    uint32_t* AH = (uint32_t*)g_AH4;
    uint32_t* AL = (uint32_t*)g_AL4;
    int r0 = b*TT + q0 + 16*w + (lane >> 2);
    int cl = (lane & 3)*2;
    #pragma unroll
    for (int n = 0; n < 8; n++) {
        wr_pair64(AH, AL, r0,     n*8 + cl, o[n][0]*inv0, o[n][1]*inv0);
        wr_pair64(AH, AL, r0 + 8, n*8 + cl, o[n][2]*inv1, o[n][3]*inv1);
    }
}

// ===================== conv1d: pre-split operands, X loaded once ===========
template<int WB, int NH, bool SPLIT>
__global__ __launch_bounds__(256) void convt_kernel(
    const uint4* __restrict__ inH4, const uint4* __restrict__ inL4,
    const uint32_t* __restrict__ wH, const uint32_t* __restrict__ wL,
    const float* __restrict__ bias,
    const float* __restrict__ resid, float* __restrict__ outF,
    uint32_t* __restrict__ outH, uint32_t* __restrict__ outL)
{
    extern __shared__ __align__(16) char smp[];
    const uint32_t sb = smem_u32(smp);
    const int b = blockIdx.y, t0 = blockIdx.x*128, z = blockIdx.z;
    const int tid = threadIdx.x, wrp = tid >> 5, lane = tid & 31;

    const int XH = 0, XL = 130*WB;
    const int W0 = 2*130*WB, WL0 = W0 + NH*8192;

    const int n4 = 130*(WB/16);
    for (int i = tid; i < 2*n4; i += 256) {
        int sel = (i >= n4); int j = sel ? i - n4 : i;
        int r = j/(WB/16), c = j%(WB/16);
        int t = t0 + r - 1;
        uint4 v = make_uint4(0,0,0,0);
        if (t >= 0 && t < TT) v = (sel ? inL4 : inH4)[(size_t)(b*TT+t)*(WB/16) + c];
        *(uint4*)(smp + (sel ? XL : XH) + r*WB + c*16) = v;
    }

    float o[8][4];
    #pragma unroll
    for (int m = 0; m < 8; m++) { o[m][0]=o[m][1]=o[m][2]=o[m][3]=0.f; }
    const int laneR = (lane & 7) + ((lane >> 3) & 1)*8;
    const int chS   = lane >> 4;

    for (int k = 0; k < 3; k++) {
        __syncthreads();
        for (int i = tid; i < NH*2*512; i += 256) {
            int sel = (i >= NH*512); int j = sel ? i - NH*512 : i;
            int h = j >> 9, c = j & 511;
            const uint32_t* src = (sel ? wL : wH) + (size_t)((k*NH+h)*2 + z)*2048 + c*4;
            *(uint4*)(smp + (sel ? WL0 : W0) + h*8192 + c*16) = *(const uint4*)src;
        }
        __syncthreads();

        #pragma unroll
        for (int h = 0; h < NH; h++) {
            #pragma unroll
            for (int ks = 0; ks < 4; ks++) {
                int ar = 16*wrp + laneR + k;
                uint32_t aoff = (uint32_t)(ar*WB + h*128 + (((2*ks+chS) ^ ((ar+7)&7))<<4));
                uint32_t ah[4], al[4];
                LDSM4(ah, sb + XH + aoff);
                LDSM4(al, sb + XL + aoff);
                #pragma unroll
                for (int g = 0; g < 4; g++) {
                    int br = ks*16 + laneR;
                    uint32_t boff = (uint32_t)(h*8192 + br*128 + (((2*g+chS) ^ (br&7))<<4));
                    uint32_t bh[4], bl[4];
                    LDSM4T(bh, sb + W0  + boff);
                    LDSM4T(bl, sb + WL0 + boff);
                    mma16816(o[2*g],   ah, bh[0], bh[1]);
                    mma16816(o[2*g],   al, bh[0], bh[1]);
                    mma16816(o[2*g],   ah, bl[0], bl[1]);
                    mma16816(o[2*g+1], ah, bh[2], bh[3]);
                    mma16816(o[2*g+1], al, bh[2], bh[3]);
                    mma16816(o[2*g+1], ah, bl[2], bl[3]);
                }
            }
        }
    }

    int r0 = t0 + 16*wrp + (lane >> 2);
    #pragma unroll
    for (int m = 0; m < 8; m++) {
        int col = (m >> 1)*16 + (m & 1)*8 + (lane & 3)*2;
        int co  = z*64 + col;
        float b0 = bias[co], b1 = bias[co + 1];
        float v0 = fmaxf(o[m][0] + b0, 0.f);
        float v1 = fmaxf(o[m][1] + b1, 0.f);
        float v2 = fmaxf(o[m][2] + b0, 0.f);
        float v3 = fmaxf(o[m][3] + b1, 0.f);
        if (SPLIT) {
            #pragma unroll
            for (int rr = 0; rr < 2; rr++) {
                int row = b*TT + r0 + rr*8;
                float a = rr ? v2 : v0, bb = rr ? v3 : v1;
                int ch = co >> 3;
                int chp = (ch & 8) | ((ch ^ (row & 7)) & 7);
                int u = row*64 + (chp << 2) + ((co & 7) >> 1);
                __nv_bfloat16 ha=__float2bfloat16(a), hb=__float2bfloat16(bb);
                outH[u] = ((uint32_t)__bfloat16_as_ushort(hb)<<16)|__bfloat16_as_ushort(ha);
                outL[u] = packbf(a-__bfloat162float(ha), bb-__bfloat162float(hb));
            }
        } else {
            size_t base0 = (size_t)(b*TT + r0)*NOUT + co;
            size_t base1 = (size_t)(b*TT + r0 + 8)*NOUT + co;
            float2 ra = *(const float2*)(resid + base0);
            float2 rb = *(const float2*)(resid + base1);
            float2 s0; s0.x = fmaxf(v0 + ra.x, 0.f); s0.y = fmaxf(v1 + ra.y, 0.f);
            float2 s1; s1.x = fmaxf(v2 + rb.x, 0.f); s1.y = fmaxf(v3 + rb.y, 0.f);
            *(float2*)(outF + base0) = s0;
            *(float2*)(outF + base1) = s1;
        }
    }
}

// ---------------------------------------------------------------------------
extern "C" void kernel_launch(void* const* d_in, const int* in_sizes, int n_in,
                              void* d_out, int out_size)
{
    const float* x       = (const float*)d_in[0];
    const float* qkv_w   = (const float*)d_in[1];
    const float* qkv_b   = (const float*)d_in[2];
    const float* scale   = (const float*)d_in[3];
    const float* conv_w1 = (const float*)d_in[4];
    const float* conv_b1 = (const float*)d_in[5];
    const float* conv_w2 = (const float*)d_in[6];
    const float* conv_b2 = (const float*)d_in[7];
    const float* down_w  = (const float*)d_in[8];
    float* out = (float*)d_out;

    const int SM1 = 2*130*128 + 2*8192;          // 49664
    const int SM2 = 2*130*256 + 2*2*8192;        // 99328

    cudaFuncSetAttribute(projm_kernel, cudaFuncAttributeMaxDynamicSharedMemorySize, PROJM_SMEM);
    cudaFuncSetAttribute(attn7_kernel, cudaFuncAttributeMaxDynamicSharedMemorySize, ATTN7_SMEM);
    cudaFuncSetAttribute((const void*)convt_kernel<128,1,true>,
                         cudaFuncAttributeMaxDynamicSharedMemorySize, SM1);
    cudaFuncSetAttribute((const void*)convt_kernel<256,2,false>,
                         cudaFuncAttributeMaxDynamicSharedMemorySize, SM2);

    uint4 *aH, *aL, *hH, *hL, *w1H, *w1L, *w2H, *w2L, *pwH, *pwL;
    float *xdw;
    cudaGetSymbolAddress((void**)&aH,  g_AH4);
    cudaGetSymbolAddress((void**)&aL,  g_AL4);
    cudaGetSymbolAddress((void**)&hH,  g_HH4);
    cudaGetSymbolAddress((void**)&hL,  g_HL4);
    cudaGetSymbolAddress((void**)&w1H, g_W1H4);
    cudaGetSymbolAddress((void**)&w1L, g_W1L4);
    cudaGetSymbolAddress((void**)&w2H, g_W2H4);
    cudaGetSymbolAddress((void**)&w2L, g_W2L4);
    cudaGetSymbolAddress((void**)&pwH, g_PWH4);
    cudaGetSymbolAddress((void**)&pwL, g_PWL4);
    cudaGetSymbolAddress((void**)&xdw, g_XDW);

    prep_w_kernel <<<48, 256>>>(conv_w1, 64,  (uint32_t*)w1H, (uint32_t*)w1L);
    prep_w_kernel <<<96, 256>>>(conv_w2, 128, (uint32_t*)w2H, (uint32_t*)w2L);
    prep_pw_kernel<<<60, 256>>>(qkv_w, down_w, (uint32_t*)pwH, (uint32_t*)pwL);
    projm_kernel<<<dim3(BT/64, 5), 256, PROJM_SMEM>>>(x, qkv_b, scale);
    attn7_kernel<<<dim3(TT/128, BB), 256, ATTN7_SMEM>>>();
    convt_kernel<128,1,true ><<<dim3(TT/128, BB, 2), 256, SM1>>>(
        aH, aL, (uint32_t*)w1H, (uint32_t*)w1L, conv_b1, nullptr, nullptr,
        (uint32_t*)hH, (uint32_t*)hL);
    convt_kernel<256,2,false><<<dim3(TT/128, BB, 2), 256, SM2>>>(
        hH, hL, (uint32_t*)w2H, (uint32_t*)w2L, conv_b2, xdw, out,
        nullptr, nullptr);
}

// round 14
// speedup vs baseline: 1.4269x; 1.0724x over previous
#include <cuda_runtime.h>
#include <cuda_bf16.h>
#include <cstdint>

#define BB   16
#define TT   2048
#define NIN  96
#define NOUT 128
#define DD   64
#define BT   (BB*TT)

// ---- global scratch (pre-split bf16 hi/lo, swizzled 128B/256B rows) ----
__device__ uint4 g_QH4[BT*8]; __device__ uint4 g_QL4[BT*8];
__device__ uint4 g_KH4[BT*8]; __device__ uint4 g_KL4[BT*8];
__device__ uint4 g_VH4[BT*8]; __device__ uint4 g_VL4[BT*8];
__device__ uint4 g_AH4[BT*8]; __device__ uint4 g_AL4[BT*8];   // attn out
__device__ uint4 g_HH4[BT*16]; __device__ uint4 g_HL4[BT*16]; // conv1 out (256B rows)
__device__ float g_XDW[BT*NOUT];
__device__ uint4 g_W1H4[3*2*512];   __device__ uint4 g_W1L4[3*2*512];
__device__ uint4 g_W2H4[3*2*2*512]; __device__ uint4 g_W2L4[3*2*2*512];
__device__ uint4 g_PWH4[5*768];     __device__ uint4 g_PWL4[5*768];   // proj weights

// ===================== helpers =====================
__device__ __forceinline__ uint32_t smem_u32(const void* p){
    uint32_t a;
    asm("{ .reg .u64 t; cvta.to.shared.u64 t, %1; cvt.u32.u64 %0, t; }" : "=r"(a) : "l"(p));
    return a;
}
#define LDSM4(R, A) \
    asm volatile("ldmatrix.sync.aligned.m8n8.x4.shared.b16 {%0,%1,%2,%3}, [%4];" \
        : "=r"((R)[0]),"=r"((R)[1]),"=r"((R)[2]),"=r"((R)[3]) : "r"(A))
#define LDSM4T(R, A) \
    asm volatile("ldmatrix.sync.aligned.m8n8.x4.trans.shared.b16 {%0,%1,%2,%3}, [%4];" \
        : "=r"((R)[0]),"=r"((R)[1]),"=r"((R)[2]),"=r"((R)[3]) : "r"(A))
#define CPA(dst, src) \
    asm volatile("cp.async.cg.shared.global [%0], [%1], 16;" :: "r"(dst), "l"(src))
#define CPC() asm volatile("cp.async.commit_group;")
#define CPW(n) asm volatile("cp.async.wait_group %0;" :: "n"(n))

__device__ __forceinline__ void mma16816(float* c, const uint32_t* a, uint32_t b0, uint32_t b1){
    asm volatile(
        "mma.sync.aligned.m16n8k16.row.col.f32.bf16.bf16.f32 "
        "{%0,%1,%2,%3},{%4,%5,%6,%7},{%8,%9},{%0,%1,%2,%3};"
        : "+f"(c[0]),"+f"(c[1]),"+f"(c[2]),"+f"(c[3])
        : "r"(a[0]),"r"(a[1]),"r"(a[2]),"r"(a[3]),"r"(b0),"r"(b1));
}
__device__ __forceinline__ uint32_t packbf(float lo, float hi){
    uint16_t l = __bfloat16_as_ushort(__float2bfloat16(lo));
    uint16_t h = __bfloat16_as_ushort(__float2bfloat16(hi));
    return ((uint32_t)h << 16) | (uint32_t)l;
}
__device__ __forceinline__ uint32_t cvt2(float hi, float lo){
    uint32_t r;
    asm("cvt.rn.bf16x2.f32 %0, %1, %2;" : "=r"(r) : "f"(hi), "f"(lo));
    return r;
}
__device__ __forceinline__ uint32_t swz(int r, int ch){
    return (uint32_t)(r*128 + ((ch ^ (r & 7)) << 4));
}
// write a hi/lo split pair (cols cl, cl+1, cl even) into 128B-row global arrays
__device__ __forceinline__ void wr_pair64(uint32_t* H, uint32_t* L, int row, int cl,
                                          float a, float bvv){
    int byte = cl*2;
    int u = row*32 + (((byte>>4) ^ (row&7))<<2) + ((byte&15)>>2);
    __nv_bfloat16 ha=__float2bfloat16(a), hb=__float2bfloat16(bvv);
    H[u] = ((uint32_t)__bfloat16_as_ushort(hb)<<16)|__bfloat16_as_ushort(ha);
    L[u] = packbf(a-__bfloat162float(ha), bvv-__bfloat162float(hb));
}

// ===================== conv weight prep =====================
__global__ void prep_w_kernel(const float* __restrict__ w, int Cin,
                              uint32_t* __restrict__ wH, uint32_t* __restrict__ wL)
{
    int nh = Cin >> 6;
    int total = 3*Cin*64;   // co-pairs
    for (int idx = blockIdx.x*blockDim.x + threadIdx.x; idx < total;
         idx += gridDim.x*blockDim.x) {
        int k = idx/(Cin*64); int rem = idx - k*Cin*64;
        int ci = rem >> 6, cop = rem & 63;
        float2 v = *(const float2*)(w + (size_t)(k*Cin+ci)*NOUT + cop*2);
        int hci = ci>>6, cil = ci&63, hco = cop>>5, copl = cop&31;
        int tidx = (k*nh + hci)*2 + hco;
        int u = tidx*2048 + cil*32 + (((copl>>2) ^ (cil&7))<<2) + (copl&3);
        __nv_bfloat16 hx=__float2bfloat16(v.x), hy=__float2bfloat16(v.y);
        wH[u] = ((uint32_t)__bfloat16_as_ushort(hy)<<16)|__bfloat16_as_ushort(hx);
        wL[u] = packbf(v.x-__bfloat162float(hx), v.y-__bfloat162float(hy));
    }
}

// ===================== proj weight prep: [96, 192|128] -> 5 z-tiles ========
__global__ void prep_pw_kernel(const float* __restrict__ qkv_w,
                               const float* __restrict__ down_w,
                               uint32_t* __restrict__ pH, uint32_t* __restrict__ pL)
{
    int total = 96*160;   // (ci, co-pair)
    for (int idx = blockIdx.x*blockDim.x + threadIdx.x; idx < total;
         idx += gridDim.x*blockDim.x) {
        int ci = idx/160, cop = idx - ci*160;
        int z = cop >> 5, copl = cop & 31;
        int col = cop*2;
        float2 v = (z < 3) ? *(const float2*)(qkv_w + ci*192 + col)
                           : *(const float2*)(down_w + ci*128 + (col - 192));
        int u = z*3072 + ci*32 + (((copl>>2) ^ (ci&7))<<2) + (copl&3);
        __nv_bfloat16 hx=__float2bfloat16(v.x), hy=__float2bfloat16(v.y);
        pH[u] = ((uint32_t)__bfloat16_as_ushort(hy)<<16)|__bfloat16_as_ushort(hx);
        pL[u] = packbf(v.x-__bfloat162float(hx), v.y-__bfloat162float(hy));
    }
}

// ===================== proj as 3-term bf16 mma GEMM (M=64 tiles) ===========
#define PM_XH 0
#define PM_XL 16384
#define PM_WH 32768
#define PM_WL 45056
#define PROJM_SMEM 57344
__global__ __launch_bounds__(256) void projm_kernel(
    const float* __restrict__ x, const float* __restrict__ qkv_b,
    const float* __restrict__ scale)
{
    extern __shared__ __align__(16) char smp[];
    const uint32_t sb = smem_u32(smp);
    const int row0 = blockIdx.x * 64;
    const int z    = blockIdx.y;
    const int tid  = threadIdx.x, wrp = tid >> 5, lane = tid & 31;
    const int mw   = wrp & 3, nh = wrp >> 2;

    {
        const uint4* srcH = (const uint4*)((const uint32_t*)g_PWH4 + z*3072);
        const uint4* srcL = (const uint4*)((const uint32_t*)g_PWL4 + z*3072);
        #pragma unroll
        for (int i = tid; i < 1536; i += 256) {
            int sel = (i >= 768); int j = sel ? i - 768 : i;
            CPA(sb + (sel ? PM_WL : PM_WH) + j*16, (sel ? srcL : srcH) + j);
        }
        CPC();
    }

    {
        float2 vals[12];
        #pragma unroll
        for (int j = 0; j < 12; j++) {
            int i = tid + j*256;
            int r = i/48, p = i - r*48;
            vals[j] = *(const float2*)(x + (size_t)(row0 + r)*NIN + p*2);
        }
        #pragma unroll
        for (int j = 0; j < 12; j++) {
            int i = tid + j*256;
            int r = i/48, p = i - r*48;
            int c = p >> 2;
            int pos = (c & 8) | ((c ^ (r & 7)) & 7);
            uint32_t off = (uint32_t)(r*256 + pos*16 + (p & 3)*4);
            uint32_t h = cvt2(vals[j].y, vals[j].x);
            *(uint32_t*)(smp + PM_XH + off) = h;
            *(uint32_t*)(smp + PM_XL + off) = cvt2(vals[j].y - __uint_as_float(h & 0xFFFF0000u),
                                                   vals[j].x - __uint_as_float(h << 16));
        }
    }
    CPW(0);
    __syncthreads();

    float o[4][4];
    #pragma unroll
    for (int m = 0; m < 4; m++) { o[m][0]=o[m][1]=o[m][2]=o[m][3]=0.f; }
    const int laneR = (lane & 7) + ((lane >> 3) & 1)*8;
    const int chS   = lane >> 4;

    #pragma unroll
    for (int ks = 0; ks < 6; ks++) {
        int ar = 16*mw + laneR;
        int c  = 2*ks + chS;
        uint32_t aoff = (uint32_t)(ar*256 + (((c & 8) | ((c ^ (ar & 7)) & 7)) << 4));
        uint32_t ah[4], al[4];
        LDSM4(ah, sb + PM_XH + aoff);
        LDSM4(al, sb + PM_XL + aoff);
        #pragma unroll
        for (int g = 0; g < 2; g++) {
            int br = ks*16 + laneR;
            int cch = nh*4 + 2*g + chS;
            uint32_t boff = (uint32_t)(br*128 + ((cch ^ (br & 7)) << 4));
            uint32_t bh[4], bl[4];
            LDSM4T(bh, sb + PM_WH + boff);
            LDSM4T(bl, sb + PM_WL + boff);
            mma16816(o[2*g],   ah, bh[0], bh[1]);
            mma16816(o[2*g],   al, bh[0], bh[1]);
            mma16816(o[2*g],   ah, bl[0], bl[1]);
            mma16816(o[2*g+1], ah, bh[2], bh[3]);
            mma16816(o[2*g+1], al, bh[2], bh[3]);
            mma16816(o[2*g+1], ah, bl[2], bl[3]);
        }
    }

    const float sc    = scale[0];
    const float enres = 1.0f + 1.0f/(float)TT;
    uint32_t *H = nullptr, *L = nullptr;
    if      (z == 0) { H = (uint32_t*)g_QH4; L = (uint32_t*)g_QL4; }
    else if (z == 1) { H = (uint32_t*)g_KH4; L = (uint32_t*)g_KL4; }
    else if (z == 2) { H = (uint32_t*)g_VH4; L = (uint32_t*)g_VL4; }

    int r0 = row0 + 16*mw + (lane >> 2);
    #pragma unroll
    for (int m = 0; m < 4; m++) {
        int col = nh*32 + (m >> 1)*16 + (m & 1)*8 + (lane & 3)*2;
        if (z < 3) {
            float b0 = qkv_b[z*64 + col], b1 = qkv_b[z*64 + col + 1];
            float v0 = o[m][0] + b0, v1 = o[m][1] + b1;
            float v2 = o[m][2] + b0, v3 = o[m][3] + b1;
            if (z == 0) { v0*=sc; v1*=sc; v2*=sc; v3*=sc; }
            wr_pair64(H, L, r0,     col, v0, v1);
            wr_pair64(H, L, r0 + 8, col, v2, v3);
        } else {
            int oc = (z - 3)*64 + col;
            float2 s0; s0.x = o[m][0]*enres; s0.y = o[m][1]*enres;
            float2 s1; s1.x = o[m][2]*enres; s1.y = o[m][3]*enres;
            *(float2*)(g_XDW + (size_t)r0*NOUT + oc)       = s0;
            *(float2*)(g_XDW + (size_t)(r0 + 8)*NOUT + oc) = s1;
        }
    }
}

// ===================== attention: 32-row KV tiles, 3-stage pipeline ========
#define T_QH 0
#define T_QL 16384
#define T_KV 32768
#define ATTN7_SMEM 81920

__global__ __launch_bounds__(256, 2) void attn7_kernel()
{
    extern __shared__ __align__(16) char smp[];
    const uint32_t sb = smem_u32(smp);
    const int b    = blockIdx.y;
    const int q0   = blockIdx.x * 128;
    const int tid  = threadIdx.x;
    const int w    = tid >> 5;
    const int lane = tid & 31;
    const int toff = ((blockIdx.x + blockIdx.y) & 7) << 3;

    auto issue_kv = [&](int t, int s){
        const uint4* s0 = g_KH4 + (size_t)(b*TT + t*32)*8;
        const uint4* s1 = g_KL4 + (size_t)(b*TT + t*32)*8;
        const uint4* s2 = g_VH4 + (size_t)(b*TT + t*32)*8;
        const uint4* s3 = g_VL4 + (size_t)(b*TT + t*32)*8;
        uint32_t base = sb + T_KV + s*16384;
        #pragma unroll
        for (int i = tid; i < 1024; i += 256) {
            int m = i >> 8, j = i & 255;
            const uint4* src = (m==0) ? s0 : (m==1) ? s1 : (m==2) ? s2 : s3;
            CPA(base + m*4096 + j*16, src + j);
        }
        CPC();
    };

    {
        const uint4* qh4 = g_QH4 + (size_t)(b*TT + q0)*8;
        const uint4* ql4 = g_QL4 + (size_t)(b*TT + q0)*8;
        for (int i = tid; i < 2048; i += 256) {
            int sel = i >> 10, j = i & 1023;
            CPA(sb + (sel ? T_QL : T_QH) + j*16, (sel ? ql4 : qh4) + j);
        }
        CPC();
    }
    issue_kv(toff, 0);
    issue_kv((toff + 1) & 63, 1);
    CPW(2);
    __syncthreads();

    uint32_t qh[4][4], ql[4][4];
    {
        int rr = 16*w + (lane & 7) + ((lane >> 3) & 1)*8;
        #pragma unroll
        for (int k = 0; k < 4; k++) {
            int ch = 2*k + (lane >> 4);
            LDSM4(qh[k], sb + T_QH + swz(rr, ch));
            LDSM4(ql[k], sb + T_QL + swz(rr, ch));
        }
    }

    float o[8][4];
    #pragma unroll
    for (int n = 0; n < 8; n++) { o[n][0]=o[n][1]=o[n][2]=o[n][3]=0.f; }
    float lacc0 = 0.f, lacc1 = 0.f;

    const int rBk  = (lane & 7) + (lane >> 4)*8;
    const int chBk = (lane >> 3) & 1;
    const int rBv  = (lane & 7) + ((lane >> 3) & 1)*8;
    const int chBv = (lane >> 4);

    int stage = 0;
    for (int t = 0; t < 64; t++) {
        if (t < 63) CPW(1); else CPW(0);
        __syncthreads();
        if (t + 2 < 64) {
            int s2 = stage + 2; if (s2 >= 3) s2 -= 3;
            issue_kv((t + 2 + toff) & 63, s2);
        }
        const uint32_t KH = sb + T_KV + stage*16384;
        const uint32_t KL = KH + 4096, VH = KH + 8192, VL = KH + 12288;

        #pragma unroll
        for (int n2 = 0; n2 < 2; n2++) {
            float c0[4] = {0,0,0,0}, c1[4] = {0,0,0,0};
            int s0 = n2*16;
            #pragma unroll
            for (int k = 0; k < 4; k++) {
                uint32_t off = swz(s0 + rBk, 2*k + chBk);
                uint32_t bh[4], bl[4];
                LDSM4(bh, KH + off);
                LDSM4(bl, KL + off);
                mma16816(c0, qh[k], bh[0], bh[1]);
                mma16816(c0, ql[k], bh[0], bh[1]);
                mma16816(c0, qh[k], bl[0], bl[1]);
                mma16816(c1, qh[k], bh[2], bh[3]);
                mma16816(c1, ql[k], bh[2], bh[3]);
                mma16816(c1, qh[k], bl[2], bl[3]);
            }
            float e0 = __expf(c0[0]), e1 = __expf(c0[1]);
            float e2 = __expf(c0[2]), e3 = __expf(c0[3]);
            float e4 = __expf(c1[0]), e5 = __expf(c1[1]);
            float e6 = __expf(c1[2]), e7 = __expf(c1[3]);
            lacc0 += e0 + e1 + e4 + e5;
            lacc1 += e2 + e3 + e6 + e7;
            uint32_t ph[4], pl[4];
            ph[0] = cvt2(e1, e0);
            ph[1] = cvt2(e3, e2);
            ph[2] = cvt2(e5, e4);
            ph[3] = cvt2(e7, e6);
            pl[0] = cvt2(e1 - __uint_as_float(ph[0] & 0xFFFF0000u),
                         e0 - __uint_as_float(ph[0] << 16));
            pl[1] = cvt2(e3 - __uint_as_float(ph[1] & 0xFFFF0000u),
                         e2 - __uint_as_float(ph[1] << 16));
            pl[2] = cvt2(e5 - __uint_as_float(ph[2] & 0xFFFF0000u),
                         e4 - __uint_as_float(ph[2] << 16));
            pl[3] = cvt2(e7 - __uint_as_float(ph[3] & 0xFFFF0000u),
                         e6 - __uint_as_float(ph[3] << 16));

            #pragma unroll
            for (int dp = 0; dp < 4; dp++) {
                uint32_t off = swz(s0 + rBv, 2*dp + chBv);
                uint32_t bh[4], bl[4];
                LDSM4T(bh, VH + off);
                LDSM4T(bl, VL + off);
                mma16816(o[2*dp],   ph, bh[0], bh[1]);
                mma16816(o[2*dp],   pl, bh[0], bh[1]);
                mma16816(o[2*dp],   ph, bl[0], bl[1]);
                mma16816(o[2*dp+1], ph, bh[2], bh[3]);
                mma16816(o[2*dp+1], pl, bh[2], bh[3]);
                mma16816(o[2*dp+1], ph, bl[2], bl[3]);
            }
        }
        if (++stage == 3) stage = 0;
    }

    lacc0 += __shfl_xor_sync(0xffffffffu, lacc0, 1);
    lacc0 += __shfl_xor_sync(0xffffffffu, lacc0, 2);
    lacc1 += __shfl_xor_sync(0xffffffffu, lacc1, 1);
    lacc1 += __shfl_xor_sync(0xffffffffu, lacc1, 2);
    float inv0 = 1.f / lacc0, inv1 = 1.f / lacc1;

    uint32_t* AH = (uint32_t*)g_AH4;
    uint32_t* AL = (uint32_t*)g_AL4;
    int r0 = b*TT + q0 + 16*w + (lane >> 2);
    int cl = (lane & 3)*2;
    #pragma unroll
    for (int n = 0; n < 8; n++) {
        wr_pair64(AH, AL, r0,     n*8 + cl, o[n][0]*inv0, o[n][1]*inv0);
        wr_pair64(AH, AL, r0 + 8, n*8 + cl, o[n][2]*inv1, o[n][3]*inv1);
    }
}

// ===================== conv1d: 64-row tiles, cp.async, high occupancy ======
// WB = input row bytes (128 or 256); NH = Cin/64; SPLIT: write bf16 out.
// Tile = 64 t-rows x 64 co (z). Halo 66 rows. 4 m-warps x 2 n-halves.
// smem: conv1 33.3KB (6 CTA/SM), conv2 66.6KB (3 CTA/SM).
template<int WB, int NH, bool SPLIT>
__global__ __launch_bounds__(256) void convs_kernel(
    const uint4* __restrict__ inH4, const uint4* __restrict__ inL4,
    const uint32_t* __restrict__ wH, const uint32_t* __restrict__ wL,
    const float* __restrict__ bias,
    const float* __restrict__ resid, float* __restrict__ outF,
    uint32_t* __restrict__ outH, uint32_t* __restrict__ outL)
{
    extern __shared__ __align__(16) char smp[];
    const uint32_t sb = smem_u32(smp);
    const int b = blockIdx.y, t0 = blockIdx.x*64, z = blockIdx.z;
    const int tid = threadIdx.x, wrp = tid >> 5, lane = tid & 31;
    const int mw = wrp & 3, nhw = wrp >> 2;

    const int XH = 0, XL = 66*WB;
    const int W0 = 2*66*WB, WL0 = W0 + NH*8192;

    // ---- X halo tile via cp.async (edge rows zeroed directly) ----
    const int n4 = 66*(WB/16);
    for (int i = tid; i < 2*n4; i += 256) {
        int sel = (i >= n4); int j = sel ? i - n4 : i;
        int r = j/(WB/16), c = j%(WB/16);
        int t = t0 + r - 1;
        uint32_t dst = sb + (sel ? XL : XH) + r*WB + c*16;
        if (t >= 0 && t < TT) CPA(dst, (sel ? inL4 : inH4) + (size_t)(b*TT+t)*(WB/16) + c);
        else *(uint4*)(smp + (sel ? XL : XH) + r*WB + c*16) = make_uint4(0,0,0,0);
    }
    CPC();

    float o[4][4];
    #pragma unroll
    for (int m = 0; m < 4; m++) { o[m][0]=o[m][1]=o[m][2]=o[m][3]=0.f; }
    const int laneR = (lane & 7) + ((lane >> 3) & 1)*8;
    const int chS   = lane >> 4;

    for (int k = 0; k < 3; k++) {
        __syncthreads();   // prior mma done before W overwrite (and X safe at k=0)
        for (int i = tid; i < NH*2*512; i += 256) {
            int sel = (i >= NH*512); int j = sel ? i - NH*512 : i;
            int h = j >> 9, c = j & 511;
            const uint32_t* src = (sel ? wL : wH) + (size_t)((k*NH+h)*2 + z)*2048 + c*4;
            CPA(sb + (sel ? WL0 : W0) + h*8192 + c*16, (const uint4*)src);
        }
        CPC();
        CPW(0);            // X (k=0) + this W slice
        __syncthreads();

        #pragma unroll
        for (int h = 0; h < NH; h++) {
            #pragma unroll
            for (int ks = 0; ks < 4; ks++) {
                int ar = 16*mw + laneR + k;
                // swizzle key = global row & 7 = (ar-1)&7 (halo shift)
                uint32_t aoff = (uint32_t)(ar*WB + h*128 + (((2*ks+chS) ^ ((ar+7)&7))<<4));
                uint32_t ah[4], al[4];
                LDSM4(ah, sb + XH + aoff);
                LDSM4(al, sb + XL + aoff);
                #pragma unroll
                for (int g = 0; g < 2; g++) {
                    int br = ks*16 + laneR;
                    int cch = nhw*4 + 2*g + chS;
                    uint32_t boff = (uint32_t)(h*8192 + br*128 + ((cch ^ (br&7))<<4));
                    uint32_t bh[4], bl[4];
                    LDSM4T(bh, sb + W0  + boff);
                    LDSM4T(bl, sb + WL0 + boff);
                    mma16816(o[2*g],   ah, bh[0], bh[1]);
                    mma16816(o[2*g],   al, bh[0], bh[1]);
                    mma16816(o[2*g],   ah, bl[0], bl[1]);
                    mma16816(o[2*g+1], ah, bh[2], bh[3]);
                    mma16816(o[2*g+1], al, bh[2], bh[3]);
                    mma16816(o[2*g+1], ah, bl[2], bl[3]);
                }
            }
        }
    }

    // ---- epilogue ----
    int r0 = t0 + 16*mw + (lane >> 2);
    #pragma unroll
    for (int m = 0; m < 4; m++) {
        int col = nhw*32 + (m >> 1)*16 + (m & 1)*8 + (lane & 3)*2;
        int co  = z*64 + col;
        float b0 = bias[co], b1 = bias[co + 1];
        float v0 = fmaxf(o[m][0] + b0, 0.f);
        float v1 = fmaxf(o[m][1] + b1, 0.f);
        float v2 = fmaxf(o[m][2] + b0, 0.f);
        float v3 = fmaxf(o[m][3] + b1, 0.f);
        if (SPLIT) {
            #pragma unroll
            for (int rr = 0; rr < 2; rr++) {
                int row = b*TT + r0 + rr*8;
                float a = rr ? v2 : v0, bb = rr ? v3 : v1;
                int ch = co >> 3;
                int chp = (ch & 8) | ((ch ^ (row & 7)) & 7);
                int u = row*64 + (chp << 2) + ((co & 7) >> 1);
                __nv_bfloat16 ha=__float2bfloat16(a), hb=__float2bfloat16(bb);
                outH[u] = ((uint32_t)__bfloat16_as_ushort(hb)<<16)|__bfloat16_as_ushort(ha);
                outL[u] = packbf(a-__bfloat162float(ha), bb-__bfloat162float(hb));
            }
        } else {
            size_t base0 = (size_t)(b*TT + r0)*NOUT + co;
            size_t base1 = (size_t)(b*TT + r0 + 8)*NOUT + co;
            float2 ra = *(const float2*)(resid + base0);
            float2 rb = *(const float2*)(resid + base1);
            float2 s0; s0.x = fmaxf(v0 + ra.x, 0.f); s0.y = fmaxf(v1 + ra.y, 0.f);
            float2 s1; s1.x = fmaxf(v2 + rb.x, 0.f); s1.y = fmaxf(v3 + rb.y, 0.f);
            *(float2*)(outF + base0) = s0;
            *(float2*)(outF + base1) = s1;
        }
    }
}

// ---------------------------------------------------------------------------
extern "C" void kernel_launch(void* const* d_in, const int* in_sizes, int n_in,
                              void* d_out, int out_size)
{
    const float* x       = (const float*)d_in[0];
    const float* qkv_w   = (const float*)d_in[1];
    const float* qkv_b   = (const float*)d_in[2];
    const float* scale   = (const float*)d_in[3];
    const float* conv_w1 = (const float*)d_in[4];
    const float* conv_b1 = (const float*)d_in[5];
    const float* conv_w2 = (const float*)d_in[6];
    const float* conv_b2 = (const float*)d_in[7];
    const float* down_w  = (const float*)d_in[8];
    float* out = (float*)d_out;

    const int SM1 = 2*66*128 + 2*8192;           // 33280 -> 6 CTA/SM
    const int SM2 = 2*66*256 + 2*2*8192;         // 66560 -> 3 CTA/SM

    cudaFuncSetAttribute(projm_kernel, cudaFuncAttributeMaxDynamicSharedMemorySize, PROJM_SMEM);
    cudaFuncSetAttribute(attn7_kernel, cudaFuncAttributeMaxDynamicSharedMemorySize, ATTN7_SMEM);
    cudaFuncSetAttribute((const void*)convs_kernel<128,1,true>,
                         cudaFuncAttributeMaxDynamicSharedMemorySize, SM1);
    cudaFuncSetAttribute((const void*)convs_kernel<256,2,false>,
                         cudaFuncAttributeMaxDynamicSharedMemorySize, SM2);

    uint4 *aH, *aL, *hH, *hL, *w1H, *w1L, *w2H, *w2L, *pwH, *pwL;
    float *xdw;
    cudaGetSymbolAddress((void**)&aH,  g_AH4);
    cudaGetSymbolAddress((void**)&aL,  g_AL4);
    cudaGetSymbolAddress((void**)&hH,  g_HH4);
    cudaGetSymbolAddress((void**)&hL,  g_HL4);
    cudaGetSymbolAddress((void**)&w1H, g_W1H4);
    cudaGetSymbolAddress((void**)&w1L, g_W1L4);
    cudaGetSymbolAddress((void**)&w2H, g_W2H4);
    cudaGetSymbolAddress((void**)&w2L, g_W2L4);
    cudaGetSymbolAddress((void**)&pwH, g_PWH4);
    cudaGetSymbolAddress((void**)&pwL, g_PWL4);
    cudaGetSymbolAddress((void**)&xdw, g_XDW);

    prep_w_kernel <<<48, 256>>>(conv_w1, 64,  (uint32_t*)w1H, (uint32_t*)w1L);
    prep_w_kernel <<<96, 256>>>(conv_w2, 128, (uint32_t*)w2H, (uint32_t*)w2L);
    prep_pw_kernel<<<60, 256>>>(qkv_w, down_w, (uint32_t*)pwH, (uint32_t*)pwL);
    projm_kernel<<<dim3(BT/64, 5), 256, PROJM_SMEM>>>(x, qkv_b, scale);
    attn7_kernel<<<dim3(TT/128, BB), 256, ATTN7_SMEM>>>();
    convs_kernel<128,1,true ><<<dim3(TT/64, BB, 2), 256, SM1>>>(
        aH, aL, (uint32_t*)w1H, (uint32_t*)w1L, conv_b1, nullptr, nullptr,
        (uint32_t*)hH, (uint32_t*)hL);
    convs_kernel<256,2,false><<<dim3(TT/64, BB, 2), 256, SM2>>>(
        hH, hL, (uint32_t*)w2H, (uint32_t*)w2L, conv_b2, xdw, out,
        nullptr, nullptr);
}

// round 15
// speedup vs baseline: 1.4679x; 1.0288x over previous
#include <cuda_runtime.h>
#include <cuda_bf16.h>
#include <cstdint>

#define BB   16
#define TT   2048
#define NIN  96
#define NOUT 128
#define DD   64
#define BT   (BB*TT)

// ---- global scratch (pre-split bf16 hi/lo, swizzled 128B/256B rows) ----
__device__ uint4 g_QH4[BT*8]; __device__ uint4 g_QL4[BT*8];
__device__ uint4 g_KH4[BT*8]; __device__ uint4 g_KL4[BT*8];
__device__ uint4 g_VH4[BT*8]; __device__ uint4 g_VL4[BT*8];
__device__ uint4 g_AH4[BT*8]; __device__ uint4 g_AL4[BT*8];   // attn out
__device__ uint4 g_HH4[BT*16]; __device__ uint4 g_HL4[BT*16]; // conv1 out (256B rows)
__device__ float g_XDW[BT*NOUT];
__device__ uint4 g_W1H4[3*2*512];   __device__ uint4 g_W1L4[3*2*512];
__device__ uint4 g_W2H4[3*2*2*512]; __device__ uint4 g_W2L4[3*2*2*512];
__device__ uint4 g_PWH4[5*768];     __device__ uint4 g_PWL4[5*768];   // proj weights

// ===================== helpers =====================
__device__ __forceinline__ uint32_t smem_u32(const void* p){
    uint32_t a;
    asm("{ .reg .u64 t; cvta.to.shared.u64 t, %1; cvt.u32.u64 %0, t; }" : "=r"(a) : "l"(p));
    return a;
}
#define LDSM4(R, A) \
    asm volatile("ldmatrix.sync.aligned.m8n8.x4.shared.b16 {%0,%1,%2,%3}, [%4];" \
        : "=r"((R)[0]),"=r"((R)[1]),"=r"((R)[2]),"=r"((R)[3]) : "r"(A))
#define LDSM4T(R, A) \
    asm volatile("ldmatrix.sync.aligned.m8n8.x4.trans.shared.b16 {%0,%1,%2,%3}, [%4];" \
        : "=r"((R)[0]),"=r"((R)[1]),"=r"((R)[2]),"=r"((R)[3]) : "r"(A))
#define CPA(dst, src) \
    asm volatile("cp.async.cg.shared.global [%0], [%1], 16;" :: "r"(dst), "l"(src))
#define CPC() asm volatile("cp.async.commit_group;")
#define CPW(n) asm volatile("cp.async.wait_group %0;" :: "n"(n))

__device__ __forceinline__ void mma16816(float* c, const uint32_t* a, uint32_t b0, uint32_t b1){
    asm volatile(
        "mma.sync.aligned.m16n8k16.row.col.f32.bf16.bf16.f32 "
        "{%0,%1,%2,%3},{%4,%5,%6,%7},{%8,%9},{%0,%1,%2,%3};"
        : "+f"(c[0]),"+f"(c[1]),"+f"(c[2]),"+f"(c[3])
        : "r"(a[0]),"r"(a[1]),"r"(a[2]),"r"(a[3]),"r"(b0),"r"(b1));
}
__device__ __forceinline__ uint32_t packbf(float lo, float hi){
    uint16_t l = __bfloat16_as_ushort(__float2bfloat16(lo));
    uint16_t h = __bfloat16_as_ushort(__float2bfloat16(hi));
    return ((uint32_t)h << 16) | (uint32_t)l;
}
__device__ __forceinline__ uint32_t cvt2(float hi, float lo){
    uint32_t r;
    asm("cvt.rn.bf16x2.f32 %0, %1, %2;" : "=r"(r) : "f"(hi), "f"(lo));
    return r;
}
__device__ __forceinline__ uint32_t swz(int r, int ch){
    return (uint32_t)(r*128 + ((ch ^ (r & 7)) << 4));
}
// write a hi/lo split pair (cols cl, cl+1, cl even) into 128B-row global arrays
__device__ __forceinline__ void wr_pair64(uint32_t* H, uint32_t* L, int row, int cl,
                                          float a, float bvv){
    int byte = cl*2;
    int u = row*32 + (((byte>>4) ^ (row&7))<<2) + ((byte&15)>>2);
    __nv_bfloat16 ha=__float2bfloat16(a), hb=__float2bfloat16(bvv);
    H[u] = ((uint32_t)__bfloat16_as_ushort(hb)<<16)|__bfloat16_as_ushort(ha);
    L[u] = packbf(a-__bfloat162float(ha), bvv-__bfloat162float(hb));
}

// ===================== merged weight prep =====================
__device__ __forceinline__ void prep_conv_item(const float* w, int Cin, int idx,
                                               uint32_t* wH, uint32_t* wL){
    int nh = Cin >> 6;
    int k = idx/(Cin*64); int rem = idx - k*Cin*64;
    int ci = rem >> 6, cop = rem & 63;
    float2 v = *(const float2*)(w + (size_t)(k*Cin+ci)*NOUT + cop*2);
    int hci = ci>>6, cil = ci&63, hco = cop>>5, copl = cop&31;
    int tidx = (k*nh + hci)*2 + hco;
    int u = tidx*2048 + cil*32 + (((copl>>2) ^ (cil&7))<<2) + (copl&3);
    __nv_bfloat16 hx=__float2bfloat16(v.x), hy=__float2bfloat16(v.y);
    wH[u] = ((uint32_t)__bfloat16_as_ushort(hy)<<16)|__bfloat16_as_ushort(hx);
    wL[u] = packbf(v.x-__bfloat162float(hx), v.y-__bfloat162float(hy));
}
__global__ void prep_all_kernel(
    const float* __restrict__ w1, const float* __restrict__ w2,
    const float* __restrict__ qkv_w, const float* __restrict__ down_w,
    uint32_t* __restrict__ w1H, uint32_t* __restrict__ w1L,
    uint32_t* __restrict__ w2H, uint32_t* __restrict__ w2L,
    uint32_t* __restrict__ pH,  uint32_t* __restrict__ pL)
{
    const int N1 = 3*64*64;        // 12288
    const int N2 = 3*128*64;       // 24576
    const int NP = 96*160;         // 15360
    for (int idx = blockIdx.x*blockDim.x + threadIdx.x; idx < N1 + N2 + NP;
         idx += gridDim.x*blockDim.x) {
        if (idx < N1) {
            prep_conv_item(w1, 64, idx, w1H, w1L);
        } else if (idx < N1 + N2) {
            prep_conv_item(w2, 128, idx - N1, w2H, w2L);
        } else {
            int j = idx - N1 - N2;
            int ci = j/160, cop = j - ci*160;
            int z = cop >> 5, copl = cop & 31;
            int col = cop*2;
            float2 v = (z < 3) ? *(const float2*)(qkv_w + ci*192 + col)
                               : *(const float2*)(down_w + ci*128 + (col - 192));
            int u = z*3072 + ci*32 + (((copl>>2) ^ (ci&7))<<2) + (copl&3);
            __nv_bfloat16 hx=__float2bfloat16(v.x), hy=__float2bfloat16(v.y);
            pH[u] = ((uint32_t)__bfloat16_as_ushort(hy)<<16)|__bfloat16_as_ushort(hx);
            pL[u] = packbf(v.x-__bfloat162float(hx), v.y-__bfloat162float(hy));
        }
    }
}

// ===================== proj: resident X, z-loop, double-buffered W =========
// CTA = 64 rows x all 320 cols (5 z of 64). X loaded/split once (32KB).
// W tiles (24KB each) double-buffered via cp.async. 80KB -> 2 CTAs/SM.
#define P2_XH 0
#define P2_XL 16384
#define P2_W0 32768          // stage s at P2_W0 + s*24576; WL = +12288
#define PROJ2_SMEM 81920
__global__ __launch_bounds__(256, 2) void projm2_kernel(
    const float* __restrict__ x, const float* __restrict__ qkv_b,
    const float* __restrict__ scale)
{
    extern __shared__ __align__(16) char smp[];
    const uint32_t sb = smem_u32(smp);
    const int row0 = blockIdx.x * 64;
    const int tid  = threadIdx.x, wrp = tid >> 5, lane = tid & 31;
    const int mw   = wrp & 3, nh = wrp >> 2;

    auto issue_w = [&](int z, int s){
        const uint4* srcH = (const uint4*)((const uint32_t*)g_PWH4 + z*3072);
        const uint4* srcL = (const uint4*)((const uint32_t*)g_PWL4 + z*3072);
        uint32_t base = sb + P2_W0 + s*24576;
        #pragma unroll
        for (int i = tid; i < 1536; i += 256) {
            int sel = (i >= 768); int j = sel ? i - 768 : i;
            CPA(base + sel*12288 + j*16, (sel ? srcL : srcH) + j);
        }
        CPC();
    };

    issue_w(0, 0);

    // ---- X tile [64][96] -> hi/lo bf16, 256B rows, half-swizzled (once) ----
    {
        float2 vals[12];
        #pragma unroll
        for (int j = 0; j < 12; j++) {
            int i = tid + j*256;
            int r = i/48, p = i - r*48;
            vals[j] = *(const float2*)(x + (size_t)(row0 + r)*NIN + p*2);
        }
        #pragma unroll
        for (int j = 0; j < 12; j++) {
            int i = tid + j*256;
            int r = i/48, p = i - r*48;
            int c = p >> 2;
            int pos = (c & 8) | ((c ^ (r & 7)) & 7);
            uint32_t off = (uint32_t)(r*256 + pos*16 + (p & 3)*4);
            uint32_t h = cvt2(vals[j].y, vals[j].x);
            *(uint32_t*)(smp + P2_XH + off) = h;
            *(uint32_t*)(smp + P2_XL + off) = cvt2(vals[j].y - __uint_as_float(h & 0xFFFF0000u),
                                                   vals[j].x - __uint_as_float(h << 16));
        }
    }

    const float sc    = scale[0];
    const float enres = 1.0f + 1.0f/(float)TT;
    const int laneR = (lane & 7) + ((lane >> 3) & 1)*8;
    const int chS   = lane >> 4;
    const int r0    = row0 + 16*mw + (lane >> 2);

    for (int z = 0; z < 5; z++) {
        __syncthreads();                 // stage (z+1)&1 free (z-1 compute done)
        if (z < 4) issue_w(z + 1, (z + 1) & 1);
        if (z < 4) CPW(1); else CPW(0);  // W(z) arrived
        __syncthreads();                 // visibility

        const uint32_t WH = sb + P2_W0 + (z & 1)*24576;
        const uint32_t WL = WH + 12288;

        float o[4][4];
        #pragma unroll
        for (int m = 0; m < 4; m++) { o[m][0]=o[m][1]=o[m][2]=o[m][3]=0.f; }

        #pragma unroll
        for (int ks = 0; ks < 6; ks++) {
            int ar = 16*mw + laneR;
            int c  = 2*ks + chS;
            uint32_t aoff = (uint32_t)(ar*256 + (((c & 8) | ((c ^ (ar & 7)) & 7)) << 4));
            uint32_t ah[4], al[4];
            LDSM4(ah, sb + P2_XH + aoff);
            LDSM4(al, sb + P2_XL + aoff);
            #pragma unroll
            for (int g = 0; g < 2; g++) {
                int br = ks*16 + laneR;
                int cch = nh*4 + 2*g + chS;
                uint32_t boff = (uint32_t)(br*128 + ((cch ^ (br & 7)) << 4));
                uint32_t bh[4], bl[4];
                LDSM4T(bh, WH + boff);
                LDSM4T(bl, WL + boff);
                mma16816(o[2*g],   ah, bh[0], bh[1]);
                mma16816(o[2*g],   al, bh[0], bh[1]);
                mma16816(o[2*g],   ah, bl[0], bl[1]);
                mma16816(o[2*g+1], ah, bh[2], bh[3]);
                mma16816(o[2*g+1], al, bh[2], bh[3]);
                mma16816(o[2*g+1], ah, bl[2], bl[3]);
            }
        }

        // ---- epilogue for this z ----
        uint32_t *H = nullptr, *L = nullptr;
        if      (z == 0) { H = (uint32_t*)g_QH4; L = (uint32_t*)g_QL4; }
        else if (z == 1) { H = (uint32_t*)g_KH4; L = (uint32_t*)g_KL4; }
        else if (z == 2) { H = (uint32_t*)g_VH4; L = (uint32_t*)g_VL4; }

        #pragma unroll
        for (int m = 0; m < 4; m++) {
            int col = nh*32 + (m >> 1)*16 + (m & 1)*8 + (lane & 3)*2;
            if (z < 3) {
                float b0 = qkv_b[z*64 + col], b1 = qkv_b[z*64 + col + 1];
                float v0 = o[m][0] + b0, v1 = o[m][1] + b1;
                float v2 = o[m][2] + b0, v3 = o[m][3] + b1;
                if (z == 0) { v0*=sc; v1*=sc; v2*=sc; v3*=sc; }
                wr_pair64(H, L, r0,     col, v0, v1);
                wr_pair64(H, L, r0 + 8, col, v2, v3);
            } else {
                int oc = (z - 3)*64 + col;
                float2 s0; s0.x = o[m][0]*enres; s0.y = o[m][1]*enres;
                float2 s1; s1.x = o[m][2]*enres; s1.y = o[m][3]*enres;
                *(float2*)(g_XDW + (size_t)r0*NOUT + oc)       = s0;
                *(float2*)(g_XDW + (size_t)(r0 + 8)*NOUT + oc) = s1;
            }
        }
    }
}

// ===================== attention: 32-row KV tiles, 3-stage pipeline ========
#define T_QH 0
#define T_QL 16384
#define T_KV 32768
#define ATTN7_SMEM 81920

__global__ __launch_bounds__(256, 2) void attn7_kernel()
{
    extern __shared__ __align__(16) char smp[];
    const uint32_t sb = smem_u32(smp);
    const int b    = blockIdx.y;
    const int q0   = blockIdx.x * 128;
    const int tid  = threadIdx.x;
    const int w    = tid >> 5;
    const int lane = tid & 31;
    const int toff = ((blockIdx.x + blockIdx.y) & 7) << 3;

    auto issue_kv = [&](int t, int s){
        const uint4* s0 = g_KH4 + (size_t)(b*TT + t*32)*8;
        const uint4* s1 = g_KL4 + (size_t)(b*TT + t*32)*8;
        const uint4* s2 = g_VH4 + (size_t)(b*TT + t*32)*8;
        const uint4* s3 = g_VL4 + (size_t)(b*TT + t*32)*8;
        uint32_t base = sb + T_KV + s*16384;
        #pragma unroll
        for (int i = tid; i < 1024; i += 256) {
            int m = i >> 8, j = i & 255;
            const uint4* src = (m==0) ? s0 : (m==1) ? s1 : (m==2) ? s2 : s3;
            CPA(base + m*4096 + j*16, src + j);
        }
        CPC();
    };

    {
        const uint4* qh4 = g_QH4 + (size_t)(b*TT + q0)*8;
        const uint4* ql4 = g_QL4 + (size_t)(b*TT + q0)*8;
        for (int i = tid; i < 2048; i += 256) {
            int sel = i >> 10, j = i & 1023;
            CPA(sb + (sel ? T_QL : T_QH) + j*16, (sel ? ql4 : qh4) + j);
        }
        CPC();
    }
    issue_kv(toff, 0);
    issue_kv((toff + 1) & 63, 1);
    CPW(2);
    __syncthreads();

    uint32_t qh[4][4], ql[4][4];
    {
        int rr = 16*w + (lane & 7) + ((lane >> 3) & 1)*8;
        #pragma unroll
        for (int k = 0; k < 4; k++) {
            int ch = 2*k + (lane >> 4);
            LDSM4(qh[k], sb + T_QH + swz(rr, ch));
            LDSM4(ql[k], sb + T_QL + swz(rr, ch));
        }
    }

    float o[8][4];
    #pragma unroll
    for (int n = 0; n < 8; n++) { o[n][0]=o[n][1]=o[n][2]=o[n][3]=0.f; }
    float lacc0 = 0.f, lacc1 = 0.f;

    const int rBk  = (lane & 7) + (lane >> 4)*8;
    const int chBk = (lane >> 3) & 1;
    const int rBv  = (lane & 7) + ((lane >> 3) & 1)*8;
    const int chBv = (lane >> 4);

    int stage = 0;
    for (int t = 0; t < 64; t++) {
        if (t < 63) CPW(1); else CPW(0);
        __syncthreads();
        if (t + 2 < 64) {
            int s2 = stage + 2; if (s2 >= 3) s2 -= 3;
            issue_kv((t + 2 + toff) & 63, s2);
        }
        const uint32_t KH = sb + T_KV + stage*16384;
        const uint32_t KL = KH + 4096, VH = KH + 8192, VL = KH + 12288;

        #pragma unroll
        for (int n2 = 0; n2 < 2; n2++) {
            float c0[4] = {0,0,0,0}, c1[4] = {0,0,0,0};
            int s0 = n2*16;
            #pragma unroll
            for (int k = 0; k < 4; k++) {
                uint32_t off = swz(s0 + rBk, 2*k + chBk);
                uint32_t bh[4], bl[4];
                LDSM4(bh, KH + off);
                LDSM4(bl, KL + off);
                mma16816(c0, qh[k], bh[0], bh[1]);
                mma16816(c0, ql[k], bh[0], bh[1]);
                mma16816(c0, qh[k], bl[0], bl[1]);
                mma16816(c1, qh[k], bh[2], bh[3]);
                mma16816(c1, ql[k], bh[2], bh[3]);
                mma16816(c1, qh[k], bl[2], bl[3]);
            }
            float e0 = __expf(c0[0]), e1 = __expf(c0[1]);
            float e2 = __expf(c0[2]), e3 = __expf(c0[3]);
            float e4 = __expf(c1[0]), e5 = __expf(c1[1]);
            float e6 = __expf(c1[2]), e7 = __expf(c1[3]);
            lacc0 += e0 + e1 + e4 + e5;
            lacc1 += e2 + e3 + e6 + e7;
            uint32_t ph[4], pl[4];
            ph[0] = cvt2(e1, e0);
            ph[1] = cvt2(e3, e2);
            ph[2] = cvt2(e5, e4);
            ph[3] = cvt2(e7, e6);
            pl[0] = cvt2(e1 - __uint_as_float(ph[0] & 0xFFFF0000u),
                         e0 - __uint_as_float(ph[0] << 16));
            pl[1] = cvt2(e3 - __uint_as_float(ph[1] & 0xFFFF0000u),
                         e2 - __uint_as_float(ph[1] << 16));
            pl[2] = cvt2(e5 - __uint_as_float(ph[2] & 0xFFFF0000u),
                         e4 - __uint_as_float(ph[2] << 16));
            pl[3] = cvt2(e7 - __uint_as_float(ph[3] & 0xFFFF0000u),
                         e6 - __uint_as_float(ph[3] << 16));

            #pragma unroll
            for (int dp = 0; dp < 4; dp++) {
                uint32_t off = swz(s0 + rBv, 2*dp + chBv);
                uint32_t bh[4], bl[4];
                LDSM4T(bh, VH + off);
                LDSM4T(bl, VL + off);
                mma16816(o[2*dp],   ph, bh[0], bh[1]);
                mma16816(o[2*dp],   pl, bh[0], bh[1]);
                mma16816(o[2*dp],   ph, bl[0], bl[1]);
                mma16816(o[2*dp+1], ph, bh[2], bh[3]);
                mma16816(o[2*dp+1], pl, bh[2], bh[3]);
                mma16816(o[2*dp+1], ph, bl[2], bl[3]);
            }
        }
        if (++stage == 3) stage = 0;
    }

    lacc0 += __shfl_xor_sync(0xffffffffu, lacc0, 1);
    lacc0 += __shfl_xor_sync(0xffffffffu, lacc0, 2);
    lacc1 += __shfl_xor_sync(0xffffffffu, lacc1, 1);
    lacc1 += __shfl_xor_sync(0xffffffffu, lacc1, 2);
    float inv0 = 1.f / lacc0, inv1 = 1.f / lacc1;

    uint32_t* AH = (uint32_t*)g_AH4;
    uint32_t* AL = (uint32_t*)g_AL4;
    int r0 = b*TT + q0 + 16*w + (lane >> 2);
    int cl = (lane & 3)*2;
    #pragma unroll
    for (int n = 0; n < 8; n++) {
        wr_pair64(AH, AL, r0,     n*8 + cl, o[n][0]*inv0, o[n][1]*inv0);
        wr_pair64(AH, AL, r0 + 8, n*8 + cl, o[n][2]*inv1, o[n][3]*inv1);
    }
}

// ===================== conv1d: 64-row tiles, per-(k,h) W slices ============
// WB = input row bytes; NH = Cin/64; SPLIT: write bf16 out.
// smem: X halo 2*66*WB + one W slice 16KB. conv1 33.3KB (6 CTA/SM),
// conv2 50.2KB (4 CTA/SM). Same (k,h) accumulation order as before.
template<int WB, int NH, bool SPLIT>
__global__ __launch_bounds__(256) void convs_kernel(
    const uint4* __restrict__ inH4, const uint4* __restrict__ inL4,
    const uint32_t* __restrict__ wH, const uint32_t* __restrict__ wL,
    const float* __restrict__ bias,
    const float* __restrict__ resid, float* __restrict__ outF,
    uint32_t* __restrict__ outH, uint32_t* __restrict__ outL)
{
    extern __shared__ __align__(16) char smp[];
    const uint32_t sb = smem_u32(smp);
    const int b = blockIdx.y, t0 = blockIdx.x*64, z = blockIdx.z;
    const int tid = threadIdx.x, wrp = tid >> 5, lane = tid & 31;
    const int mw = wrp & 3, nhw = wrp >> 2;

    const int XH = 0, XL = 66*WB;
    const int W0 = 2*66*WB, WL0 = W0 + 8192;

    // ---- X halo tile via cp.async (edge rows zeroed directly) ----
    const int n4 = 66*(WB/16);
    for (int i = tid; i < 2*n4; i += 256) {
        int sel = (i >= n4); int j = sel ? i - n4 : i;
        int r = j/(WB/16), c = j%(WB/16);
        int t = t0 + r - 1;
        uint32_t dst = sb + (sel ? XL : XH) + r*WB + c*16;
        if (t >= 0 && t < TT) CPA(dst, (sel ? inL4 : inH4) + (size_t)(b*TT+t)*(WB/16) + c);
        else *(uint4*)(smp + (sel ? XL : XH) + r*WB + c*16) = make_uint4(0,0,0,0);
    }
    CPC();

    float o[4][4];
    #pragma unroll
    for (int m = 0; m < 4; m++) { o[m][0]=o[m][1]=o[m][2]=o[m][3]=0.f; }
    const int laneR = (lane & 7) + ((lane >> 3) & 1)*8;
    const int chS   = lane >> 4;

    for (int kh = 0; kh < 3*NH; kh++) {
        const int k = kh / NH, h = kh - k*NH;
        __syncthreads();   // prior mma done before W overwrite (X safe at kh=0)
        for (int i = tid; i < 1024; i += 256) {   // one 16KB W slice (k,h)
            int sel = (i >= 512); int j = sel ? i - 512 : i;
            const uint32_t* src = (sel ? wL : wH) + (size_t)((k*NH+h)*2 + z)*2048 + j*4;
            CPA(sb + (sel ? WL0 : W0) + j*16, (const uint4*)src);
        }
        CPC();
        CPW(0);            // X (kh=0) + this W slice
        __syncthreads();

        #pragma unroll
        for (int ks = 0; ks < 4; ks++) {
            int ar = 16*mw + laneR + k;
            // swizzle key = global row & 7 = (ar-1)&7 (halo shift)
            uint32_t aoff = (uint32_t)(ar*WB + h*128 + (((2*ks+chS) ^ ((ar+7)&7))<<4));
            uint32_t ah[4], al[4];
            LDSM4(ah, sb + XH + aoff);
            LDSM4(al, sb + XL + aoff);
            #pragma unroll
            for (int g = 0; g < 2; g++) {
                int br = ks*16 + laneR;
                int cch = nhw*4 + 2*g + chS;
                uint32_t boff = (uint32_t)(br*128 + ((cch ^ (br&7))<<4));
                uint32_t bh[4], bl[4];
                LDSM4T(bh, sb + W0  + boff);
                LDSM4T(bl, sb + WL0 + boff);
                mma16816(o[2*g],   ah, bh[0], bh[1]);
                mma16816(o[2*g],   al, bh[0], bh[1]);
                mma16816(o[2*g],   ah, bl[0], bl[1]);
                mma16816(o[2*g+1], ah, bh[2], bh[3]);
                mma16816(o[2*g+1], al, bh[2], bh[3]);
                mma16816(o[2*g+1], ah, bl[2], bl[3]);
            }
        }
    }

    // ---- epilogue ----
    int r0 = t0 + 16*mw + (lane >> 2);
    #pragma unroll
    for (int m = 0; m < 4; m++) {
        int col = nhw*32 + (m >> 1)*16 + (m & 1)*8 + (lane & 3)*2;
        int co  = z*64 + col;
        float b0 = bias[co], b1 = bias[co + 1];
        float v0 = fmaxf(o[m][0] + b0, 0.f);
        float v1 = fmaxf(o[m][1] + b1, 0.f);
        float v2 = fmaxf(o[m][2] + b0, 0.f);
        float v3 = fmaxf(o[m][3] + b1, 0.f);
        if (SPLIT) {
            #pragma unroll
            for (int rr = 0; rr < 2; rr++) {
                int row = b*TT + r0 + rr*8;
                float a = rr ? v2 : v0, bb = rr ? v3 : v1;
                int ch = co >> 3;
                int chp = (ch & 8) | ((ch ^ (row & 7)) & 7);
                int u = row*64 + (chp << 2) + ((co & 7) >> 1);
                __nv_bfloat16 ha=__float2bfloat16(a), hb=__float2bfloat16(bb);
                outH[u] = ((uint32_t)__bfloat16_as_ushort(hb)<<16)|__bfloat16_as_ushort(ha);
                outL[u] = packbf(a-__bfloat162float(ha), bb-__bfloat162float(hb));
            }
        } else {
            size_t base0 = (size_t)(b*TT + r0)*NOUT + co;
            size_t base1 = (size_t)(b*TT + r0 + 8)*NOUT + co;
            float2 ra = *(const float2*)(resid + base0);
            float2 rb = *(const float2*)(resid + base1);
            float2 s0; s0.x = fmaxf(v0 + ra.x, 0.f); s0.y = fmaxf(v1 + ra.y, 0.f);
            float2 s1; s1.x = fmaxf(v2 + rb.x, 0.f); s1.y = fmaxf(v3 + rb.y, 0.f);
            *(float2*)(outF + base0) = s0;
            *(float2*)(outF + base1) = s1;
        }
    }
}

// ---------------------------------------------------------------------------
extern "C" void kernel_launch(void* const* d_in, const int* in_sizes, int n_in,
                              void* d_out, int out_size)
{
    const float* x       = (const float*)d_in[0];
    const float* qkv_w   = (const float*)d_in[1];
    const float* qkv_b   = (const float*)d_in[2];
    const float* scale   = (const float*)d_in[3];
    const float* conv_w1 = (const float*)d_in[4];
    const float* conv_b1 = (const float*)d_in[5];
    const float* conv_w2 = (const float*)d_in[6];
    const float* conv_b2 = (const float*)d_in[7];
    const float* down_w  = (const float*)d_in[8];
    float* out = (float*)d_out;

    const int SM1 = 2*66*128 + 16384;            // 33280 -> 6 CTA/SM
    const int SM2 = 2*66*256 + 16384;            // 50176 -> 4 CTA/SM

    cudaFuncSetAttribute(projm2_kernel, cudaFuncAttributeMaxDynamicSharedMemorySize, PROJ2_SMEM);
    cudaFuncSetAttribute(attn7_kernel,  cudaFuncAttributeMaxDynamicSharedMemorySize, ATTN7_SMEM);
    cudaFuncSetAttribute((const void*)convs_kernel<128,1,true>,
                         cudaFuncAttributeMaxDynamicSharedMemorySize, SM1);
    cudaFuncSetAttribute((const void*)convs_kernel<256,2,false>,
                         cudaFuncAttributeMaxDynamicSharedMemorySize, SM2);

    uint4 *aH, *aL, *hH, *hL, *w1H, *w1L, *w2H, *w2L, *pwH, *pwL;
    float *xdw;
    cudaGetSymbolAddress((void**)&aH,  g_AH4);
    cudaGetSymbolAddress((void**)&aL,  g_AL4);
    cudaGetSymbolAddress((void**)&hH,  g_HH4);
    cudaGetSymbolAddress((void**)&hL,  g_HL4);
    cudaGetSymbolAddress((void**)&w1H, g_W1H4);
    cudaGetSymbolAddress((void**)&w1L, g_W1L4);
    cudaGetSymbolAddress((void**)&w2H, g_W2H4);
    cudaGetSymbolAddress((void**)&w2L, g_W2L4);
    cudaGetSymbolAddress((void**)&pwH, g_PWH4);
    cudaGetSymbolAddress((void**)&pwL, g_PWL4);
    cudaGetSymbolAddress((void**)&xdw, g_XDW);

    prep_all_kernel<<<204, 256>>>(conv_w1, conv_w2, qkv_w, down_w,
        (uint32_t*)w1H, (uint32_t*)w1L, (uint32_t*)w2H, (uint32_t*)w2L,
        (uint32_t*)pwH, (uint32_t*)pwL);
    projm2_kernel<<<BT/64, 256, PROJ2_SMEM>>>(x, qkv_b, scale);
    attn7_kernel<<<dim3(TT/128, BB), 256, ATTN7_SMEM>>>();
    convs_kernel<128,1,true ><<<dim3(TT/64, BB, 2), 256, SM1>>>(
        aH, aL, (uint32_t*)w1H, (uint32_t*)w1L, conv_b1, nullptr, nullptr,
        (uint32_t*)hH, (uint32_t*)hL);
    convs_kernel<256,2,false><<<dim3(TT/64, BB, 2), 256, SM2>>>(
        hH, hL, (uint32_t*)w2H, (uint32_t*)w2L, conv_b2, xdw, out,
        nullptr, nullptr);
}

// round 16
// speedup vs baseline: 1.5881x; 1.0819x over previous
#include <cuda_runtime.h>
#include <cuda_bf16.h>
#include <cstdint>

#define BB   16
#define TT   2048
#define NIN  96
#define NOUT 128
#define DD   64
#define BT   (BB*TT)

// ---- global scratch (pre-split bf16 hi/lo, swizzled 128B/256B rows) ----
__device__ uint4 g_QH4[BT*8]; __device__ uint4 g_QL4[BT*8];
__device__ uint4 g_KH4[BT*8]; __device__ uint4 g_KL4[BT*8];
__device__ uint4 g_VH4[BT*8]; __device__ uint4 g_VL4[BT*8];
__device__ uint4 g_AH4[BT*8]; __device__ uint4 g_AL4[BT*8];   // attn out
__device__ uint4 g_HH4[BT*16]; __device__ uint4 g_HL4[BT*16]; // conv1 out (256B rows)
__device__ float g_XDW[BT*NOUT];
__device__ uint4 g_W1H4[3*2*512];   __device__ uint4 g_W1L4[3*2*512];
__device__ uint4 g_W2H4[3*2*2*512]; __device__ uint4 g_W2L4[3*2*2*512];
__device__ uint4 g_PWH4[5*768];     __device__ uint4 g_PWL4[5*768];   // proj weights

// ===================== helpers =====================
__device__ __forceinline__ uint32_t smem_u32(const void* p){
    uint32_t a;
    asm("{ .reg .u64 t; cvta.to.shared.u64 t, %1; cvt.u32.u64 %0, t; }" : "=r"(a) : "l"(p));
    return a;
}
#define LDSM4(R, A) \
    asm volatile("ldmatrix.sync.aligned.m8n8.x4.shared.b16 {%0,%1,%2,%3}, [%4];" \
        : "=r"((R)[0]),"=r"((R)[1]),"=r"((R)[2]),"=r"((R)[3]) : "r"(A))
#define LDSM4T(R, A) \
    asm volatile("ldmatrix.sync.aligned.m8n8.x4.trans.shared.b16 {%0,%1,%2,%3}, [%4];" \
        : "=r"((R)[0]),"=r"((R)[1]),"=r"((R)[2]),"=r"((R)[3]) : "r"(A))
#define CPA(dst, src) \
    asm volatile("cp.async.cg.shared.global [%0], [%1], 16;" :: "r"(dst), "l"(src))
#define CPC() asm volatile("cp.async.commit_group;")
#define CPW(n) asm volatile("cp.async.wait_group %0;" :: "n"(n))

__device__ __forceinline__ void mma16816(float* c, const uint32_t* a, uint32_t b0, uint32_t b1){
    asm volatile(
        "mma.sync.aligned.m16n8k16.row.col.f32.bf16.bf16.f32 "
        "{%0,%1,%2,%3},{%4,%5,%6,%7},{%8,%9},{%0,%1,%2,%3};"
        : "+f"(c[0]),"+f"(c[1]),"+f"(c[2]),"+f"(c[3])
        : "r"(a[0]),"r"(a[1]),"r"(a[2]),"r"(a[3]),"r"(b0),"r"(b1));
}
__device__ __forceinline__ uint32_t packbf(float lo, float hi){
    uint16_t l = __bfloat16_as_ushort(__float2bfloat16(lo));
    uint16_t h = __bfloat16_as_ushort(__float2bfloat16(hi));
    return ((uint32_t)h << 16) | (uint32_t)l;
}
__device__ __forceinline__ uint32_t cvt2(float hi, float lo){
    uint32_t r;
    asm("cvt.rn.bf16x2.f32 %0, %1, %2;" : "=r"(r) : "f"(hi), "f"(lo));
    return r;
}
__device__ __forceinline__ uint32_t swz(int r, int ch){
    return (uint32_t)(r*128 + ((ch ^ (r & 7)) << 4));
}
// write a hi/lo split pair (cols cl, cl+1, cl even) into 128B-row global arrays
__device__ __forceinline__ void wr_pair64(uint32_t* H, uint32_t* L, int row, int cl,
                                          float a, float bvv){
    int byte = cl*2;
    int u = row*32 + (((byte>>4) ^ (row&7))<<2) + ((byte&15)>>2);
    __nv_bfloat16 ha=__float2bfloat16(a), hb=__float2bfloat16(bvv);
    H[u] = ((uint32_t)__bfloat16_as_ushort(hb)<<16)|__bfloat16_as_ushort(ha);
    L[u] = packbf(a-__bfloat162float(ha), bvv-__bfloat162float(hb));
}

// ===================== merged weight prep =====================
__device__ __forceinline__ void prep_conv_item(const float* w, int Cin, int idx,
                                               uint32_t* wH, uint32_t* wL){
    int nh = Cin >> 6;
    int k = idx/(Cin*64); int rem = idx - k*Cin*64;
    int ci = rem >> 6, cop = rem & 63;
    float2 v = *(const float2*)(w + (size_t)(k*Cin+ci)*NOUT + cop*2);
    int hci = ci>>6, cil = ci&63, hco = cop>>5, copl = cop&31;
    int tidx = (k*nh + hci)*2 + hco;
    int u = tidx*2048 + cil*32 + (((copl>>2) ^ (cil&7))<<2) + (copl&3);
    __nv_bfloat16 hx=__float2bfloat16(v.x), hy=__float2bfloat16(v.y);
    wH[u] = ((uint32_t)__bfloat16_as_ushort(hy)<<16)|__bfloat16_as_ushort(hx);
    wL[u] = packbf(v.x-__bfloat162float(hx), v.y-__bfloat162float(hy));
}
__global__ void prep_all_kernel(
    const float* __restrict__ w1, const float* __restrict__ w2,
    const float* __restrict__ qkv_w, const float* __restrict__ down_w,
    uint32_t* __restrict__ w1H, uint32_t* __restrict__ w1L,
    uint32_t* __restrict__ w2H, uint32_t* __restrict__ w2L,
    uint32_t* __restrict__ pH,  uint32_t* __restrict__ pL)
{
    const int N1 = 3*64*64;        // 12288
    const int N2 = 3*128*64;       // 24576
    const int NP = 96*160;         // 15360
    for (int idx = blockIdx.x*blockDim.x + threadIdx.x; idx < N1 + N2 + NP;
         idx += gridDim.x*blockDim.x) {
        if (idx < N1) {
            prep_conv_item(w1, 64, idx, w1H, w1L);
        } else if (idx < N1 + N2) {
            prep_conv_item(w2, 128, idx - N1, w2H, w2L);
        } else {
            int j = idx - N1 - N2;
            int ci = j/160, cop = j - ci*160;
            int z = cop >> 5, copl = cop & 31;
            int col = cop*2;
            float2 v = (z < 3) ? *(const float2*)(qkv_w + ci*192 + col)
                               : *(const float2*)(down_w + ci*128 + (col - 192));
            int u = z*3072 + ci*32 + (((copl>>2) ^ (ci&7))<<2) + (copl&3);
            __nv_bfloat16 hx=__float2bfloat16(v.x), hy=__float2bfloat16(v.y);
            pH[u] = ((uint32_t)__bfloat16_as_ushort(hy)<<16)|__bfloat16_as_ushort(hx);
            pL[u] = packbf(v.x-__bfloat162float(hx), v.y-__bfloat162float(hy));
        }
    }
}

// ===================== proj: resident X, z-loop, double-buffered W =========
#define P2_XH 0
#define P2_XL 16384
#define P2_W0 32768          // stage s at P2_W0 + s*24576; WL = +12288
#define PROJ2_SMEM 81920
__global__ __launch_bounds__(256, 2) void projm2_kernel(
    const float* __restrict__ x, const float* __restrict__ qkv_b,
    const float* __restrict__ scale)
{
    extern __shared__ __align__(16) char smp[];
    const uint32_t sb = smem_u32(smp);
    const int row0 = blockIdx.x * 64;
    const int tid  = threadIdx.x, wrp = tid >> 5, lane = tid & 31;
    const int mw   = wrp & 3, nh = wrp >> 2;

    auto issue_w = [&](int z, int s){
        const uint4* srcH = (const uint4*)((const uint32_t*)g_PWH4 + z*3072);
        const uint4* srcL = (const uint4*)((const uint32_t*)g_PWL4 + z*3072);
        uint32_t base = sb + P2_W0 + s*24576;
        #pragma unroll
        for (int i = tid; i < 1536; i += 256) {
            int sel = (i >= 768); int j = sel ? i - 768 : i;
            CPA(base + sel*12288 + j*16, (sel ? srcL : srcH) + j);
        }
        CPC();
    };

    issue_w(0, 0);

    {
        float2 vals[12];
        #pragma unroll
        for (int j = 0; j < 12; j++) {
            int i = tid + j*256;
            int r = i/48, p = i - r*48;
            vals[j] = *(const float2*)(x + (size_t)(row0 + r)*NIN + p*2);
        }
        #pragma unroll
        for (int j = 0; j < 12; j++) {
            int i = tid + j*256;
            int r = i/48, p = i - r*48;
            int c = p >> 2;
            int pos = (c & 8) | ((c ^ (r & 7)) & 7);
            uint32_t off = (uint32_t)(r*256 + pos*16 + (p & 3)*4);
            uint32_t h = cvt2(vals[j].y, vals[j].x);
            *(uint32_t*)(smp + P2_XH + off) = h;
            *(uint32_t*)(smp + P2_XL + off) = cvt2(vals[j].y - __uint_as_float(h & 0xFFFF0000u),
                                                   vals[j].x - __uint_as_float(h << 16));
        }
    }

    const float sc    = scale[0];
    const float enres = 1.0f + 1.0f/(float)TT;
    const int laneR = (lane & 7) + ((lane >> 3) & 1)*8;
    const int chS   = lane >> 4;
    const int r0    = row0 + 16*mw + (lane >> 2);

    for (int z = 0; z < 5; z++) {
        __syncthreads();
        if (z < 4) issue_w(z + 1, (z + 1) & 1);
        if (z < 4) CPW(1); else CPW(0);
        __syncthreads();

        const uint32_t WH = sb + P2_W0 + (z & 1)*24576;
        const uint32_t WL = WH + 12288;

        float o[4][4];
        #pragma unroll
        for (int m = 0; m < 4; m++) { o[m][0]=o[m][1]=o[m][2]=o[m][3]=0.f; }

        #pragma unroll
        for (int ks = 0; ks < 6; ks++) {
            int ar = 16*mw + laneR;
            int c  = 2*ks + chS;
            uint32_t aoff = (uint32_t)(ar*256 + (((c & 8) | ((c ^ (ar & 7)) & 7)) << 4));
            uint32_t ah[4], al[4];
            LDSM4(ah, sb + P2_XH + aoff);
            LDSM4(al, sb + P2_XL + aoff);
            #pragma unroll
            for (int g = 0; g < 2; g++) {
                int br = ks*16 + laneR;
                int cch = nh*4 + 2*g + chS;
                uint32_t boff = (uint32_t)(br*128 + ((cch ^ (br & 7)) << 4));
                uint32_t bh[4], bl[4];
                LDSM4T(bh, WH + boff);
                LDSM4T(bl, WL + boff);
                mma16816(o[2*g],   ah, bh[0], bh[1]);
                mma16816(o[2*g],   al, bh[0], bh[1]);
                mma16816(o[2*g],   ah, bl[0], bl[1]);
                mma16816(o[2*g+1], ah, bh[2], bh[3]);
                mma16816(o[2*g+1], al, bh[2], bh[3]);
                mma16816(o[2*g+1], ah, bl[2], bl[3]);
            }
        }

        uint32_t *H = nullptr, *L = nullptr;
        if      (z == 0) { H = (uint32_t*)g_QH4; L = (uint32_t*)g_QL4; }
        else if (z == 1) { H = (uint32_t*)g_KH4; L = (uint32_t*)g_KL4; }
        else if (z == 2) { H = (uint32_t*)g_VH4; L = (uint32_t*)g_VL4; }

        #pragma unroll
        for (int m = 0; m < 4; m++) {
            int col = nh*32 + (m >> 1)*16 + (m & 1)*8 + (lane & 3)*2;
            if (z < 3) {
                float b0 = qkv_b[z*64 + col], b1 = qkv_b[z*64 + col + 1];
                float v0 = o[m][0] + b0, v1 = o[m][1] + b1;
                float v2 = o[m][2] + b0, v3 = o[m][3] + b1;
                if (z == 0) { v0*=sc; v1*=sc; v2*=sc; v3*=sc; }
                wr_pair64(H, L, r0,     col, v0, v1);
                wr_pair64(H, L, r0 + 8, col, v2, v3);
            } else {
                int oc = (z - 3)*64 + col;
                float2 s0; s0.x = o[m][0]*enres; s0.y = o[m][1]*enres;
                float2 s1; s1.x = o[m][2]*enres; s1.y = o[m][3]*enres;
                *(float2*)(g_XDW + (size_t)r0*NOUT + oc)       = s0;
                *(float2*)(g_XDW + (size_t)(r0 + 8)*NOUT + oc) = s1;
            }
        }
    }
}

// ===================== attention: 2-term QK^T, KL dropped, 3-stage =========
// S = Qh.Kh + Ql.Kh  (dropped Qh.Kl: error ~2^-9 in S, washes out in the
// 2048-term normalized PV average; rel_err budget 1e-3 >> est 1e-4).
// KV stage = {KH, VH, VL} = 12KB. smem 32K Q + 3*12K = 68.6KB, 2 CTAs/SM.
#define T_QH 0
#define T_QL 16384
#define T_KV 32768
#define ATTN8_SMEM 69632

__global__ __launch_bounds__(256, 2) void attn8_kernel()
{
    extern __shared__ __align__(16) char smp[];
    const uint32_t sb = smem_u32(smp);
    const int b    = blockIdx.y;
    const int q0   = blockIdx.x * 128;
    const int tid  = threadIdx.x;
    const int w    = tid >> 5;
    const int lane = tid & 31;
    const int toff = ((blockIdx.x + blockIdx.y) & 7) << 3;

    auto issue_kv = [&](int t, int s){
        const uint4* s0 = g_KH4 + (size_t)(b*TT + t*32)*8;
        const uint4* s1 = g_VH4 + (size_t)(b*TT + t*32)*8;
        const uint4* s2 = g_VL4 + (size_t)(b*TT + t*32)*8;
        uint32_t base = sb + T_KV + s*12288;
        #pragma unroll
        for (int i = tid; i < 768; i += 256) {
            int m = i >> 8, j = i & 255;
            const uint4* src = (m==0) ? s0 : (m==1) ? s1 : s2;
            CPA(base + m*4096 + j*16, src + j);
        }
        CPC();
    };

    {
        const uint4* qh4 = g_QH4 + (size_t)(b*TT + q0)*8;
        const uint4* ql4 = g_QL4 + (size_t)(b*TT + q0)*8;
        for (int i = tid; i < 2048; i += 256) {
            int sel = i >> 10, j = i & 1023;
            CPA(sb + (sel ? T_QL : T_QH) + j*16, (sel ? ql4 : qh4) + j);
        }
        CPC();
    }
    issue_kv(toff, 0);
    issue_kv((toff + 1) & 63, 1);
    CPW(2);
    __syncthreads();

    uint32_t qh[4][4], ql[4][4];
    {
        int rr = 16*w + (lane & 7) + ((lane >> 3) & 1)*8;
        #pragma unroll
        for (int k = 0; k < 4; k++) {
            int ch = 2*k + (lane >> 4);
            LDSM4(qh[k], sb + T_QH + swz(rr, ch));
            LDSM4(ql[k], sb + T_QL + swz(rr, ch));
        }
    }

    float o[8][4];
    #pragma unroll
    for (int n = 0; n < 8; n++) { o[n][0]=o[n][1]=o[n][2]=o[n][3]=0.f; }
    float lacc0 = 0.f, lacc1 = 0.f;

    const int rBk  = (lane & 7) + (lane >> 4)*8;
    const int chBk = (lane >> 3) & 1;
    const int rBv  = (lane & 7) + ((lane >> 3) & 1)*8;
    const int chBv = (lane >> 4);

    int stage = 0;
    for (int t = 0; t < 64; t++) {
        if (t < 63) CPW(1); else CPW(0);
        __syncthreads();
        if (t + 2 < 64) {
            int s2 = stage + 2; if (s2 >= 3) s2 -= 3;
            issue_kv((t + 2 + toff) & 63, s2);
        }
        const uint32_t KH = sb + T_KV + stage*12288;
        const uint32_t VH = KH + 4096, VL = KH + 8192;

        #pragma unroll
        for (int n2 = 0; n2 < 2; n2++) {
            // ---- S block: 2-term (K un-split) ----
            float c0[4] = {0,0,0,0}, c1[4] = {0,0,0,0};
            int s0 = n2*16;
            #pragma unroll
            for (int k = 0; k < 4; k++) {
                uint32_t off = swz(s0 + rBk, 2*k + chBk);
                uint32_t bh[4];
                LDSM4(bh, KH + off);
                mma16816(c0, qh[k], bh[0], bh[1]);
                mma16816(c0, ql[k], bh[0], bh[1]);
                mma16816(c1, qh[k], bh[2], bh[3]);
                mma16816(c1, ql[k], bh[2], bh[3]);
            }
            float e0 = __expf(c0[0]), e1 = __expf(c0[1]);
            float e2 = __expf(c0[2]), e3 = __expf(c0[3]);
            float e4 = __expf(c1[0]), e5 = __expf(c1[1]);
            float e6 = __expf(c1[2]), e7 = __expf(c1[3]);
            lacc0 += e0 + e1 + e4 + e5;
            lacc1 += e2 + e3 + e6 + e7;
            uint32_t ph[4], pl[4];
            ph[0] = cvt2(e1, e0);
            ph[1] = cvt2(e3, e2);
            ph[2] = cvt2(e5, e4);
            ph[3] = cvt2(e7, e6);
            pl[0] = cvt2(e1 - __uint_as_float(ph[0] & 0xFFFF0000u),
                         e0 - __uint_as_float(ph[0] << 16));
            pl[1] = cvt2(e3 - __uint_as_float(ph[1] & 0xFFFF0000u),
                         e2 - __uint_as_float(ph[1] << 16));
            pl[2] = cvt2(e5 - __uint_as_float(ph[2] & 0xFFFF0000u),
                         e4 - __uint_as_float(ph[2] << 16));
            pl[3] = cvt2(e7 - __uint_as_float(ph[3] & 0xFFFF0000u),
                         e6 - __uint_as_float(ph[3] << 16));

            // ---- PV: 3-term (unchanged) ----
            #pragma unroll
            for (int dp = 0; dp < 4; dp++) {
                uint32_t off = swz(s0 + rBv, 2*dp + chBv);
                uint32_t bh[4], bl[4];
                LDSM4T(bh, VH + off);
                LDSM4T(bl, VL + off);
                mma16816(o[2*dp],   ph, bh[0], bh[1]);
                mma16816(o[2*dp],   pl, bh[0], bh[1]);
                mma16816(o[2*dp],   ph, bl[0], bl[1]);
                mma16816(o[2*dp+1], ph, bh[2], bh[3]);
                mma16816(o[2*dp+1], pl, bh[2], bh[3]);
                mma16816(o[2*dp+1], ph, bl[2], bl[3]);
            }
        }
        if (++stage == 3) stage = 0;
    }

    lacc0 += __shfl_xor_sync(0xffffffffu, lacc0, 1);
    lacc0 += __shfl_xor_sync(0xffffffffu, lacc0, 2);
    lacc1 += __shfl_xor_sync(0xffffffffu, lacc1, 1);
    lacc1 += __shfl_xor_sync(0xffffffffu, lacc1, 2);
    float inv0 = 1.f / lacc0, inv1 = 1.f / lacc1;

    uint32_t* AH = (uint32_t*)g_AH4;
    uint32_t* AL = (uint32_t*)g_AL4;
    int r0 = b*TT + q0 + 16*w + (lane >> 2);
    int cl = (lane & 3)*2;
    #pragma unroll
    for (int n = 0; n < 8; n++) {
        wr_pair64(AH, AL, r0,     n*8 + cl, o[n][0]*inv0, o[n][1]*inv0);
        wr_pair64(AH, AL, r0 + 8, n*8 + cl, o[n][2]*inv1, o[n][3]*inv1);
    }
}

// ===================== conv1d: 64-row tiles, per-(k,h) W slices ============
template<int WB, int NH, bool SPLIT>
__global__ __launch_bounds__(256) void convs_kernel(
    const uint4* __restrict__ inH4, const uint4* __restrict__ inL4,
    const uint32_t* __restrict__ wH, const uint32_t* __restrict__ wL,
    const float* __restrict__ bias,
    const float* __restrict__ resid, float* __restrict__ outF,
    uint32_t* __restrict__ outH, uint32_t* __restrict__ outL)
{
    extern __shared__ __align__(16) char smp[];
    const uint32_t sb = smem_u32(smp);
    const int b = blockIdx.y, t0 = blockIdx.x*64, z = blockIdx.z;
    const int tid = threadIdx.x, wrp = tid >> 5, lane = tid & 31;
    const int mw = wrp & 3, nhw = wrp >> 2;

    const int XH = 0, XL = 66*WB;
    const int W0 = 2*66*WB, WL0 = W0 + 8192;

    const int n4 = 66*(WB/16);
    for (int i = tid; i < 2*n4; i += 256) {
        int sel = (i >= n4); int j = sel ? i - n4 : i;
        int r = j/(WB/16), c = j%(WB/16);
        int t = t0 + r - 1;
        uint32_t dst = sb + (sel ? XL : XH) + r*WB + c*16;
        if (t >= 0 && t < TT) CPA(dst, (sel ? inL4 : inH4) + (size_t)(b*TT+t)*(WB/16) + c);
        else *(uint4*)(smp + (sel ? XL : XH) + r*WB + c*16) = make_uint4(0,0,0,0);
    }
    CPC();

    float o[4][4];
    #pragma unroll
    for (int m = 0; m < 4; m++) { o[m][0]=o[m][1]=o[m][2]=o[m][3]=0.f; }
    const int laneR = (lane & 7) + ((lane >> 3) & 1)*8;
    const int chS   = lane >> 4;

    for (int kh = 0; kh < 3*NH; kh++) {
        const int k = kh / NH, h = kh - k*NH;
        __syncthreads();
        for (int i = tid; i < 1024; i += 256) {
            int sel = (i >= 512); int j = sel ? i - 512 : i;
            const uint32_t* src = (sel ? wL : wH) + (size_t)((k*NH+h)*2 + z)*2048 + j*4;
            CPA(sb + (sel ? WL0 : W0) + j*16, (const uint4*)src);
        }
        CPC();
        CPW(0);
        __syncthreads();

        #pragma unroll
        for (int ks = 0; ks < 4; ks++) {
            int ar = 16*mw + laneR + k;
            uint32_t aoff = (uint32_t)(ar*WB + h*128 + (((2*ks+chS) ^ ((ar+7)&7))<<4));
            uint32_t ah[4], al[4];
            LDSM4(ah, sb + XH + aoff);
            LDSM4(al, sb + XL + aoff);
            #pragma unroll
            for (int g = 0; g < 2; g++) {
                int br = ks*16 + laneR;
                int cch = nhw*4 + 2*g + chS;
                uint32_t boff = (uint32_t)(br*128 + ((cch ^ (br&7))<<4));
                uint32_t bh[4], bl[4];
                LDSM4T(bh, sb + W0  + boff);
                LDSM4T(bl, sb + WL0 + boff);
                mma16816(o[2*g],   ah, bh[0], bh[1]);
                mma16816(o[2*g],   al, bh[0], bh[1]);
                mma16816(o[2*g],   ah, bl[0], bl[1]);
                mma16816(o[2*g+1], ah, bh[2], bh[3]);
                mma16816(o[2*g+1], al, bh[2], bh[3]);
                mma16816(o[2*g+1], ah, bl[2], bl[3]);
            }
        }
    }

    int r0 = t0 + 16*mw + (lane >> 2);
    #pragma unroll
    for (int m = 0; m < 4; m++) {
        int col = nhw*32 + (m >> 1)*16 + (m & 1)*8 + (lane & 3)*2;
        int co  = z*64 + col;
        float b0 = bias[co], b1 = bias[co + 1];
        float v0 = fmaxf(o[m][0] + b0, 0.f);
        float v1 = fmaxf(o[m][1] + b1, 0.f);
        float v2 = fmaxf(o[m][2] + b0, 0.f);
        float v3 = fmaxf(o[m][3] + b1, 0.f);
        if (SPLIT) {
            #pragma unroll
            for (int rr = 0; rr < 2; rr++) {
                int row = b*TT + r0 + rr*8;
                float a = rr ? v2 : v0, bb = rr ? v3 : v1;
                int ch = co >> 3;
                int chp = (ch & 8) | ((ch ^ (row & 7)) & 7);
                int u = row*64 + (chp << 2) + ((co & 7) >> 1);
                __nv_bfloat16 ha=__float2bfloat16(a), hb=__float2bfloat16(bb);
                outH[u] = ((uint32_t)__bfloat16_as_ushort(hb)<<16)|__bfloat16_as_ushort(ha);
                outL[u] = packbf(a-__bfloat162float(ha), bb-__bfloat162float(hb));
            }
        } else {
            size_t base0 = (size_t)(b*TT + r0)*NOUT + co;
            size_t base1 = (size_t)(b*TT + r0 + 8)*NOUT + co;
            float2 ra = *(const float2*)(resid + base0);
            float2 rb = *(const float2*)(resid + base1);
            float2 s0; s0.x = fmaxf(v0 + ra.x, 0.f); s0.y = fmaxf(v1 + ra.y, 0.f);
            float2 s1; s1.x = fmaxf(v2 + rb.x, 0.f); s1.y = fmaxf(v3 + rb.y, 0.f);
            *(float2*)(outF + base0) = s0;
            *(float2*)(outF + base1) = s1;
        }
    }
}

// ---------------------------------------------------------------------------
extern "C" void kernel_launch(void* const* d_in, const int* in_sizes, int n_in,
                              void* d_out, int out_size)
{
    const float* x       = (const float*)d_in[0];
    const float* qkv_w   = (const float*)d_in[1];
    const float* qkv_b   = (const float*)d_in[2];
    const float* scale   = (const float*)d_in[3];
    const float* conv_w1 = (const float*)d_in[4];
    const float* conv_b1 = (const float*)d_in[5];
    const float* conv_w2 = (const float*)d_in[6];
    const float* conv_b2 = (const float*)d_in[7];
    const float* down_w  = (const float*)d_in[8];
    float* out = (float*)d_out;

    const int SM1 = 2*66*128 + 16384;            // 33280 -> 6 CTA/SM
    const int SM2 = 2*66*256 + 16384;            // 50176 -> 4 CTA/SM

    cudaFuncSetAttribute(projm2_kernel, cudaFuncAttributeMaxDynamicSharedMemorySize, PROJ2_SMEM);
    cudaFuncSetAttribute(attn8_kernel,  cudaFuncAttributeMaxDynamicSharedMemorySize, ATTN8_SMEM);
    cudaFuncSetAttribute((const void*)convs_kernel<128,1,true>,
                         cudaFuncAttributeMaxDynamicSharedMemorySize, SM1);
    cudaFuncSetAttribute((const void*)convs_kernel<256,2,false>,
                         cudaFuncAttributeMaxDynamicSharedMemorySize, SM2);

    uint4 *aH, *aL, *hH, *hL, *w1H, *w1L, *w2H, *w2L, *pwH, *pwL;
    float *xdw;
    cudaGetSymbolAddress((void**)&aH,  g_AH4);
    cudaGetSymbolAddress((void**)&aL,  g_AL4);
    cudaGetSymbolAddress((void**)&hH,  g_HH4);
    cudaGetSymbolAddress((void**)&hL,  g_HL4);
    cudaGetSymbolAddress((void**)&w1H, g_W1H4);
    cudaGetSymbolAddress((void**)&w1L, g_W1L4);
    cudaGetSymbolAddress((void**)&w2H, g_W2H4);
    cudaGetSymbolAddress((void**)&w2L, g_W2L4);
    cudaGetSymbolAddress((void**)&pwH, g_PWH4);
    cudaGetSymbolAddress((void**)&pwL, g_PWL4);
    cudaGetSymbolAddress((void**)&xdw, g_XDW);

    prep_all_kernel<<<204, 256>>>(conv_w1, conv_w2, qkv_w, down_w,
        (uint32_t*)w1H, (uint32_t*)w1L, (uint32_t*)w2H, (uint32_t*)w2L,
        (uint32_t*)pwH, (uint32_t*)pwL);
    projm2_kernel<<<BT/64, 256, PROJ2_SMEM>>>(x, qkv_b, scale);
    attn8_kernel<<<dim3(TT/128, BB), 256, ATTN8_SMEM>>>();
    convs_kernel<128,1,true ><<<dim3(TT/64, BB, 2), 256, SM1>>>(
        aH, aL, (uint32_t*)w1H, (uint32_t*)w1L, conv_b1, nullptr, nullptr,
        (uint32_t*)hH, (uint32_t*)hL);
    convs_kernel<256,2,false><<<dim3(TT/64, BB, 2), 256, SM2>>>(
        hH, hL, (uint32_t*)w2H, (uint32_t*)w2L, conv_b2, xdw, out,
        nullptr, nullptr);
}

// round 17
// speedup vs baseline: 1.9069x; 1.2007x over previous
#include <cuda_runtime.h>
#include <cuda_bf16.h>
#include <cstdint>

#define BB   16
#define TT   2048
#define NIN  96
#define NOUT 128
#define DD   64
#define BT   (BB*TT)

// ---- global scratch (pre-split bf16 hi/lo, swizzled 128B/256B rows) ----
__device__ uint4 g_QH4[BT*8]; __device__ uint4 g_QL4[BT*8];
__device__ uint4 g_KH4[BT*8];
__device__ uint4 g_VH4[BT*8];
__device__ uint4 g_AH4[BT*8];                      // attn out (single bf16)
__device__ uint4 g_HH4[BT*16];                     // conv1 out (256B rows, single bf16)
__device__ float g_XDW[BT*NOUT];
__device__ uint4 g_W1H4[3*2*512];   __device__ uint4 g_W1L4[3*2*512];
__device__ uint4 g_W2H4[3*2*2*512]; __device__ uint4 g_W2L4[3*2*2*512];
__device__ uint4 g_PWH4[5*768];     __device__ uint4 g_PWL4[5*768];   // proj weights

// ===================== helpers =====================
__device__ __forceinline__ uint32_t smem_u32(const void* p){
    uint32_t a;
    asm("{ .reg .u64 t; cvta.to.shared.u64 t, %1; cvt.u32.u64 %0, t; }" : "=r"(a) : "l"(p));
    return a;
}
#define LDSM4(R, A) \
    asm volatile("ldmatrix.sync.aligned.m8n8.x4.shared.b16 {%0,%1,%2,%3}, [%4];" \
        : "=r"((R)[0]),"=r"((R)[1]),"=r"((R)[2]),"=r"((R)[3]) : "r"(A))
#define LDSM4T(R, A) \
    asm volatile("ldmatrix.sync.aligned.m8n8.x4.trans.shared.b16 {%0,%1,%2,%3}, [%4];" \
        : "=r"((R)[0]),"=r"((R)[1]),"=r"((R)[2]),"=r"((R)[3]) : "r"(A))
#define CPA(dst, src) \
    asm volatile("cp.async.cg.shared.global [%0], [%1], 16;" :: "r"(dst), "l"(src))
#define CPC() asm volatile("cp.async.commit_group;")
#define CPW(n) asm volatile("cp.async.wait_group %0;" :: "n"(n))

__device__ __forceinline__ void mma16816(float* c, const uint32_t* a, uint32_t b0, uint32_t b1){
    asm volatile(
        "mma.sync.aligned.m16n8k16.row.col.f32.bf16.bf16.f32 "
        "{%0,%1,%2,%3},{%4,%5,%6,%7},{%8,%9},{%0,%1,%2,%3};"
        : "+f"(c[0]),"+f"(c[1]),"+f"(c[2]),"+f"(c[3])
        : "r"(a[0]),"r"(a[1]),"r"(a[2]),"r"(a[3]),"r"(b0),"r"(b1));
}
__device__ __forceinline__ uint32_t packbf(float lo, float hi){
    uint16_t l = __bfloat16_as_ushort(__float2bfloat16(lo));
    uint16_t h = __bfloat16_as_ushort(__float2bfloat16(hi));
    return ((uint32_t)h << 16) | (uint32_t)l;
}
__device__ __forceinline__ uint32_t cvt2(float hi, float lo){
    uint32_t r;
    asm("cvt.rn.bf16x2.f32 %0, %1, %2;" : "=r"(r) : "f"(hi), "f"(lo));
    return r;
}
__device__ __forceinline__ uint32_t swz(int r, int ch){
    return (uint32_t)(r*128 + ((ch ^ (r & 7)) << 4));
}
// write hi/lo split pair into 128B-row global arrays
__device__ __forceinline__ void wr_pair64(uint32_t* H, uint32_t* L, int row, int cl,
                                          float a, float bvv){
    int byte = cl*2;
    int u = row*32 + (((byte>>4) ^ (row&7))<<2) + ((byte&15)>>2);
    __nv_bfloat16 ha=__float2bfloat16(a), hb=__float2bfloat16(bvv);
    H[u] = ((uint32_t)__bfloat16_as_ushort(hb)<<16)|__bfloat16_as_ushort(ha);
    L[u] = packbf(a-__bfloat162float(ha), bvv-__bfloat162float(hb));
}
// write hi-only pair into 128B-row global array
__device__ __forceinline__ void wr_h64(uint32_t* H, int row, int cl, float a, float bvv){
    int byte = cl*2;
    int u = row*32 + (((byte>>4) ^ (row&7))<<2) + ((byte&15)>>2);
    H[u] = cvt2(bvv, a);
}

// ===================== merged weight prep =====================
__device__ __forceinline__ void prep_conv_item(const float* w, int Cin, int idx,
                                               uint32_t* wH, uint32_t* wL){
    int nh = Cin >> 6;
    int k = idx/(Cin*64); int rem = idx - k*Cin*64;
    int ci = rem >> 6, cop = rem & 63;
    float2 v = *(const float2*)(w + (size_t)(k*Cin+ci)*NOUT + cop*2);
    int hci = ci>>6, cil = ci&63, hco = cop>>5, copl = cop&31;
    int tidx = (k*nh + hci)*2 + hco;
    int u = tidx*2048 + cil*32 + (((copl>>2) ^ (cil&7))<<2) + (copl&3);
    __nv_bfloat16 hx=__float2bfloat16(v.x), hy=__float2bfloat16(v.y);
    wH[u] = ((uint32_t)__bfloat16_as_ushort(hy)<<16)|__bfloat16_as_ushort(hx);
    wL[u] = packbf(v.x-__bfloat162float(hx), v.y-__bfloat162float(hy));
}
__global__ void prep_all_kernel(
    const float* __restrict__ w1, const float* __restrict__ w2,
    const float* __restrict__ qkv_w, const float* __restrict__ down_w,
    uint32_t* __restrict__ w1H, uint32_t* __restrict__ w1L,
    uint32_t* __restrict__ w2H, uint32_t* __restrict__ w2L,
    uint32_t* __restrict__ pH,  uint32_t* __restrict__ pL)
{
    const int N1 = 3*64*64;
    const int N2 = 3*128*64;
    const int NP = 96*160;
    for (int idx = blockIdx.x*blockDim.x + threadIdx.x; idx < N1 + N2 + NP;
         idx += gridDim.x*blockDim.x) {
        if (idx < N1) {
            prep_conv_item(w1, 64, idx, w1H, w1L);
        } else if (idx < N1 + N2) {
            prep_conv_item(w2, 128, idx - N1, w2H, w2L);
        } else {
            int j = idx - N1 - N2;
            int ci = j/160, cop = j - ci*160;
            int z = cop >> 5, copl = cop & 31;
            int col = cop*2;
            float2 v = (z < 3) ? *(const float2*)(qkv_w + ci*192 + col)
                               : *(const float2*)(down_w + ci*128 + (col - 192));
            int u = z*3072 + ci*32 + (((copl>>2) ^ (ci&7))<<2) + (copl&3);
            __nv_bfloat16 hx=__float2bfloat16(v.x), hy=__float2bfloat16(v.y);
            pH[u] = ((uint32_t)__bfloat16_as_ushort(hy)<<16)|__bfloat16_as_ushort(hx);
            pL[u] = packbf(v.x-__bfloat162float(hx), v.y-__bfloat162float(hy));
        }
    }
}

// ===================== proj: resident X, z-loop, double-buffered W =========
#define P2_XH 0
#define P2_XL 16384
#define P2_W0 32768          // stage s at P2_W0 + s*24576; WL = +12288
#define PROJ2_SMEM 81920
__global__ __launch_bounds__(256, 2) void projm2_kernel(
    const float* __restrict__ x, const float* __restrict__ qkv_b,
    const float* __restrict__ scale)
{
    extern __shared__ __align__(16) char smp[];
    const uint32_t sb = smem_u32(smp);
    const int row0 = blockIdx.x * 64;
    const int tid  = threadIdx.x, wrp = tid >> 5, lane = tid & 31;
    const int mw   = wrp & 3, nh = wrp >> 2;

    auto issue_w = [&](int z, int s){
        const uint4* srcH = (const uint4*)((const uint32_t*)g_PWH4 + z*3072);
        const uint4* srcL = (const uint4*)((const uint32_t*)g_PWL4 + z*3072);
        uint32_t base = sb + P2_W0 + s*24576;
        #pragma unroll
        for (int i = tid; i < 1536; i += 256) {
            int sel = (i >= 768); int j = sel ? i - 768 : i;
            CPA(base + sel*12288 + j*16, (sel ? srcL : srcH) + j);
        }
        CPC();
    };

    issue_w(0, 0);

    {
        float2 vals[12];
        #pragma unroll
        for (int j = 0; j < 12; j++) {
            int i = tid + j*256;
            int r = i/48, p = i - r*48;
            vals[j] = *(const float2*)(x + (size_t)(row0 + r)*NIN + p*2);
        }
        #pragma unroll
        for (int j = 0; j < 12; j++) {
            int i = tid + j*256;
            int r = i/48, p = i - r*48;
            int c = p >> 2;
            int pos = (c & 8) | ((c ^ (r & 7)) & 7);
            uint32_t off = (uint32_t)(r*256 + pos*16 + (p & 3)*4);
            uint32_t h = cvt2(vals[j].y, vals[j].x);
            *(uint32_t*)(smp + P2_XH + off) = h;
            *(uint32_t*)(smp + P2_XL + off) = cvt2(vals[j].y - __uint_as_float(h & 0xFFFF0000u),
                                                   vals[j].x - __uint_as_float(h << 16));
        }
    }

    const float sc    = scale[0];
    const float enres = 1.0f + 1.0f/(float)TT;
    const int laneR = (lane & 7) + ((lane >> 3) & 1)*8;
    const int chS   = lane >> 4;
    const int r0    = row0 + 16*mw + (lane >> 2);

    for (int z = 0; z < 5; z++) {
        __syncthreads();
        if (z < 4) issue_w(z + 1, (z + 1) & 1);
        if (z < 4) CPW(1); else CPW(0);
        __syncthreads();

        const uint32_t WH = sb + P2_W0 + (z & 1)*24576;
        const uint32_t WL = WH + 12288;

        float o[4][4];
        #pragma unroll
        for (int m = 0; m < 4; m++) { o[m][0]=o[m][1]=o[m][2]=o[m][3]=0.f; }

        #pragma unroll
        for (int ks = 0; ks < 6; ks++) {
            int ar = 16*mw + laneR;
            int c  = 2*ks + chS;
            uint32_t aoff = (uint32_t)(ar*256 + (((c & 8) | ((c ^ (ar & 7)) & 7)) << 4));
            uint32_t ah[4], al[4];
            LDSM4(ah, sb + P2_XH + aoff);
            LDSM4(al, sb + P2_XL + aoff);
            #pragma unroll
            for (int g = 0; g < 2; g++) {
                int br = ks*16 + laneR;
                int cch = nh*4 + 2*g + chS;
                uint32_t boff = (uint32_t)(br*128 + ((cch ^ (br & 7)) << 4));
                uint32_t bh[4], bl[4];
                LDSM4T(bh, WH + boff);
                LDSM4T(bl, WL + boff);
                mma16816(o[2*g],   ah, bh[0], bh[1]);
                mma16816(o[2*g],   al, bh[0], bh[1]);
                mma16816(o[2*g],   ah, bl[0], bl[1]);
                mma16816(o[2*g+1], ah, bh[2], bh[3]);
                mma16816(o[2*g+1], al, bh[2], bh[3]);
                mma16816(o[2*g+1], ah, bl[2], bl[3]);
            }
        }

        #pragma unroll
        for (int m = 0; m < 4; m++) {
            int col = nh*32 + (m >> 1)*16 + (m & 1)*8 + (lane & 3)*2;
            if (z == 0) {
                float b0 = qkv_b[col], b1 = qkv_b[col + 1];
                float v0 = (o[m][0] + b0)*sc, v1 = (o[m][1] + b1)*sc;
                float v2 = (o[m][2] + b0)*sc, v3 = (o[m][3] + b1)*sc;
                wr_pair64((uint32_t*)g_QH4, (uint32_t*)g_QL4, r0,     col, v0, v1);
                wr_pair64((uint32_t*)g_QH4, (uint32_t*)g_QL4, r0 + 8, col, v2, v3);
            } else if (z < 3) {
                uint32_t* H = (z == 1) ? (uint32_t*)g_KH4 : (uint32_t*)g_VH4;
                float b0 = qkv_b[z*64 + col], b1 = qkv_b[z*64 + col + 1];
                wr_h64(H, r0,     col, o[m][0] + b0, o[m][1] + b1);
                wr_h64(H, r0 + 8, col, o[m][2] + b0, o[m][3] + b1);
            } else {
                int oc = (z - 3)*64 + col;
                float2 s0; s0.x = o[m][0]*enres; s0.y = o[m][1]*enres;
                float2 s1; s1.x = o[m][2]*enres; s1.y = o[m][3]*enres;
                *(float2*)(g_XDW + (size_t)r0*NOUT + oc)       = s0;
                *(float2*)(g_XDW + (size_t)(r0 + 8)*NOUT + oc) = s1;
            }
        }
    }
}

// ===================== attention: 2-term QK^T, single-bf16 V, 3-stage ======
// S = Qh.Kh + Ql.Kh ; O += Ph.Vh + Pl.Vh (V un-split).
// KV stage = {KH, VH} = 8KB. smem 32K Q + 3*8K = 56KB, 2 CTAs/SM.
#define T_QH 0
#define T_QL 16384
#define T_KV 32768
#define ATTN9_SMEM 57344

__global__ __launch_bounds__(256, 2) void attn9_kernel()
{
    extern __shared__ __align__(16) char smp[];
    const uint32_t sb = smem_u32(smp);
    const int b    = blockIdx.y;
    const int q0   = blockIdx.x * 128;
    const int tid  = threadIdx.x;
    const int w    = tid >> 5;
    const int lane = tid & 31;
    const int toff = ((blockIdx.x + blockIdx.y) & 7) << 3;

    auto issue_kv = [&](int t, int s){
        const uint4* s0 = g_KH4 + (size_t)(b*TT + t*32)*8;
        const uint4* s1 = g_VH4 + (size_t)(b*TT + t*32)*8;
        uint32_t base = sb + T_KV + s*8192;
        #pragma unroll
        for (int i = tid; i < 512; i += 256) {
            int m = i >> 8, j = i & 255;
            CPA(base + m*4096 + j*16, ((m==0) ? s0 : s1) + j);
        }
        CPC();
    };

    {
        const uint4* qh4 = g_QH4 + (size_t)(b*TT + q0)*8;
        const uint4* ql4 = g_QL4 + (size_t)(b*TT + q0)*8;
        for (int i = tid; i < 2048; i += 256) {
            int sel = i >> 10, j = i & 1023;
            CPA(sb + (sel ? T_QL : T_QH) + j*16, (sel ? ql4 : qh4) + j);
        }
        CPC();
    }
    issue_kv(toff, 0);
    issue_kv((toff + 1) & 63, 1);
    CPW(2);
    __syncthreads();

    uint32_t qh[4][4], ql[4][4];
    {
        int rr = 16*w + (lane & 7) + ((lane >> 3) & 1)*8;
        #pragma unroll
        for (int k = 0; k < 4; k++) {
            int ch = 2*k + (lane >> 4);
            LDSM4(qh[k], sb + T_QH + swz(rr, ch));
            LDSM4(ql[k], sb + T_QL + swz(rr, ch));
        }
    }

    float o[8][4];
    #pragma unroll
    for (int n = 0; n < 8; n++) { o[n][0]=o[n][1]=o[n][2]=o[n][3]=0.f; }
    float lacc0 = 0.f, lacc1 = 0.f;

    const int rBk  = (lane & 7) + (lane >> 4)*8;
    const int chBk = (lane >> 3) & 1;
    const int rBv  = (lane & 7) + ((lane >> 3) & 1)*8;
    const int chBv = (lane >> 4);

    int stage = 0;
    for (int t = 0; t < 64; t++) {
        if (t < 63) CPW(1); else CPW(0);
        __syncthreads();
        if (t + 2 < 64) {
            int s2 = stage + 2; if (s2 >= 3) s2 -= 3;
            issue_kv((t + 2 + toff) & 63, s2);
        }
        const uint32_t KH = sb + T_KV + stage*8192;
        const uint32_t VH = KH + 4096;

        #pragma unroll
        for (int n2 = 0; n2 < 2; n2++) {
            // ---- S block: 2-term ----
            float c0[4] = {0,0,0,0}, c1[4] = {0,0,0,0};
            int s0 = n2*16;
            #pragma unroll
            for (int k = 0; k < 4; k++) {
                uint32_t off = swz(s0 + rBk, 2*k + chBk);
                uint32_t bh[4];
                LDSM4(bh, KH + off);
                mma16816(c0, qh[k], bh[0], bh[1]);
                mma16816(c0, ql[k], bh[0], bh[1]);
                mma16816(c1, qh[k], bh[2], bh[3]);
                mma16816(c1, ql[k], bh[2], bh[3]);
            }
            float e0 = __expf(c0[0]), e1 = __expf(c0[1]);
            float e2 = __expf(c0[2]), e3 = __expf(c0[3]);
            float e4 = __expf(c1[0]), e5 = __expf(c1[1]);
            float e6 = __expf(c1[2]), e7 = __expf(c1[3]);
            lacc0 += e0 + e1 + e4 + e5;
            lacc1 += e2 + e3 + e6 + e7;
            uint32_t ph[4], pl[4];
            ph[0] = cvt2(e1, e0);
            ph[1] = cvt2(e3, e2);
            ph[2] = cvt2(e5, e4);
            ph[3] = cvt2(e7, e6);
            pl[0] = cvt2(e1 - __uint_as_float(ph[0] & 0xFFFF0000u),
                         e0 - __uint_as_float(ph[0] << 16));
            pl[1] = cvt2(e3 - __uint_as_float(ph[1] & 0xFFFF0000u),
                         e2 - __uint_as_float(ph[1] << 16));
            pl[2] = cvt2(e5 - __uint_as_float(ph[2] & 0xFFFF0000u),
                         e4 - __uint_as_float(ph[2] << 16));
            pl[3] = cvt2(e7 - __uint_as_float(ph[3] & 0xFFFF0000u),
                         e6 - __uint_as_float(ph[3] << 16));

            // ---- PV: 2-term (P split, V un-split) ----
            #pragma unroll
            for (int dp = 0; dp < 4; dp++) {
                uint32_t off = swz(s0 + rBv, 2*dp + chBv);
                uint32_t bh[4];
                LDSM4T(bh, VH + off);
                mma16816(o[2*dp],   ph, bh[0], bh[1]);
                mma16816(o[2*dp],   pl, bh[0], bh[1]);
                mma16816(o[2*dp+1], ph, bh[2], bh[3]);
                mma16816(o[2*dp+1], pl, bh[2], bh[3]);
            }
        }
        if (++stage == 3) stage = 0;
    }

    lacc0 += __shfl_xor_sync(0xffffffffu, lacc0, 1);
    lacc0 += __shfl_xor_sync(0xffffffffu, lacc0, 2);
    lacc1 += __shfl_xor_sync(0xffffffffu, lacc1, 1);
    lacc1 += __shfl_xor_sync(0xffffffffu, lacc1, 2);
    float inv0 = 1.f / lacc0, inv1 = 1.f / lacc1;

    uint32_t* AH = (uint32_t*)g_AH4;
    int r0 = b*TT + q0 + 16*w + (lane >> 2);
    int cl = (lane & 3)*2;
    #pragma unroll
    for (int n = 0; n < 8; n++) {
        wr_h64(AH, r0,     n*8 + cl, o[n][0]*inv0, o[n][1]*inv0);
        wr_h64(AH, r0 + 8, n*8 + cl, o[n][2]*inv1, o[n][3]*inv1);
    }
}

// ===================== conv1d: single-bf16 X, split W, per-(k,h) slices ====
// WB = input row bytes; NH = Cin/64; SPLIT: write bf16 out (hi only).
// conv1 24.8KB (8 CTA/SM), conv2 33.3KB (6 CTA/SM).
template<int WB, int NH, bool SPLIT>
__global__ __launch_bounds__(256) void convs_kernel(
    const uint4* __restrict__ inH4,
    const uint32_t* __restrict__ wH, const uint32_t* __restrict__ wL,
    const float* __restrict__ bias,
    const float* __restrict__ resid, float* __restrict__ outF,
    uint32_t* __restrict__ outH)
{
    extern __shared__ __align__(16) char smp[];
    const uint32_t sb = smem_u32(smp);
    const int b = blockIdx.y, t0 = blockIdx.x*64, z = blockIdx.z;
    const int tid = threadIdx.x, wrp = tid >> 5, lane = tid & 31;
    const int mw = wrp & 3, nhw = wrp >> 2;

    const int XH = 0;
    const int W0 = 66*WB, WL0 = W0 + 8192;

    // ---- X halo tile (hi only) via cp.async ----
    const int n4 = 66*(WB/16);
    for (int i = tid; i < n4; i += 256) {
        int r = i/(WB/16), c = i%(WB/16);
        int t = t0 + r - 1;
        uint32_t dst = sb + XH + r*WB + c*16;
        if (t >= 0 && t < TT) CPA(dst, inH4 + (size_t)(b*TT+t)*(WB/16) + c);
        else *(uint4*)(smp + XH + r*WB + c*16) = make_uint4(0,0,0,0);
    }
    CPC();

    float o[4][4];
    #pragma unroll
    for (int m = 0; m < 4; m++) { o[m][0]=o[m][1]=o[m][2]=o[m][3]=0.f; }
    const int laneR = (lane & 7) + ((lane >> 3) & 1)*8;
    const int chS   = lane >> 4;

    for (int kh = 0; kh < 3*NH; kh++) {
        const int k = kh / NH, h = kh - k*NH;
        __syncthreads();
        for (int i = tid; i < 1024; i += 256) {
            int sel = (i >= 512); int j = sel ? i - 512 : i;
            const uint32_t* src = (sel ? wL : wH) + (size_t)((k*NH+h)*2 + z)*2048 + j*4;
            CPA(sb + (sel ? WL0 : W0) + j*16, (const uint4*)src);
        }
        CPC();
        CPW(0);
        __syncthreads();

        #pragma unroll
        for (int ks = 0; ks < 4; ks++) {
            int ar = 16*mw + laneR + k;
            // swizzle key = global row & 7 = (ar-1)&7 (halo shift)
            uint32_t aoff = (uint32_t)(ar*WB + h*128 + (((2*ks+chS) ^ ((ar+7)&7))<<4));
            uint32_t ah[4];
            LDSM4(ah, sb + XH + aoff);
            #pragma unroll
            for (int g = 0; g < 2; g++) {
                int br = ks*16 + laneR;
                int cch = nhw*4 + 2*g + chS;
                uint32_t boff = (uint32_t)(br*128 + ((cch ^ (br&7))<<4));
                uint32_t bh[4], bl[4];
                LDSM4T(bh, sb + W0  + boff);
                LDSM4T(bl, sb + WL0 + boff);
                mma16816(o[2*g],   ah, bh[0], bh[1]);
                mma16816(o[2*g],   ah, bl[0], bl[1]);
                mma16816(o[2*g+1], ah, bh[2], bh[3]);
                mma16816(o[2*g+1], ah, bl[2], bl[3]);
            }
        }
    }

    // ---- epilogue ----
    int r0 = t0 + 16*mw + (lane >> 2);
    #pragma unroll
    for (int m = 0; m < 4; m++) {
        int col = nhw*32 + (m >> 1)*16 + (m & 1)*8 + (lane & 3)*2;
        int co  = z*64 + col;
        float b0 = bias[co], b1 = bias[co + 1];
        float v0 = fmaxf(o[m][0] + b0, 0.f);
        float v1 = fmaxf(o[m][1] + b1, 0.f);
        float v2 = fmaxf(o[m][2] + b0, 0.f);
        float v3 = fmaxf(o[m][3] + b1, 0.f);
        if (SPLIT) {
            // 256B rows (hi only), key = global row & 7
            #pragma unroll
            for (int rr = 0; rr < 2; rr++) {
                int row = b*TT + r0 + rr*8;
                float a = rr ? v2 : v0, bb = rr ? v3 : v1;
                int ch = co >> 3;
                int chp = (ch & 8) | ((ch ^ (row & 7)) & 7);
                int u = row*64 + (chp << 2) + ((co & 7) >> 1);
                outH[u] = cvt2(bb, a);
            }
        } else {
            size_t base0 = (size_t)(b*TT + r0)*NOUT + co;
            size_t base1 = (size_t)(b*TT + r0 + 8)*NOUT + co;
            float2 ra = *(const float2*)(resid + base0);
            float2 rb = *(const float2*)(resid + base1);
            float2 s0; s0.x = fmaxf(v0 + ra.x, 0.f); s0.y = fmaxf(v1 + ra.y, 0.f);
            float2 s1; s1.x = fmaxf(v2 + rb.x, 0.f); s1.y = fmaxf(v3 + rb.y, 0.f);
            *(float2*)(outF + base0) = s0;
            *(float2*)(outF + base1) = s1;
        }
    }
}

// ---------------------------------------------------------------------------
extern "C" void kernel_launch(void* const* d_in, const int* in_sizes, int n_in,
                              void* d_out, int out_size)
{
    const float* x       = (const float*)d_in[0];
    const float* qkv_w   = (const float*)d_in[1];
    const float* qkv_b   = (const float*)d_in[2];
    const float* scale   = (const float*)d_in[3];
    const float* conv_w1 = (const float*)d_in[4];
    const float* conv_b1 = (const float*)d_in[5];
    const float* conv_w2 = (const float*)d_in[6];
    const float* conv_b2 = (const float*)d_in[7];
    const float* down_w  = (const float*)d_in[8];
    float* out = (float*)d_out;

    const int SM1 = 66*128 + 16384;              // 24832 -> 8 CTA/SM
    const int SM2 = 66*256 + 16384;              // 33280 -> 6 CTA/SM

    cudaFuncSetAttribute(projm2_kernel, cudaFuncAttributeMaxDynamicSharedMemorySize, PROJ2_SMEM);
    cudaFuncSetAttribute(attn9_kernel,  cudaFuncAttributeMaxDynamicSharedMemorySize, ATTN9_SMEM);
    cudaFuncSetAttribute((const void*)convs_kernel<128,1,true>,
                         cudaFuncAttributeMaxDynamicSharedMemorySize, SM1);
    cudaFuncSetAttribute((const void*)convs_kernel<256,2,false>,
                         cudaFuncAttributeMaxDynamicSharedMemorySize, SM2);

    uint4 *aH, *hH, *w1H, *w1L, *w2H, *w2L, *pwH, *pwL;
    float *xdw;
    cudaGetSymbolAddress((void**)&aH,  g_AH4);
    cudaGetSymbolAddress((void**)&hH,  g_HH4);
    cudaGetSymbolAddress((void**)&w1H, g_W1H4);
    cudaGetSymbolAddress((void**)&w1L, g_W1L4);
    cudaGetSymbolAddress((void**)&w2H, g_W2H4);
    cudaGetSymbolAddress((void**)&w2L, g_W2L4);
    cudaGetSymbolAddress((void**)&pwH, g_PWH4);
    cudaGetSymbolAddress((void**)&pwL, g_PWL4);
    cudaGetSymbolAddress((void**)&xdw, g_XDW);

    prep_all_kernel<<<204, 256>>>(conv_w1, conv_w2, qkv_w, down_w,
        (uint32_t*)w1H, (uint32_t*)w1L, (uint32_t*)w2H, (uint32_t*)w2L,
        (uint32_t*)pwH, (uint32_t*)pwL);
    projm2_kernel<<<BT/64, 256, PROJ2_SMEM>>>(x, qkv_b, scale);
    attn9_kernel<<<dim3(TT/128, BB), 256, ATTN9_SMEM>>>();
    convs_kernel<128,1,true ><<<dim3(TT/64, BB, 2), 256, SM1>>>(
        aH, (uint32_t*)w1H, (uint32_t*)w1L, conv_b1, nullptr, nullptr,
        (uint32_t*)hH);
    convs_kernel<256,2,false><<<dim3(TT/64, BB, 2), 256, SM2>>>(
        hH, (uint32_t*)w2H, (uint32_t*)w2L, conv_b2, xdw, out,
        nullptr);
}